// round 5
// baseline (speedup 1.0000x reference)
#include <cuda_runtime.h>
#include <math.h>

// ---------------- problem constants ----------------
#define BATCH   2
#define SEQLEN  4096
#define DMODEL  768
#define DINNER  1536
#define NHEADS  24
#define CONVDIM 1664
#define DPROJ   3544
#define NTOK    (BATCH*SEQLEN)      // 8192
#define NCHUNK  (SEQLEN/64)         // 64

// column offsets inside one proj row (width DPROJ)
#define OFF_XBC 1536
#define OFF_B   1536                // within g_xbc row (width CONVDIM)
#define OFF_C   1600                // within g_xbc row
#define OFF_DT  3200
#define OFF_R   3224
#define OFF_K   3288
#define OFF_V   3352
#define OFF_W   3416
#define OFF_BON 3480

// ---------------- scratch: static device globals (no allocs) ----------------
__device__ float g_umix [(size_t)NTOK*DMODEL];
__device__ float g_proj [(size_t)NTOK*DPROJ];
__device__ float g_xbc  [(size_t)NTOK*CONVDIM];
__device__ float g_dt   [(size_t)NTOK*NHEADS];
__device__ float g_cumA [(size_t)NTOK*NHEADS];
__device__ float g_alast[(size_t)BATCH*NCHUNK*NHEADS];
__device__ float g_states[(size_t)BATCH*NCHUNK*NHEADS*4096];
__device__ float g_hcat [(size_t)NTOK*2*DINNER];   // [y_mamba | y_rwkv]
__device__ float g_h    [(size_t)NTOK*DINNER];
__device__ float g_ypre [(size_t)NTOK*DINNER];
__device__ float g_ynorm[(size_t)NTOK*DINNER];
__device__ float g_wcum [(size_t)NTOK*64];
__device__ float g_wT   [(size_t)BATCH*NCHUNK*4096];
__device__ float g_wdecay[(size_t)BATCH*NCHUNK*64];
__device__ float g_wkvy [(size_t)NTOK*64];

__device__ __forceinline__ float sigf(float x){ return 1.f/(1.f+__expf(-x)); }

// 16-step k-major micro-GEMM: acc[i][j] += sum_kk P[kk][ty+16i]*Q[kk][tx+16j]
__device__ __forceinline__ void mm16(const float* __restrict__ P,
                                     const float* __restrict__ Q,
                                     float acc[4][4], int ty, int tx)
{
    #pragma unroll
    for (int kk = 0; kk < 16; kk++) {
        float a[4], b[4];
        #pragma unroll
        for (int i=0;i<4;i++) a[i] = P[kk*64 + ty + 16*i];
        #pragma unroll
        for (int j=0;j<4;j++) b[j] = Q[kk*64 + tx + 16*j];
        #pragma unroll
        for (int i=0;i<4;i++)
            #pragma unroll
            for (int j=0;j<4;j++) acc[i][j] = fmaf(a[i], b[j], acc[i][j]);
    }
}

// ---------------- elementwise kernels ----------------
__global__ void umix_kernel(const float* __restrict__ u, const float* __restrict__ tm)
{
    int idx = blockIdx.x*256 + threadIdx.x;
    if (idx >= NTOK*DMODEL) return;
    int m = idx / DMODEL, ch = idx - m*DMODEL;
    int t = m & (SEQLEN-1);
    float tmx = tm[ch];
    float cur = u[idx];
    float prev = (t > 0) ? u[idx - DMODEL] : 0.f;
    g_umix[idx] = cur*tmx + prev*(1.f - tmx);
}

__global__ void conv_kernel(const float* __restrict__ cw, const float* __restrict__ cb)
{
    int idx = blockIdx.x*256 + threadIdx.x;
    if (idx >= NTOK*CONVDIM) return;
    int m = idx / CONVDIM, ch = idx - m*CONVDIM;
    int t = m & (SEQLEN-1);
    float acc = cb[ch];
    #pragma unroll
    for (int k2 = 0; k2 < 4; k2++) {
        int tt = t - 3 + k2;
        if (tt >= 0)
            acc = fmaf(cw[ch*4+k2], g_proj[(size_t)(m-3+k2)*DPROJ + OFF_XBC + ch], acc);
    }
    g_xbc[(size_t)m*CONVDIM + ch] = acc * sigf(acc);   // SiLU
}

__global__ void dt_kernel(const float* __restrict__ dt_bias)
{
    int idx = blockIdx.x*256 + threadIdx.x;
    if (idx >= NTOK*NHEADS) return;
    int hh = idx % NHEADS;
    size_t m = idx / NHEADS;
    float x = g_proj[m*DPROJ + OFF_DT + hh] + dt_bias[hh];
    g_dt[idx] = (x > 20.f) ? x : log1pf(__expf(x));
}

// ---------------- generic fp32 GEMM: C = A(MxK) * W(NxK)^T ----------------
// EPI 0: store. EPI 1: silu(acc+bias). EPI 2: gate combine.
template<int EPI>
__global__ void __launch_bounds__(256) sgemm_kernel(
    const float* __restrict__ A, int lda,
    const float* __restrict__ W,
    const float* __restrict__ bias,
    float* __restrict__ C, int ldc,
    int N, int K,
    const float* __restrict__ p1, const float* __restrict__ p2)
{
    __shared__ float As[16*64];
    __shared__ float Bs[16*64];
    int tid = threadIdx.x;
    int tx = tid & 15, ty = tid >> 4;
    int bm = blockIdx.y * 64, bn = blockIdx.x * 64;
    int r = tid >> 2, q = tid & 3;
    float acc[4][4];
    #pragma unroll
    for (int i=0;i<4;i++)
        #pragma unroll
        for (int j=0;j<4;j++) acc[i][j]=0.f;

    for (int k0 = 0; k0 < K; k0 += 16) {
        float4 av = *(const float4*)(A + (size_t)(bm + r)*lda + k0 + q*4);
        float4 wv = make_float4(0.f,0.f,0.f,0.f);
        if (bn + r < N)
            wv = *(const float4*)(W + (size_t)(bn + r)*K + k0 + q*4);
        As[(q*4+0)*64+r]=av.x; As[(q*4+1)*64+r]=av.y;
        As[(q*4+2)*64+r]=av.z; As[(q*4+3)*64+r]=av.w;
        Bs[(q*4+0)*64+r]=wv.x; Bs[(q*4+1)*64+r]=wv.y;
        Bs[(q*4+2)*64+r]=wv.z; Bs[(q*4+3)*64+r]=wv.w;
        __syncthreads();
        mm16(As, Bs, acc, ty, tx);
        __syncthreads();
    }

    #pragma unroll
    for (int i=0;i<4;i++) {
        int m = bm + ty + 16*i;
        #pragma unroll
        for (int j=0;j<4;j++) {
            int n = bn + tx + 16*j;
            if (n >= N) continue;
            float v = acc[i][j];
            if (EPI == 0) {
                C[(size_t)m*ldc + n] = v;
            } else if (EPI == 1) {
                v += bias[n];
                C[(size_t)m*ldc + n] = v * sigf(v);
            } else {
                float g  = sigf(v + bias[n]);
                float ym = p1[(size_t)m*(2*DINNER) + n];
                float yr = p1[(size_t)m*(2*DINNER) + DINNER + n];
                float z  = p2[(size_t)m*DPROJ + n];
                float sz = z * sigf(z);
                C[(size_t)m*ldc + n] = (g*ym + (1.f-g)*yr) * sz;
            }
        }
    }
}

// ---------------- SSD kernel 1: per (c,h,b): cum, Y_diag, chunk state ----------------
__global__ void __launch_bounds__(256) ssd_chunk_kernel(const float* __restrict__ A_log)
{
    int c = blockIdx.x, h = blockIdx.y, b = blockIdx.z;
    int tid = threadIdx.x, tx = tid & 15, ty = tid >> 4;
    int r = tid >> 2, q = tid & 3;
    int tok0 = b*SEQLEN + c*64;

    __shared__ float sP[16*64];
    __shared__ float sQ[16*64];
    __shared__ float sG[64*64];     // s-major: sG[s*64 + t]
    __shared__ float cum[64], sdt[64];

    if (tid < 64) sdt[tid] = g_dt[(size_t)(tok0+tid)*NHEADS + h];
    __syncthreads();
    if (tid == 0) {
        float Ah = -__expf(A_log[h]);
        float s = 0.f;
        for (int t = 0; t < 64; t++) { s += Ah*sdt[t]; cum[t] = s; }
    }
    __syncthreads();
    if (tid < 64) g_cumA[(size_t)(tok0+tid)*NHEADS + h] = cum[tid];
    if (tid == 0) g_alast[(size_t)(b*NCHUNK+c)*NHEADS + h] = cum[63];

    float acc[4][4];
    // ---- G = C * B^T over n (DSTATE=64) ----
    #pragma unroll
    for (int i=0;i<4;i++)
        #pragma unroll
        for (int j=0;j<4;j++) acc[i][j]=0.f;
    for (int n0 = 0; n0 < 64; n0 += 16) {
        float4 cv = *(const float4*)(g_xbc + (size_t)(tok0+r)*CONVDIM + OFF_C + n0 + q*4);
        float4 bv = *(const float4*)(g_xbc + (size_t)(tok0+r)*CONVDIM + OFF_B + n0 + q*4);
        sP[(q*4+0)*64+r]=cv.x; sP[(q*4+1)*64+r]=cv.y;
        sP[(q*4+2)*64+r]=cv.z; sP[(q*4+3)*64+r]=cv.w;
        sQ[(q*4+0)*64+r]=bv.x; sQ[(q*4+1)*64+r]=bv.y;
        sQ[(q*4+2)*64+r]=bv.z; sQ[(q*4+3)*64+r]=bv.w;
        __syncthreads();
        mm16(sP, sQ, acc, ty, tx);
        __syncthreads();
    }
    #pragma unroll
    for (int i=0;i<4;i++)
        #pragma unroll
        for (int j=0;j<4;j++){
            int t = ty+16*i, s = tx+16*j;
            sG[s*64 + t] = (s <= t) ? acc[i][j]*__expf(cum[t]-cum[s]) : 0.f;
        }
    __syncthreads();

    // ---- Y_diag = Gm @ X   (X = x*dt) ----
    #pragma unroll
    for (int i=0;i<4;i++)
        #pragma unroll
        for (int j=0;j<4;j++) acc[i][j]=0.f;
    {
        int kk2 = tid >> 4, p4 = tid & 15;
        for (int s0 = 0; s0 < 64; s0 += 16) {
            float d = sdt[s0+kk2];
            float4 xv = *(const float4*)(g_xbc + (size_t)(tok0+s0+kk2)*CONVDIM + h*64 + p4*4);
            sQ[kk2*64 + p4*4+0]=xv.x*d; sQ[kk2*64 + p4*4+1]=xv.y*d;
            sQ[kk2*64 + p4*4+2]=xv.z*d; sQ[kk2*64 + p4*4+3]=xv.w*d;
            __syncthreads();
            mm16(&sG[s0*64], sQ, acc, ty, tx);
            __syncthreads();
        }
    }
    #pragma unroll
    for (int i=0;i<4;i++)
        #pragma unroll
        for (int j=0;j<4;j++)
            g_hcat[(size_t)(tok0+ty+16*i)*(2*DINNER) + h*64 + tx+16*j] = acc[i][j];

    // ---- states[p][n] = sum_t (x*dt*exp(alast-cum_t))[t,p] * B[t,n] ----
    #pragma unroll
    for (int i=0;i<4;i++)
        #pragma unroll
        for (int j=0;j<4;j++) acc[i][j]=0.f;
    {
        int kk2 = tid >> 4, p4 = tid & 15;
        float alastv = cum[63];
        for (int t0 = 0; t0 < 64; t0 += 16) {
            float f = sdt[t0+kk2] * __expf(alastv - cum[t0+kk2]);
            float4 xv = *(const float4*)(g_xbc + (size_t)(tok0+t0+kk2)*CONVDIM + h*64 + p4*4);
            float4 bv = *(const float4*)(g_xbc + (size_t)(tok0+t0+kk2)*CONVDIM + OFF_B + p4*4);
            sP[kk2*64 + p4*4+0]=xv.x*f; sP[kk2*64 + p4*4+1]=xv.y*f;
            sP[kk2*64 + p4*4+2]=xv.z*f; sP[kk2*64 + p4*4+3]=xv.w*f;
            sQ[kk2*64 + p4*4+0]=bv.x;   sQ[kk2*64 + p4*4+1]=bv.y;
            sQ[kk2*64 + p4*4+2]=bv.z;   sQ[kk2*64 + p4*4+3]=bv.w;
            __syncthreads();
            mm16(sP, sQ, acc, ty, tx);
            __syncthreads();
        }
    }
    {
        float* sb = g_states + ((size_t)(b*NCHUNK+c)*NHEADS + h)*4096;
        #pragma unroll
        for (int i=0;i<4;i++)
            #pragma unroll
            for (int j=0;j<4;j++)
                sb[(ty+16*i)*64 + tx+16*j] = acc[i][j];
    }
}

// ---------------- SSD kernel 2: cross-chunk state scan ----------------
__global__ void __launch_bounds__(256) ssd_scan_kernel()
{
    int h = blockIdx.x, b = blockIdx.y;
    int tid = threadIdx.x;
    float S[16];
    #pragma unroll
    for (int u=0;u<16;u++) S[u]=0.f;
    size_t eoff = (size_t)tid*16;
    for (int c = 0; c < NCHUNK; c++) {
        float e = __expf(g_alast[(size_t)(b*NCHUNK+c)*NHEADS + h]);
        float* ptr = g_states + ((size_t)(b*NCHUNK+c)*NHEADS + h)*4096 + eoff;
        #pragma unroll
        for (int u=0;u<16;u+=4){
            float4 o = *(float4*)(ptr+u);
            *(float4*)(ptr+u) = make_float4(S[u],S[u+1],S[u+2],S[u+3]);
            S[u+0]=S[u+0]*e+o.x; S[u+1]=S[u+1]*e+o.y;
            S[u+2]=S[u+2]*e+o.z; S[u+3]=S[u+3]*e+o.w;
        }
    }
}

// ---------------- SSD kernel 3: Y += exp(cum)*(C @ S_in^T) + x*D_skip ----------------
__global__ void __launch_bounds__(256) ssd_off_kernel(const float* __restrict__ D_skip)
{
    int c = blockIdx.x, h = blockIdx.y, b = blockIdx.z;
    int tid = threadIdx.x, tx = tid & 15, ty = tid >> 4;
    int r = tid >> 2, q = tid & 3;
    int tok0 = b*SEQLEN + c*64;

    __shared__ float sS[64*64];     // n-major: sS[n*64 + p]
    __shared__ float sC[16*64];
    __shared__ float cum[64];

    {
        const float* sb = g_states + ((size_t)(b*NCHUNK+c)*NHEADS + h)*4096;
        #pragma unroll
        for (int u=0;u<4;u++){
            float4 v = *(const float4*)(sb + r*64 + q*16 + u*4);
            sS[(q*16+u*4+0)*64 + r]=v.x; sS[(q*16+u*4+1)*64 + r]=v.y;
            sS[(q*16+u*4+2)*64 + r]=v.z; sS[(q*16+u*4+3)*64 + r]=v.w;
        }
    }
    if (tid < 64) cum[tid] = g_cumA[(size_t)(tok0+tid)*NHEADS + h];
    __syncthreads();

    float acc[4][4];
    #pragma unroll
    for (int i=0;i<4;i++)
        #pragma unroll
        for (int j=0;j<4;j++) acc[i][j]=0.f;
    for (int n0 = 0; n0 < 64; n0 += 16) {
        float4 cv = *(const float4*)(g_xbc + (size_t)(tok0+r)*CONVDIM + OFF_C + n0 + q*4);
        sC[(q*4+0)*64+r]=cv.x; sC[(q*4+1)*64+r]=cv.y;
        sC[(q*4+2)*64+r]=cv.z; sC[(q*4+3)*64+r]=cv.w;
        __syncthreads();
        mm16(sC, &sS[n0*64], acc, ty, tx);
        __syncthreads();
    }
    float dsk = D_skip[h];
    #pragma unroll
    for (int i=0;i<4;i++){
        int t = ty+16*i;
        float e = __expf(cum[t]);
        #pragma unroll
        for (int j=0;j<4;j++){
            int p = tx+16*j;
            float xv = g_xbc[(size_t)(tok0+t)*CONVDIM + h*64 + p];
            size_t o = (size_t)(tok0+t)*(2*DINNER) + h*64 + p;
            g_hcat[o] = g_hcat[o] + e*acc[i][j] + xv*dsk;
        }
    }
}

// ---------------- RWKV kernel 0: per-channel chunk-local cumsum of log(w) ----------------
__global__ void rwkv_pre_kernel()
{
    int bc = blockIdx.x;            // b*NCHUNK + c
    int i = threadIdx.x;            // 64 threads
    int tok0 = (bc/NCHUNK)*SEQLEN + (bc%NCHUNK)*64;
    float cumv = 0.f;
    for (int t = 0; t < 64; t++) {
        float rw = g_proj[(size_t)(tok0+t)*DPROJ + OFF_W + i];
        cumv += -__expf(rw);
        g_wcum[(size_t)(tok0+t)*64 + i] = cumv;
    }
}

// ---------------- RWKV kernel 1: gram matrix + intra-chunk output ----------------
__global__ void __launch_bounds__(256) rwkv_gram_kernel()
{
    int bc = blockIdx.x;
    int b = bc/NCHUNK, c = bc%NCHUNK;
    int tok0 = b*SEQLEN + c*64;
    int tid = threadIdx.x, tx = tid & 15, ty = tid >> 4;
    int r = tid >> 2, q = tid & 3;

    __shared__ float sA1[64*64];    // phase A: kT[j*64+t]; phase B: cum[t*64+i]
    __shared__ float sA2[64*64];    // phase A: vT[j*64+s]; phase B: a[s*64+i]
    __shared__ float sM [64*64];    // M[t*64+s]

    // phase A: load k,v j-major
    #pragma unroll
    for (int u=0;u<4;u++){
        float4 kv = *(const float4*)(g_proj + (size_t)(tok0+r)*DPROJ + OFF_K + q*16 + u*4);
        float4 vv = *(const float4*)(g_proj + (size_t)(tok0+r)*DPROJ + OFF_V + q*16 + u*4);
        sA1[(q*16+u*4+0)*64 + r]=kv.x; sA1[(q*16+u*4+1)*64 + r]=kv.y;
        sA1[(q*16+u*4+2)*64 + r]=kv.z; sA1[(q*16+u*4+3)*64 + r]=kv.w;
        sA2[(q*16+u*4+0)*64 + r]=vv.x; sA2[(q*16+u*4+1)*64 + r]=vv.y;
        sA2[(q*16+u*4+2)*64 + r]=vv.z; sA2[(q*16+u*4+3)*64 + r]=vv.w;
    }
    __syncthreads();
    float acc[4][4];
    #pragma unroll
    for (int i=0;i<4;i++)
        #pragma unroll
        for (int j=0;j<4;j++) acc[i][j]=0.f;
    #pragma unroll
    for (int j0 = 0; j0 < 64; j0 += 16)
        mm16(&sA1[j0*64], &sA2[j0*64], acc, ty, tx);
    __syncthreads();
    #pragma unroll
    for (int i=0;i<4;i++)
        #pragma unroll
        for (int j=0;j<4;j++)
            sM[(ty+16*i)*64 + tx+16*j] = acc[i][j];   // M[t][s] = k_t . v_s
    __syncthreads();

    // phase B: cum into sA1, a = k*bonus into sA2
    for (int idx = tid; idx < 4096; idx += 256) {
        int t = idx >> 6, i = idx & 63;
        sA1[idx] = g_wcum[(size_t)(tok0+t)*64 + i];
        sA2[idx] = g_proj[(size_t)(tok0+t)*DPROJ + OFF_K + i]
                 * g_proj[(size_t)(tok0+t)*DPROJ + OFF_BON + i];
    }
    __syncthreads();

    // intra output: y[t,i] = r_t[i] * sum_{s<=t} exp(cum_t[i]-cum_s[i]) a_s[i] M[t,s]
    {
        int i = tid & 63, tg = tid >> 6;
        for (int tt = 0; tt < 16; tt++) {
            int t = tg*16 + tt;
            float ct = sA1[t*64 + i];
            float sum = 0.f;
            for (int s = 0; s <= t; s++)
                sum = fmaf(__expf(ct - sA1[s*64+i]) * sA2[s*64+i], sM[t*64+s], sum);
            float rr = sigf(g_proj[(size_t)(tok0+t)*DPROJ + OFF_R + i]);
            g_wkvy[(size_t)(tok0+t)*64 + i] = rr * sum;
        }
    }
}

// ---------------- RWKV kernel 1b: chunk state T[i,j] + last decay ----------------
__global__ void __launch_bounds__(256) rwkv_state_kernel()
{
    int bc = blockIdx.x;
    int b = bc/NCHUNK, c = bc%NCHUNK;
    int tok0 = b*SEQLEN + c*64;
    int tid = threadIdx.x, tx = tid & 15, ty = tid >> 4;

    __shared__ float sP[64*64];     // P[s*64+i] = exp(cumlast[i]-cum_s[i])*k_s[i]*bon_s[i]
    __shared__ float sV[64*64];     // V[s*64+j] = v_s[j]

    for (int idx = tid; idx < 4096; idx += 256) {
        int s = idx >> 6, i = idx & 63;
        float cl = g_wcum[(size_t)(tok0+63)*64 + i];
        float cs = g_wcum[(size_t)(tok0+s)*64 + i];
        sP[idx] = __expf(cl - cs)
                * g_proj[(size_t)(tok0+s)*DPROJ + OFF_K + i]
                * g_proj[(size_t)(tok0+s)*DPROJ + OFF_BON + i];
        sV[idx] = g_proj[(size_t)(tok0+s)*DPROJ + OFF_V + i];
    }
    __syncthreads();
    if (tid < 64)
        g_wdecay[(size_t)bc*64 + tid] = __expf(g_wcum[(size_t)(tok0+63)*64 + tid]);

    float acc[4][4];
    #pragma unroll
    for (int i=0;i<4;i++)
        #pragma unroll
        for (int j=0;j<4;j++) acc[i][j]=0.f;
    #pragma unroll
    for (int s0 = 0; s0 < 64; s0 += 16)
        mm16(&sP[s0*64], &sV[s0*64], acc, ty, tx);

    float* T = g_wT + (size_t)bc*4096;
    #pragma unroll
    for (int i=0;i<4;i++)
        #pragma unroll
        for (int j=0;j<4;j++)
            T[(ty+16*i)*64 + tx+16*j] = acc[i][j];
}

// ---------------- RWKV kernel 2: cross-chunk state scan (per-row decay) ----------------
__global__ void __launch_bounds__(256) rwkv_scan_kernel()
{
    int b = blockIdx.x;
    int tid = threadIdx.x;
    int i = tid >> 2, jb = (tid & 3)*16;
    float S[16];
    #pragma unroll
    for (int u=0;u<16;u++) S[u]=0.f;
    for (int c = 0; c < NCHUNK; c++) {
        int bc = b*NCHUNK + c;
        float e = g_wdecay[(size_t)bc*64 + i];
        float* ptr = g_wT + (size_t)bc*4096 + i*64 + jb;
        #pragma unroll
        for (int u=0;u<16;u+=4){
            float4 o = *(float4*)(ptr+u);
            *(float4*)(ptr+u) = make_float4(S[u],S[u+1],S[u+2],S[u+3]);
            S[u+0]=S[u+0]*e+o.x; S[u+1]=S[u+1]*e+o.y;
            S[u+2]=S[u+2]*e+o.z; S[u+3]=S[u+3]*e+o.w;
        }
    }
}

// ---------------- RWKV kernel 3: inter-chunk output ----------------
__global__ void __launch_bounds__(256) rwkv_inter_kernel()
{
    int bc = blockIdx.x;
    int b = bc/NCHUNK, c = bc%NCHUNK;
    int tok0 = b*SEQLEN + c*64;
    int tid = threadIdx.x, tx = tid & 15, ty = tid >> 4;
    int r = tid >> 2, q = tid & 3;

    __shared__ float sK[64*64];     // j-major: sK[j*64+t] = k_t[j]
    __shared__ float sS[64*64];     // j-major: sS[j*64+i] = S_in[i][j]

    #pragma unroll
    for (int u=0;u<4;u++){
        float4 kv = *(const float4*)(g_proj + (size_t)(tok0+r)*DPROJ + OFF_K + q*16 + u*4);
        sK[(q*16+u*4+0)*64 + r]=kv.x; sK[(q*16+u*4+1)*64 + r]=kv.y;
        sK[(q*16+u*4+2)*64 + r]=kv.z; sK[(q*16+u*4+3)*64 + r]=kv.w;
        float4 sv = *(const float4*)(g_wT + (size_t)bc*4096 + r*64 + q*16 + u*4);
        sS[(q*16+u*4+0)*64 + r]=sv.x; sS[(q*16+u*4+1)*64 + r]=sv.y;
        sS[(q*16+u*4+2)*64 + r]=sv.z; sS[(q*16+u*4+3)*64 + r]=sv.w;
    }
    __syncthreads();

    float acc[4][4];
    #pragma unroll
    for (int i=0;i<4;i++)
        #pragma unroll
        for (int j=0;j<4;j++) acc[i][j]=0.f;
    #pragma unroll
    for (int j0 = 0; j0 < 64; j0 += 16)
        mm16(&sK[j0*64], &sS[j0*64], acc, ty, tx);  // acc[t][i] = sum_j k_t[j] S_in[i][j]

    #pragma unroll
    for (int ii=0;ii<4;ii++){
        int t = ty+16*ii;
        #pragma unroll
        for (int jj=0;jj<4;jj++){
            int i = tx+16*jj;
            float rr = sigf(g_proj[(size_t)(tok0+t)*DPROJ + OFF_R + i]);
            float e  = __expf(g_wcum[(size_t)(tok0+t)*64 + i]);
            size_t o = (size_t)(tok0+t)*64 + i;
            g_wkvy[o] = g_wkvy[o] + rr * e * acc[ii][jj];
        }
    }
}

// ---------------- LayerNorm ----------------
__global__ void __launch_bounds__(256) ln_kernel(const float* __restrict__ g,
                                                 const float* __restrict__ bbias)
{
    int m = blockIdx.x;
    int tid = threadIdx.x;
    const float* row = g_ypre + (size_t)m*DINNER;
    float s = 0.f, s2 = 0.f;
    #pragma unroll
    for (int u = 0; u < 6; u++) {
        float v = row[tid + 256*u];
        s += v; s2 += v*v;
    }
    __shared__ float red[16];
    #pragma unroll
    for (int o = 16; o > 0; o >>= 1) {
        s  += __shfl_xor_sync(0xffffffff, s, o);
        s2 += __shfl_xor_sync(0xffffffff, s2, o);
    }
    if ((tid & 31) == 0) { red[tid>>5] = s; red[8 + (tid>>5)] = s2; }
    __syncthreads();
    if (tid < 8) { s = red[tid]; s2 = red[8+tid]; }
    else { s = 0.f; s2 = 0.f; }
    if (tid < 32) {
        #pragma unroll
        for (int o = 4; o > 0; o >>= 1) {
            s  += __shfl_xor_sync(0xffffffff, s, o);
            s2 += __shfl_xor_sync(0xffffffff, s2, o);
        }
    }
    if (tid == 0) { red[0] = s; red[1] = s2; }
    __syncthreads();
    float mu = red[0] * (1.f/DINNER);
    float var = red[1] * (1.f/DINNER) - mu*mu;
    float inv = rsqrtf(var + 1e-5f);
    #pragma unroll
    for (int u = 0; u < 6; u++) {
        int ch = tid + 256*u;
        float v = (row[ch] - mu) * inv;
        g_ynorm[(size_t)m*DINNER + ch] = v * g[ch] + bbias[ch];
    }
}

// ---------------- launch ----------------
extern "C" void kernel_launch(void* const* d_in, const int* in_sizes, int n_in,
                              void* d_out, int out_size)
{
    const float* u         = (const float*)d_in[0];
    const float* in_proj_w = (const float*)d_in[1];
    const float* conv_w    = (const float*)d_in[2];
    const float* conv_b    = (const float*)d_in[3];
    const float* dt_bias   = (const float*)d_in[4];
    const float* A_log     = (const float*)d_in[5];
    const float* D_skip    = (const float*)d_in[6];
    const float* time_mix  = (const float*)d_in[7];
    const float* wkv_up_w  = (const float*)d_in[8];
    const float* fg_w1     = (const float*)d_in[9];
    const float* fg_b1     = (const float*)d_in[10];
    const float* fg_w2     = (const float*)d_in[11];
    const float* fg_b2     = (const float*)d_in[12];
    const float* ln_g      = (const float*)d_in[13];
    const float* ln_b      = (const float*)d_in[14];
    const float* out_proj_w= (const float*)d_in[15];
    float* out = (float*)d_out;

    float* p_umix;  cudaGetSymbolAddress((void**)&p_umix,  g_umix);
    float* p_proj;  cudaGetSymbolAddress((void**)&p_proj,  g_proj);
    float* p_hcat;  cudaGetSymbolAddress((void**)&p_hcat,  g_hcat);
    float* p_h;     cudaGetSymbolAddress((void**)&p_h,     g_h);
    float* p_ypre;  cudaGetSymbolAddress((void**)&p_ypre,  g_ypre);
    float* p_ynorm; cudaGetSymbolAddress((void**)&p_ynorm, g_ynorm);
    float* p_wkvy;  cudaGetSymbolAddress((void**)&p_wkvy,  g_wkvy);

    // 1. time-mix
    umix_kernel<<<(NTOK*DMODEL)/256, 256>>>(u, time_mix);
    // 2. in_proj GEMM: (8192 x 3544) = umix (8192x768) @ W^T
    sgemm_kernel<0><<<dim3((DPROJ+63)/64, NTOK/64), 256>>>(
        p_umix, DMODEL, in_proj_w, nullptr, p_proj, DPROJ, DPROJ, DMODEL, nullptr, nullptr);
    // 3. dt softplus
    dt_kernel<<<(NTOK*NHEADS)/256, 256>>>(dt_bias);
    // 4. causal conv + silu
    conv_kernel<<<(NTOK*CONVDIM)/256, 256>>>(conv_w, conv_b);
    // 5-7. SSD
    ssd_chunk_kernel<<<dim3(NCHUNK, NHEADS, BATCH), 256>>>(A_log);
    ssd_scan_kernel<<<dim3(NHEADS, BATCH), 256>>>();
    ssd_off_kernel<<<dim3(NCHUNK, NHEADS, BATCH), 256>>>(D_skip);
    // 8-12. RWKV
    rwkv_pre_kernel<<<BATCH*NCHUNK, 64>>>();
    rwkv_gram_kernel<<<BATCH*NCHUNK, 256>>>();
    rwkv_state_kernel<<<BATCH*NCHUNK, 256>>>();
    rwkv_scan_kernel<<<BATCH, 256>>>();
    rwkv_inter_kernel<<<BATCH*NCHUNK, 256>>>();
    // 13. wkv_up GEMM -> right half of hcat
    sgemm_kernel<0><<<dim3(DINNER/64, NTOK/64), 256>>>(
        p_wkvy, 64, wkv_up_w, nullptr, p_hcat + DINNER, 2*DINNER, DINNER, 64, nullptr, nullptr);
    // 14. fg1: h = silu(hcat @ fg_w1^T + b1)
    sgemm_kernel<1><<<dim3(DINNER/64, NTOK/64), 256>>>(
        p_hcat, 2*DINNER, fg_w1, fg_b1, p_h, DINNER, DINNER, 2*DINNER, nullptr, nullptr);
    // 15. fg2 + gate combine + silu(z)
    sgemm_kernel<2><<<dim3(DINNER/64, NTOK/64), 256>>>(
        p_h, DINNER, fg_w2, fg_b2, p_ypre, DINNER, DINNER, DINNER, p_hcat, p_proj);
    // 16. LayerNorm
    ln_kernel<<<NTOK, 256>>>(ln_g, ln_b);
    // 17. out_proj GEMM -> d_out
    sgemm_kernel<0><<<dim3(DMODEL/64, NTOK/64), 256>>>(
        p_ynorm, DINNER, out_proj_w, nullptr, out, DMODEL, DMODEL, DINNER, nullptr, nullptr);
}

// round 7
// speedup vs baseline: 1.4238x; 1.4238x over previous
#include <cuda_runtime.h>
#include <math.h>

// ---------------- problem constants ----------------
#define BATCH   2
#define SEQLEN  4096
#define DMODEL  768
#define DINNER  1536
#define NHEADS  24
#define CONVDIM 1664
#define DPROJ   3544
#define NTOK    (BATCH*SEQLEN)      // 8192
#define NCHUNK  (SEQLEN/64)         // 64

// column offsets inside one proj row (width DPROJ)
#define OFF_XBC 1536
#define OFF_B   1536                // within g_xbc row (width CONVDIM)
#define OFF_C   1600                // within g_xbc row
#define OFF_DT  3200
#define OFF_R   3224
#define OFF_K   3288
#define OFF_V   3352
#define OFF_W   3416
#define OFF_BON 3480

typedef unsigned long long ull;

// ---------------- scratch: static device globals (no allocs) ----------------
__device__ float g_umix [(size_t)NTOK*DMODEL];
__device__ float g_proj [(size_t)NTOK*DPROJ];
__device__ float g_xbc  [(size_t)NTOK*CONVDIM];
__device__ float g_dt   [(size_t)NTOK*NHEADS];
__device__ float g_cumA [(size_t)NTOK*NHEADS];
__device__ float g_alast[(size_t)BATCH*NCHUNK*NHEADS];
__device__ float g_states[(size_t)BATCH*NCHUNK*NHEADS*4096];
__device__ float g_hcat [(size_t)NTOK*2*DINNER];   // [y_mamba | y_rwkv]
__device__ float g_h    [(size_t)NTOK*DINNER];
__device__ float g_ypre [(size_t)NTOK*DINNER];
__device__ float g_ynorm[(size_t)NTOK*DINNER];
__device__ float g_wcum [(size_t)NTOK*64];
__device__ float g_wT   [(size_t)BATCH*NCHUNK*4096];
__device__ float g_wdecay[(size_t)BATCH*NCHUNK*64];
__device__ float g_wkvy [(size_t)NTOK*64];

__device__ __forceinline__ float sigf(float x){ return 1.f/(1.f+__expf(-x)); }

__device__ __forceinline__ ull pack2(float lo, float hi){
    ull r;
    asm("mov.b64 %0, {%1, %2};" : "=l"(r) : "f"(lo), "f"(hi));
    return r;
}
__device__ __forceinline__ void unpack2(float &lo, float &hi, ull v){
    asm("mov.b64 {%0, %1}, %2;" : "=f"(lo), "=f"(hi) : "l"(v));
}
__device__ __forceinline__ void ffma2(ull &d, ull a, ull b){
    asm("fma.rn.f32x2 %0, %1, %2, %0;" : "+l"(d) : "l"(a), "l"(b));
}

// 16-step k-major micro-GEMM (fp32, for scan kernels):
// acc[i][j] += sum_kk P[kk][ty+16i]*Q[kk][tx+16j]
__device__ __forceinline__ void mm16(const float* __restrict__ P,
                                     const float* __restrict__ Q,
                                     float acc[4][4], int ty, int tx)
{
    #pragma unroll
    for (int kk = 0; kk < 16; kk++) {
        float a[4], b[4];
        #pragma unroll
        for (int i=0;i<4;i++) a[i] = P[kk*64 + ty + 16*i];
        #pragma unroll
        for (int j=0;j<4;j++) b[j] = Q[kk*64 + tx + 16*j];
        #pragma unroll
        for (int i=0;i<4;i++)
            #pragma unroll
            for (int j=0;j<4;j++) acc[i][j] = fmaf(a[i], b[j], acc[i][j]);
    }
}

// ---------------- elementwise kernels ----------------
__global__ void umix_kernel(const float* __restrict__ u, const float* __restrict__ tm)
{
    int idx = blockIdx.x*256 + threadIdx.x;
    if (idx >= NTOK*DMODEL) return;
    int m = idx / DMODEL, ch = idx - m*DMODEL;
    int t = m & (SEQLEN-1);
    float tmx = tm[ch];
    float cur = u[idx];
    float prev = (t > 0) ? u[idx - DMODEL] : 0.f;
    g_umix[idx] = cur*tmx + prev*(1.f - tmx);
}

__global__ void conv_kernel(const float* __restrict__ cw, const float* __restrict__ cb)
{
    int idx = blockIdx.x*256 + threadIdx.x;
    if (idx >= NTOK*CONVDIM) return;
    int m = idx / CONVDIM, ch = idx - m*CONVDIM;
    int t = m & (SEQLEN-1);
    float acc = cb[ch];
    #pragma unroll
    for (int k2 = 0; k2 < 4; k2++) {
        int tt = t - 3 + k2;
        if (tt >= 0)
            acc = fmaf(cw[ch*4+k2], g_proj[(size_t)(m-3+k2)*DPROJ + OFF_XBC + ch], acc);
    }
    g_xbc[(size_t)m*CONVDIM + ch] = acc * sigf(acc);   // SiLU
}

__global__ void dt_kernel(const float* __restrict__ dt_bias)
{
    int idx = blockIdx.x*256 + threadIdx.x;
    if (idx >= NTOK*NHEADS) return;
    int hh = idx % NHEADS;
    size_t m = idx / NHEADS;
    float x = g_proj[m*DPROJ + OFF_DT + hh] + dt_bias[hh];
    g_dt[idx] = (x > 20.f) ? x : log1pf(__expf(x));
}

// ---------------- big fp32 GEMM via FFMA2: C = A(MxK) * W(NxK)^T ----------------
// 128x128 tile, 256 threads, 8x8 microtile (row-paired f32x2 accumulators),
// double-buffered smem, k-major tiles of depth 16.
// EPI 0: store. EPI 1: silu(acc+bias). EPI 2: gate combine.
template<int EPI>
__global__ void __launch_bounds__(256, 2) sgemm2_kernel(
    const float* __restrict__ A, int lda,
    const float* __restrict__ W,
    const float* __restrict__ bias,
    float* __restrict__ C, int ldc,
    int N, int K,
    const float* __restrict__ p1, const float* __restrict__ p2)
{
    __shared__ __align__(16) float As[2][16*128];
    __shared__ __align__(16) float Bs[2][16*128];

    int tid = threadIdx.x;
    int tx = tid & 15, ty = tid >> 4;          // compute mapping
    int bm = blockIdx.y * 128, bn = blockIdx.x * 128;
    int lr = tid >> 1, lq = (tid & 1) * 8;     // load mapping: row lr, col-block lq

    const float* Aptr = A + (size_t)(bm + lr)*lda + lq;
    const float* Wptr = W + (size_t)(bn + lr)*K + lq;
    bool wvalid = (bn + lr) < N;

    float4 a0, a1, w0, w1;
    a0 = *(const float4*)(Aptr);
    a1 = *(const float4*)(Aptr + 4);
    if (wvalid) { w0 = *(const float4*)(Wptr); w1 = *(const float4*)(Wptr + 4); }
    else        { w0 = w1 = make_float4(0.f,0.f,0.f,0.f); }

    ull acc[4][8];
    #pragma unroll
    for (int i=0;i<4;i++)
        #pragma unroll
        for (int j=0;j<8;j++) acc[i][j] = 0ull;

    // store stage 0
    {
        #pragma unroll
        for (int u=0;u<4;u++){
            As[0][(lq+u  )*128 + lr] = (&a0.x)[u];
            As[0][(lq+4+u)*128 + lr] = (&a1.x)[u];
            Bs[0][(lq+u  )*128 + lr] = (&w0.x)[u];
            Bs[0][(lq+4+u)*128 + lr] = (&w1.x)[u];
        }
    }
    __syncthreads();

    int buf = 0;
    for (int k0 = 0; k0 < K; k0 += 16) {
        bool more = (k0 + 16) < K;
        if (more) {
            a0 = *(const float4*)(Aptr + k0 + 16);
            a1 = *(const float4*)(Aptr + k0 + 20);
            if (wvalid) { w0 = *(const float4*)(Wptr + k0 + 16); w1 = *(const float4*)(Wptr + k0 + 20); }
            else        { w0 = w1 = make_float4(0.f,0.f,0.f,0.f); }
        }

        const float* __restrict__ Ab = As[buf];
        const float* __restrict__ Bb = Bs[buf];
        #pragma unroll
        for (int kk = 0; kk < 16; kk++) {
            // A row-pairs: 4 packed f32x2 straight from shared
            const ulonglong2* ap2 = (const ulonglong2*)(Ab + kk*128 + ty*8);
            ulonglong2 av0 = ap2[0], av1 = ap2[1];
            ull ap[4] = { av0.x, av0.y, av1.x, av1.y };
            // B: 8 scalars, duplicated into both lanes
            const float4* bp4 = (const float4*)(Bb + kk*128 + tx*8);
            float4 bv0 = bp4[0], bv1 = bp4[1];
            ull bd[8];
            bd[0]=pack2(bv0.x,bv0.x); bd[1]=pack2(bv0.y,bv0.y);
            bd[2]=pack2(bv0.z,bv0.z); bd[3]=pack2(bv0.w,bv0.w);
            bd[4]=pack2(bv1.x,bv1.x); bd[5]=pack2(bv1.y,bv1.y);
            bd[6]=pack2(bv1.z,bv1.z); bd[7]=pack2(bv1.w,bv1.w);
            #pragma unroll
            for (int ip=0; ip<4; ip++)
                #pragma unroll
                for (int j=0; j<8; j++)
                    ffma2(acc[ip][j], ap[ip], bd[j]);
        }

        if (more) {
            int nb = buf ^ 1;
            #pragma unroll
            for (int u=0;u<4;u++){
                As[nb][(lq+u  )*128 + lr] = (&a0.x)[u];
                As[nb][(lq+4+u)*128 + lr] = (&a1.x)[u];
                Bs[nb][(lq+u  )*128 + lr] = (&w0.x)[u];
                Bs[nb][(lq+4+u)*128 + lr] = (&w1.x)[u];
            }
            __syncthreads();
            buf = nb;
        }
    }

    // epilogue
    #pragma unroll
    for (int ip=0; ip<4; ip++) {
        int m0 = bm + ty*8 + 2*ip;
        #pragma unroll
        for (int j=0; j<8; j++) {
            int n = bn + tx*8 + j;
            if (n >= N) continue;
            float vlo, vhi;
            unpack2(vlo, vhi, acc[ip][j]);
            #pragma unroll
            for (int half=0; half<2; half++) {
                int m = m0 + half;
                float v = half ? vhi : vlo;
                if (EPI == 0) {
                    C[(size_t)m*ldc + n] = v;
                } else if (EPI == 1) {
                    v += bias[n];
                    C[(size_t)m*ldc + n] = v * sigf(v);
                } else {
                    float g  = sigf(v + bias[n]);
                    float ym = p1[(size_t)m*(2*DINNER) + n];
                    float yr = p1[(size_t)m*(2*DINNER) + DINNER + n];
                    float z  = p2[(size_t)m*DPROJ + n];
                    float sz = z * sigf(z);
                    C[(size_t)m*ldc + n] = (g*ym + (1.f-g)*yr) * sz;
                }
            }
        }
    }
}

// ---------------- SSD kernel 1: per (c,h,b): cum, Y_diag, chunk state ----------------
__global__ void __launch_bounds__(256) ssd_chunk_kernel(const float* __restrict__ A_log)
{
    int c = blockIdx.x, h = blockIdx.y, b = blockIdx.z;
    int tid = threadIdx.x, tx = tid & 15, ty = tid >> 4;
    int r = tid >> 2, q = tid & 3;
    int tok0 = b*SEQLEN + c*64;

    __shared__ float sP[16*64];
    __shared__ float sQ[16*64];
    __shared__ float sG[64*64];     // s-major: sG[s*64 + t]
    __shared__ float cum[64], sdt[64];

    if (tid < 64) sdt[tid] = g_dt[(size_t)(tok0+tid)*NHEADS + h];
    __syncthreads();
    if (tid == 0) {
        float Ah = -__expf(A_log[h]);
        float s = 0.f;
        for (int t = 0; t < 64; t++) { s += Ah*sdt[t]; cum[t] = s; }
    }
    __syncthreads();
    if (tid < 64) g_cumA[(size_t)(tok0+tid)*NHEADS + h] = cum[tid];
    if (tid == 0) g_alast[(size_t)(b*NCHUNK+c)*NHEADS + h] = cum[63];

    float acc[4][4];
    // ---- G = C * B^T over n (DSTATE=64) ----
    #pragma unroll
    for (int i=0;i<4;i++)
        #pragma unroll
        for (int j=0;j<4;j++) acc[i][j]=0.f;
    for (int n0 = 0; n0 < 64; n0 += 16) {
        float4 cv = *(const float4*)(g_xbc + (size_t)(tok0+r)*CONVDIM + OFF_C + n0 + q*4);
        float4 bv = *(const float4*)(g_xbc + (size_t)(tok0+r)*CONVDIM + OFF_B + n0 + q*4);
        sP[(q*4+0)*64+r]=cv.x; sP[(q*4+1)*64+r]=cv.y;
        sP[(q*4+2)*64+r]=cv.z; sP[(q*4+3)*64+r]=cv.w;
        sQ[(q*4+0)*64+r]=bv.x; sQ[(q*4+1)*64+r]=bv.y;
        sQ[(q*4+2)*64+r]=bv.z; sQ[(q*4+3)*64+r]=bv.w;
        __syncthreads();
        mm16(sP, sQ, acc, ty, tx);
        __syncthreads();
    }
    #pragma unroll
    for (int i=0;i<4;i++)
        #pragma unroll
        for (int j=0;j<4;j++){
            int t = ty+16*i, s = tx+16*j;
            sG[s*64 + t] = (s <= t) ? acc[i][j]*__expf(cum[t]-cum[s]) : 0.f;
        }
    __syncthreads();

    // ---- Y_diag = Gm @ X   (X = x*dt) ----
    #pragma unroll
    for (int i=0;i<4;i++)
        #pragma unroll
        for (int j=0;j<4;j++) acc[i][j]=0.f;
    {
        int kk2 = tid >> 4, p4 = tid & 15;
        for (int s0 = 0; s0 < 64; s0 += 16) {
            float d = sdt[s0+kk2];
            float4 xv = *(const float4*)(g_xbc + (size_t)(tok0+s0+kk2)*CONVDIM + h*64 + p4*4);
            sQ[kk2*64 + p4*4+0]=xv.x*d; sQ[kk2*64 + p4*4+1]=xv.y*d;
            sQ[kk2*64 + p4*4+2]=xv.z*d; sQ[kk2*64 + p4*4+3]=xv.w*d;
            __syncthreads();
            mm16(&sG[s0*64], sQ, acc, ty, tx);
            __syncthreads();
        }
    }
    #pragma unroll
    for (int i=0;i<4;i++)
        #pragma unroll
        for (int j=0;j<4;j++)
            g_hcat[(size_t)(tok0+ty+16*i)*(2*DINNER) + h*64 + tx+16*j] = acc[i][j];

    // ---- states[p][n] = sum_t (x*dt*exp(alast-cum_t))[t,p] * B[t,n] ----
    #pragma unroll
    for (int i=0;i<4;i++)
        #pragma unroll
        for (int j=0;j<4;j++) acc[i][j]=0.f;
    {
        int kk2 = tid >> 4, p4 = tid & 15;
        float alastv = cum[63];
        for (int t0 = 0; t0 < 64; t0 += 16) {
            float f = sdt[t0+kk2] * __expf(alastv - cum[t0+kk2]);
            float4 xv = *(const float4*)(g_xbc + (size_t)(tok0+t0+kk2)*CONVDIM + h*64 + p4*4);
            float4 bv = *(const float4*)(g_xbc + (size_t)(tok0+t0+kk2)*CONVDIM + OFF_B + p4*4);
            sP[kk2*64 + p4*4+0]=xv.x*f; sP[kk2*64 + p4*4+1]=xv.y*f;
            sP[kk2*64 + p4*4+2]=xv.z*f; sP[kk2*64 + p4*4+3]=xv.w*f;
            sQ[kk2*64 + p4*4+0]=bv.x;   sQ[kk2*64 + p4*4+1]=bv.y;
            sQ[kk2*64 + p4*4+2]=bv.z;   sQ[kk2*64 + p4*4+3]=bv.w;
            __syncthreads();
            mm16(sP, sQ, acc, ty, tx);
            __syncthreads();
        }
    }
    {
        float* sb = g_states + ((size_t)(b*NCHUNK+c)*NHEADS + h)*4096;
        #pragma unroll
        for (int i=0;i<4;i++)
            #pragma unroll
            for (int j=0;j<4;j++)
                sb[(ty+16*i)*64 + tx+16*j] = acc[i][j];
    }
}

// ---------------- SSD kernel 2: cross-chunk state scan ----------------
__global__ void __launch_bounds__(256) ssd_scan_kernel()
{
    int h = blockIdx.x, b = blockIdx.y;
    int tid = threadIdx.x;
    float S[16];
    #pragma unroll
    for (int u=0;u<16;u++) S[u]=0.f;
    size_t eoff = (size_t)tid*16;
    for (int c = 0; c < NCHUNK; c++) {
        float e = __expf(g_alast[(size_t)(b*NCHUNK+c)*NHEADS + h]);
        float* ptr = g_states + ((size_t)(b*NCHUNK+c)*NHEADS + h)*4096 + eoff;
        #pragma unroll
        for (int u=0;u<16;u+=4){
            float4 o = *(float4*)(ptr+u);
            *(float4*)(ptr+u) = make_float4(S[u],S[u+1],S[u+2],S[u+3]);
            S[u+0]=S[u+0]*e+o.x; S[u+1]=S[u+1]*e+o.y;
            S[u+2]=S[u+2]*e+o.z; S[u+3]=S[u+3]*e+o.w;
        }
    }
}

// ---------------- SSD kernel 3: Y += exp(cum)*(C @ S_in^T) + x*D_skip ----------------
__global__ void __launch_bounds__(256) ssd_off_kernel(const float* __restrict__ D_skip)
{
    int c = blockIdx.x, h = blockIdx.y, b = blockIdx.z;
    int tid = threadIdx.x, tx = tid & 15, ty = tid >> 4;
    int r = tid >> 2, q = tid & 3;
    int tok0 = b*SEQLEN + c*64;

    __shared__ float sS[64*64];     // n-major: sS[n*64 + p]
    __shared__ float sC[16*64];
    __shared__ float cum[64];

    {
        const float* sb = g_states + ((size_t)(b*NCHUNK+c)*NHEADS + h)*4096;
        #pragma unroll
        for (int u=0;u<4;u++){
            float4 v = *(const float4*)(sb + r*64 + q*16 + u*4);
            sS[(q*16+u*4+0)*64 + r]=v.x; sS[(q*16+u*4+1)*64 + r]=v.y;
            sS[(q*16+u*4+2)*64 + r]=v.z; sS[(q*16+u*4+3)*64 + r]=v.w;
        }
    }
    if (tid < 64) cum[tid] = g_cumA[(size_t)(tok0+tid)*NHEADS + h];
    __syncthreads();

    float acc[4][4];
    #pragma unroll
    for (int i=0;i<4;i++)
        #pragma unroll
        for (int j=0;j<4;j++) acc[i][j]=0.f;
    for (int n0 = 0; n0 < 64; n0 += 16) {
        float4 cv = *(const float4*)(g_xbc + (size_t)(tok0+r)*CONVDIM + OFF_C + n0 + q*4);
        sC[(q*4+0)*64+r]=cv.x; sC[(q*4+1)*64+r]=cv.y;
        sC[(q*4+2)*64+r]=cv.z; sC[(q*4+3)*64+r]=cv.w;
        __syncthreads();
        mm16(sC, &sS[n0*64], acc, ty, tx);
        __syncthreads();
    }
    float dsk = D_skip[h];
    #pragma unroll
    for (int i=0;i<4;i++){
        int t = ty+16*i;
        float e = __expf(cum[t]);
        #pragma unroll
        for (int j=0;j<4;j++){
            int p = tx+16*j;
            float xv = g_xbc[(size_t)(tok0+t)*CONVDIM + h*64 + p];
            size_t o = (size_t)(tok0+t)*(2*DINNER) + h*64 + p;
            g_hcat[o] = g_hcat[o] + e*acc[i][j] + xv*dsk;
        }
    }
}

// ---------------- RWKV kernel 0: per-channel chunk-local cumsum of log(w) ----------------
__global__ void rwkv_pre_kernel()
{
    int bc = blockIdx.x;            // b*NCHUNK + c
    int i = threadIdx.x;            // 64 threads
    int tok0 = (bc/NCHUNK)*SEQLEN + (bc%NCHUNK)*64;
    float cumv = 0.f;
    for (int t = 0; t < 64; t++) {
        float rw = g_proj[(size_t)(tok0+t)*DPROJ + OFF_W + i];
        cumv += -__expf(rw);
        g_wcum[(size_t)(tok0+t)*64 + i] = cumv;
    }
}

// ---------------- RWKV kernel 1: gram matrix + intra-chunk output ----------------
__global__ void __launch_bounds__(256) rwkv_gram_kernel()
{
    int bc = blockIdx.x;
    int b = bc/NCHUNK, c = bc%NCHUNK;
    int tok0 = b*SEQLEN + c*64;
    int tid = threadIdx.x, tx = tid & 15, ty = tid >> 4;
    int r = tid >> 2, q = tid & 3;

    __shared__ float sA1[64*64];    // phase A: kT[j*64+t]; phase B: cum[t*64+i]
    __shared__ float sA2[64*64];    // phase A: vT[j*64+s]; phase B: a[s*64+i]
    __shared__ float sM [64*64];    // M[t*64+s]

    // phase A: load k,v j-major
    #pragma unroll
    for (int u=0;u<4;u++){
        float4 kv = *(const float4*)(g_proj + (size_t)(tok0+r)*DPROJ + OFF_K + q*16 + u*4);
        float4 vv = *(const float4*)(g_proj + (size_t)(tok0+r)*DPROJ + OFF_V + q*16 + u*4);
        sA1[(q*16+u*4+0)*64 + r]=kv.x; sA1[(q*16+u*4+1)*64 + r]=kv.y;
        sA1[(q*16+u*4+2)*64 + r]=kv.z; sA1[(q*16+u*4+3)*64 + r]=kv.w;
        sA2[(q*16+u*4+0)*64 + r]=vv.x; sA2[(q*16+u*4+1)*64 + r]=vv.y;
        sA2[(q*16+u*4+2)*64 + r]=vv.z; sA2[(q*16+u*4+3)*64 + r]=vv.w;
    }
    __syncthreads();
    float acc[4][4];
    #pragma unroll
    for (int i=0;i<4;i++)
        #pragma unroll
        for (int j=0;j<4;j++) acc[i][j]=0.f;
    #pragma unroll
    for (int j0 = 0; j0 < 64; j0 += 16)
        mm16(&sA1[j0*64], &sA2[j0*64], acc, ty, tx);
    __syncthreads();
    #pragma unroll
    for (int i=0;i<4;i++)
        #pragma unroll
        for (int j=0;j<4;j++)
            sM[(ty+16*i)*64 + tx+16*j] = acc[i][j];   // M[t][s] = k_t . v_s
    __syncthreads();

    // phase B: cum into sA1, a = k*bonus into sA2
    for (int idx = tid; idx < 4096; idx += 256) {
        int t = idx >> 6, i = idx & 63;
        sA1[idx] = g_wcum[(size_t)(tok0+t)*64 + i];
        sA2[idx] = g_proj[(size_t)(tok0+t)*DPROJ + OFF_K + i]
                 * g_proj[(size_t)(tok0+t)*DPROJ + OFF_BON + i];
    }
    __syncthreads();

    // intra output: y[t,i] = r_t[i] * sum_{s<=t} exp(cum_t[i]-cum_s[i]) a_s[i] M[t,s]
    {
        int i = tid & 63, tg = tid >> 6;
        for (int tt = 0; tt < 16; tt++) {
            int t = tg*16 + tt;
            float ct = sA1[t*64 + i];
            float sum = 0.f;
            for (int s = 0; s <= t; s++)
                sum = fmaf(__expf(ct - sA1[s*64+i]) * sA2[s*64+i], sM[t*64+s], sum);
            float rr = sigf(g_proj[(size_t)(tok0+t)*DPROJ + OFF_R + i]);
            g_wkvy[(size_t)(tok0+t)*64 + i] = rr * sum;
        }
    }
}

// ---------------- RWKV kernel 1b: chunk state T[i,j] + last decay ----------------
__global__ void __launch_bounds__(256) rwkv_state_kernel()
{
    int bc = blockIdx.x;
    int b = bc/NCHUNK, c = bc%NCHUNK;
    int tok0 = b*SEQLEN + c*64;
    int tid = threadIdx.x, tx = tid & 15, ty = tid >> 4;

    __shared__ float sP[64*64];     // P[s*64+i] = exp(cumlast[i]-cum_s[i])*k_s[i]*bon_s[i]
    __shared__ float sV[64*64];     // V[s*64+j] = v_s[j]

    for (int idx = tid; idx < 4096; idx += 256) {
        int s = idx >> 6, i = idx & 63;
        float cl = g_wcum[(size_t)(tok0+63)*64 + i];
        float cs = g_wcum[(size_t)(tok0+s)*64 + i];
        sP[idx] = __expf(cl - cs)
                * g_proj[(size_t)(tok0+s)*DPROJ + OFF_K + i]
                * g_proj[(size_t)(tok0+s)*DPROJ + OFF_BON + i];
        sV[idx] = g_proj[(size_t)(tok0+s)*DPROJ + OFF_V + i];
    }
    __syncthreads();
    if (tid < 64)
        g_wdecay[(size_t)bc*64 + tid] = __expf(g_wcum[(size_t)(tok0+63)*64 + tid]);

    float acc[4][4];
    #pragma unroll
    for (int i=0;i<4;i++)
        #pragma unroll
        for (int j=0;j<4;j++) acc[i][j]=0.f;
    #pragma unroll
    for (int s0 = 0; s0 < 64; s0 += 16)
        mm16(&sP[s0*64], &sV[s0*64], acc, ty, tx);

    float* T = g_wT + (size_t)bc*4096;
    #pragma unroll
    for (int i=0;i<4;i++)
        #pragma unroll
        for (int j=0;j<4;j++)
            T[(ty+16*i)*64 + tx+16*j] = acc[i][j];
}

// ---------------- RWKV kernel 2: cross-chunk state scan (per-row decay) ----------------
__global__ void __launch_bounds__(256) rwkv_scan_kernel()
{
    int b = blockIdx.x;
    int tid = threadIdx.x;
    int i = tid >> 2, jb = (tid & 3)*16;
    float S[16];
    #pragma unroll
    for (int u=0;u<16;u++) S[u]=0.f;
    for (int c = 0; c < NCHUNK; c++) {
        int bc = b*NCHUNK + c;
        float e = g_wdecay[(size_t)bc*64 + i];
        float* ptr = g_wT + (size_t)bc*4096 + i*64 + jb;
        #pragma unroll
        for (int u=0;u<16;u+=4){
            float4 o = *(float4*)(ptr+u);
            *(float4*)(ptr+u) = make_float4(S[u],S[u+1],S[u+2],S[u+3]);
            S[u+0]=S[u+0]*e+o.x; S[u+1]=S[u+1]*e+o.y;
            S[u+2]=S[u+2]*e+o.z; S[u+3]=S[u+3]*e+o.w;
        }
    }
}

// ---------------- RWKV kernel 3: inter-chunk output ----------------
__global__ void __launch_bounds__(256) rwkv_inter_kernel()
{
    int bc = blockIdx.x;
    int b = bc/NCHUNK, c = bc%NCHUNK;
    int tok0 = b*SEQLEN + c*64;
    int tid = threadIdx.x, tx = tid & 15, ty = tid >> 4;
    int r = tid >> 2, q = tid & 3;

    __shared__ float sK[64*64];     // j-major: sK[j*64+t] = k_t[j]
    __shared__ float sS[64*64];     // j-major: sS[j*64+i] = S_in[i][j]

    #pragma unroll
    for (int u=0;u<4;u++){
        float4 kv = *(const float4*)(g_proj + (size_t)(tok0+r)*DPROJ + OFF_K + q*16 + u*4);
        sK[(q*16+u*4+0)*64 + r]=kv.x; sK[(q*16+u*4+1)*64 + r]=kv.y;
        sK[(q*16+u*4+2)*64 + r]=kv.z; sK[(q*16+u*4+3)*64 + r]=kv.w;
        float4 sv = *(const float4*)(g_wT + (size_t)bc*4096 + r*64 + q*16 + u*4);
        sS[(q*16+u*4+0)*64 + r]=sv.x; sS[(q*16+u*4+1)*64 + r]=sv.y;
        sS[(q*16+u*4+2)*64 + r]=sv.z; sS[(q*16+u*4+3)*64 + r]=sv.w;
    }
    __syncthreads();

    float acc[4][4];
    #pragma unroll
    for (int i=0;i<4;i++)
        #pragma unroll
        for (int j=0;j<4;j++) acc[i][j]=0.f;
    #pragma unroll
    for (int j0 = 0; j0 < 64; j0 += 16)
        mm16(&sK[j0*64], &sS[j0*64], acc, ty, tx);  // acc[t][i] = sum_j k_t[j] S_in[i][j]

    #pragma unroll
    for (int ii=0;ii<4;ii++){
        int t = ty+16*ii;
        #pragma unroll
        for (int jj=0;jj<4;jj++){
            int i = tx+16*jj;
            float rr = sigf(g_proj[(size_t)(tok0+t)*DPROJ + OFF_R + i]);
            float e  = __expf(g_wcum[(size_t)(tok0+t)*64 + i]);
            size_t o = (size_t)(tok0+t)*64 + i;
            g_wkvy[o] = g_wkvy[o] + rr * e * acc[ii][jj];
        }
    }
}

// ---------------- LayerNorm ----------------
__global__ void __launch_bounds__(256) ln_kernel(const float* __restrict__ g,
                                                 const float* __restrict__ bbias)
{
    int m = blockIdx.x;
    int tid = threadIdx.x;
    const float* row = g_ypre + (size_t)m*DINNER;
    float s = 0.f, s2 = 0.f;
    #pragma unroll
    for (int u = 0; u < 6; u++) {
        float v = row[tid + 256*u];
        s += v; s2 += v*v;
    }
    __shared__ float red[16];
    #pragma unroll
    for (int o = 16; o > 0; o >>= 1) {
        s  += __shfl_xor_sync(0xffffffff, s, o);
        s2 += __shfl_xor_sync(0xffffffff, s2, o);
    }
    if ((tid & 31) == 0) { red[tid>>5] = s; red[8 + (tid>>5)] = s2; }
    __syncthreads();
    if (tid < 8) { s = red[tid]; s2 = red[8+tid]; }
    else { s = 0.f; s2 = 0.f; }
    if (tid < 32) {
        #pragma unroll
        for (int o = 4; o > 0; o >>= 1) {
            s  += __shfl_xor_sync(0xffffffff, s, o);
            s2 += __shfl_xor_sync(0xffffffff, s2, o);
        }
    }
    if (tid == 0) { red[0] = s; red[1] = s2; }
    __syncthreads();
    float mu = red[0] * (1.f/DINNER);
    float var = red[1] * (1.f/DINNER) - mu*mu;
    float inv = rsqrtf(var + 1e-5f);
    #pragma unroll
    for (int u = 0; u < 6; u++) {
        int ch = tid + 256*u;
        float v = (row[ch] - mu) * inv;
        g_ynorm[(size_t)m*DINNER + ch] = v * g[ch] + bbias[ch];
    }
}

// ---------------- launch ----------------
extern "C" void kernel_launch(void* const* d_in, const int* in_sizes, int n_in,
                              void* d_out, int out_size)
{
    const float* u         = (const float*)d_in[0];
    const float* in_proj_w = (const float*)d_in[1];
    const float* conv_w    = (const float*)d_in[2];
    const float* conv_b    = (const float*)d_in[3];
    const float* dt_bias   = (const float*)d_in[4];
    const float* A_log     = (const float*)d_in[5];
    const float* D_skip    = (const float*)d_in[6];
    const float* time_mix  = (const float*)d_in[7];
    const float* wkv_up_w  = (const float*)d_in[8];
    const float* fg_w1     = (const float*)d_in[9];
    const float* fg_b1     = (const float*)d_in[10];
    const float* fg_w2     = (const float*)d_in[11];
    const float* fg_b2     = (const float*)d_in[12];
    const float* ln_g      = (const float*)d_in[13];
    const float* ln_b      = (const float*)d_in[14];
    const float* out_proj_w= (const float*)d_in[15];
    float* out = (float*)d_out;

    float* p_umix;  cudaGetSymbolAddress((void**)&p_umix,  g_umix);
    float* p_proj;  cudaGetSymbolAddress((void**)&p_proj,  g_proj);
    float* p_hcat;  cudaGetSymbolAddress((void**)&p_hcat,  g_hcat);
    float* p_h;     cudaGetSymbolAddress((void**)&p_h,     g_h);
    float* p_ypre;  cudaGetSymbolAddress((void**)&p_ypre,  g_ypre);
    float* p_ynorm; cudaGetSymbolAddress((void**)&p_ynorm, g_ynorm);
    float* p_wkvy;  cudaGetSymbolAddress((void**)&p_wkvy,  g_wkvy);

    // 1. time-mix
    umix_kernel<<<(NTOK*DMODEL)/256, 256>>>(u, time_mix);
    // 2. in_proj GEMM: (8192 x 3544) = umix (8192x768) @ W^T
    sgemm2_kernel<0><<<dim3((DPROJ+127)/128, NTOK/128), 256>>>(
        p_umix, DMODEL, in_proj_w, nullptr, p_proj, DPROJ, DPROJ, DMODEL, nullptr, nullptr);
    // 3. dt softplus
    dt_kernel<<<(NTOK*NHEADS)/256, 256>>>(dt_bias);
    // 4. causal conv + silu
    conv_kernel<<<(NTOK*CONVDIM)/256, 256>>>(conv_w, conv_b);
    // 5-7. SSD
    ssd_chunk_kernel<<<dim3(NCHUNK, NHEADS, BATCH), 256>>>(A_log);
    ssd_scan_kernel<<<dim3(NHEADS, BATCH), 256>>>();
    ssd_off_kernel<<<dim3(NCHUNK, NHEADS, BATCH), 256>>>(D_skip);
    // 8-12. RWKV
    rwkv_pre_kernel<<<BATCH*NCHUNK, 64>>>();
    rwkv_gram_kernel<<<BATCH*NCHUNK, 256>>>();
    rwkv_state_kernel<<<BATCH*NCHUNK, 256>>>();
    rwkv_scan_kernel<<<BATCH, 256>>>();
    rwkv_inter_kernel<<<BATCH*NCHUNK, 256>>>();
    // 13. wkv_up GEMM -> right half of hcat
    sgemm2_kernel<0><<<dim3(DINNER/128, NTOK/128), 256>>>(
        p_wkvy, 64, wkv_up_w, nullptr, p_hcat + DINNER, 2*DINNER, DINNER, 64, nullptr, nullptr);
    // 14. fg1: h = silu(hcat @ fg_w1^T + b1)
    sgemm2_kernel<1><<<dim3(DINNER/128, NTOK/128), 256>>>(
        p_hcat, 2*DINNER, fg_w1, fg_b1, p_h, DINNER, DINNER, 2*DINNER, nullptr, nullptr);
    // 15. fg2 + gate combine + silu(z)
    sgemm2_kernel<2><<<dim3(DINNER/128, NTOK/128), 256>>>(
        p_h, DINNER, fg_w2, fg_b2, p_ypre, DINNER, DINNER, DINNER, p_hcat, p_proj);
    // 16. LayerNorm
    ln_kernel<<<NTOK, 256>>>(ln_g, ln_b);
    // 17. out_proj GEMM -> d_out
    sgemm2_kernel<0><<<dim3(DMODEL/128, NTOK/128), 256>>>(
        p_ynorm, DINNER, out_proj_w, nullptr, out, DMODEL, DMODEL, DINNER, nullptr, nullptr);
}

// round 11
// speedup vs baseline: 2.4752x; 1.7384x over previous
#include <cuda_runtime.h>
#include <math.h>
#include <stdint.h>

// ---------------- problem constants ----------------
#define BATCH   2
#define SEQLEN  4096
#define DMODEL  768
#define DINNER  1536
#define NHEADS  24
#define CONVDIM 1664
#define DPROJ   3544
#define NTOK    (BATCH*SEQLEN)      // 8192
#define NCHUNK  (SEQLEN/64)         // 64

// column offsets inside one proj row (width DPROJ)
#define OFF_XBC 1536
#define OFF_B   1536                // within g_xbc row (width CONVDIM)
#define OFF_C   1600                // within g_xbc row
#define OFF_DT  3200
#define OFF_R   3224
#define OFF_K   3288
#define OFF_V   3352
#define OFF_W   3416
#define OFF_BON 3480

// ---------------- scratch: static device globals (no allocs) ----------------
__device__ float g_umix [(size_t)NTOK*DMODEL];
__device__ float g_proj [(size_t)NTOK*DPROJ];
__device__ float g_xbc  [(size_t)NTOK*CONVDIM];
__device__ float g_dt   [(size_t)NTOK*NHEADS];
__device__ float g_cumA [(size_t)NTOK*NHEADS];
__device__ float g_alast[(size_t)BATCH*NCHUNK*NHEADS];
__device__ float g_states[(size_t)BATCH*NCHUNK*NHEADS*4096];
__device__ float g_hcat [(size_t)NTOK*2*DINNER];   // [y_mamba | y_rwkv]
__device__ float g_h    [(size_t)NTOK*DINNER];
__device__ float g_ypre [(size_t)NTOK*DINNER];
__device__ float g_ynorm[(size_t)NTOK*DINNER];
__device__ float g_wcum [(size_t)NTOK*64];
__device__ float g_wT   [(size_t)BATCH*NCHUNK*4096];
__device__ float g_wdecay[(size_t)BATCH*NCHUNK*64];
__device__ float g_wkvy [(size_t)NTOK*64];

__device__ __forceinline__ float sigf(float x){ return 1.f/(1.f+__expf(-x)); }

// round fp32 -> tf32 bit pattern (kept in a float register)
__device__ __forceinline__ float tf32r(float x){
    uint32_t u; asm("cvt.rna.tf32.f32 %0, %1;" : "=r"(u) : "f"(x));
    return __uint_as_float(u);
}

// m16n8k8 tf32 MMA (baseline PTX, sm_80+; runs on sm_103 via HMMA)
__device__ __forceinline__ void mma8(float d[4], const uint32_t a[4], const uint32_t b[2]){
    asm volatile(
        "mma.sync.aligned.m16n8k8.row.col.f32.tf32.tf32.f32 "
        "{%0,%1,%2,%3}, {%4,%5,%6,%7}, {%8,%9}, {%0,%1,%2,%3};"
        : "+f"(d[0]), "+f"(d[1]), "+f"(d[2]), "+f"(d[3])
        : "r"(a[0]), "r"(a[1]), "r"(a[2]), "r"(a[3]), "r"(b[0]), "r"(b[1]));
}

// ---------------- tensor-core tf32 GEMM: C = A(MxK) @ W(NxK)^T ----------------
// 128x128 CTA tile, 256 threads = 8 warps as 4(M) x 2(N); warp tile 32x64.
// K-chunks of 32; smem rows padded to stride 36 (conflict-free fragment LDS).
// EPI 0: store. EPI 1: silu(acc+bias). EPI 2: gate combine.
#define KT    32
#define AST   36
#define TBUF  (128*AST)            // floats per tile buffer
#define GEMM_SMEM (4*TBUF*4)       // 2 bufs x (A+B) = 73728 bytes
template<int EPI>
__global__ void __launch_bounds__(256) mgemm_kernel(
    const float* __restrict__ A,
    const float* __restrict__ W,
    const float* __restrict__ bias,
    float* __restrict__ C, int ldc,
    int N, int K,
    const float* __restrict__ p1, const float* __restrict__ p2)
{
    extern __shared__ float sm[];
    // layout: A buf0 [0], A buf1 [TBUF], B buf0 [2*TBUF], B buf1 [3*TBUF]
    int tid = threadIdx.x;
    int bm = blockIdx.y * 128, bn = blockIdx.x * 128;

    int lr = tid >> 1;              // load row 0..127
    int lc = (tid & 1) * 16;        // load col base 0/16
    const float* Arow = A + (size_t)(bm + lr)*K + lc;
    const float* Wrow = W + (size_t)(bn + lr)*K + lc;
    bool wv = (bn + lr) < N;

    int lane = tid & 31, w = tid >> 5;
    int wm = (w >> 1) * 32, wn = (w & 1) * 64;
    int gr = lane >> 2, tg = lane & 3;

    float acc[2][8][4];
    #pragma unroll
    for (int mi=0;mi<2;mi++)
        #pragma unroll
        for (int ni=0;ni<8;ni++)
            #pragma unroll
            for (int e=0;e<4;e++) acc[mi][ni][e]=0.f;

    int nch = K / KT;

    // fill buffer 0
    {
        float* As_ = sm;
        float* Bs_ = sm + 2*TBUF;
        #pragma unroll
        for (int u=0;u<4;u++){
            float4 a = *(const float4*)(Arow + 4*u);
            float4 b = wv ? *(const float4*)(Wrow + 4*u) : make_float4(0.f,0.f,0.f,0.f);
            int o = lr*AST + lc + 4*u;
            As_[o+0]=tf32r(a.x); As_[o+1]=tf32r(a.y); As_[o+2]=tf32r(a.z); As_[o+3]=tf32r(a.w);
            Bs_[o+0]=tf32r(b.x); Bs_[o+1]=tf32r(b.y); Bs_[o+2]=tf32r(b.z); Bs_[o+3]=tf32r(b.w);
        }
    }
    __syncthreads();

    for (int c = 0; c < nch; c++) {
        int buf = c & 1;
        bool more = (c + 1) < nch;
        float4 pa[4], pb[4];
        if (more) {
            int k0 = (c + 1) * KT;
            #pragma unroll
            for (int u=0;u<4;u++){
                pa[u] = *(const float4*)(Arow + k0 + 4*u);
                pb[u] = wv ? *(const float4*)(Wrow + k0 + 4*u) : make_float4(0.f,0.f,0.f,0.f);
            }
        }

        const float* Ab = sm + buf*TBUF;
        const float* Bb = sm + 2*TBUF + buf*TBUF;
        #pragma unroll
        for (int k8 = 0; k8 < 4; k8++) {
            int kb = k8 * 8;
            uint32_t afr[2][4];
            #pragma unroll
            for (int mi=0;mi<2;mi++){
                const float* ap = Ab + (wm + mi*16 + gr)*AST + kb + tg;
                afr[mi][0] = __float_as_uint(ap[0]);
                afr[mi][1] = __float_as_uint(ap[8*AST]);
                afr[mi][2] = __float_as_uint(ap[4]);
                afr[mi][3] = __float_as_uint(ap[8*AST+4]);
            }
            uint32_t bfr[8][2];
            #pragma unroll
            for (int ni=0;ni<8;ni++){
                const float* bp = Bb + (wn + ni*8 + gr)*AST + kb + tg;
                bfr[ni][0] = __float_as_uint(bp[0]);
                bfr[ni][1] = __float_as_uint(bp[4]);
            }
            #pragma unroll
            for (int mi=0;mi<2;mi++)
                #pragma unroll
                for (int ni=0;ni<8;ni++)
                    mma8(acc[mi][ni], afr[mi], bfr[ni]);
        }

        if (more) {
            int nb = buf ^ 1;
            float* As_ = sm + nb*TBUF;
            float* Bs_ = sm + 2*TBUF + nb*TBUF;
            #pragma unroll
            for (int u=0;u<4;u++){
                int o = lr*AST + lc + 4*u;
                As_[o+0]=tf32r(pa[u].x); As_[o+1]=tf32r(pa[u].y);
                As_[o+2]=tf32r(pa[u].z); As_[o+3]=tf32r(pa[u].w);
                Bs_[o+0]=tf32r(pb[u].x); Bs_[o+1]=tf32r(pb[u].y);
                Bs_[o+2]=tf32r(pb[u].z); Bs_[o+3]=tf32r(pb[u].w);
            }
            __syncthreads();
        }
    }

    // ---- epilogue ----
    #pragma unroll
    for (int mi=0;mi<2;mi++){
        #pragma unroll
        for (int ni=0;ni<8;ni++){
            int col = bn + wn + ni*8 + 2*tg;
            #pragma unroll
            for (int half=0; half<2; half++){          // c0/c1 vs c2/c3
                int m = bm + wm + mi*16 + gr + half*8;
                #pragma unroll
                for (int e=0; e<2; e++){
                    int n = col + e;
                    if (n >= N) continue;
                    float v = acc[mi][ni][half*2 + e];
                    if (EPI == 0) {
                        C[(size_t)m*ldc + n] = v;
                    } else if (EPI == 1) {
                        v += bias[n];
                        C[(size_t)m*ldc + n] = v * sigf(v);
                    } else {
                        float g  = sigf(v + bias[n]);
                        float ym = p1[(size_t)m*(2*DINNER) + n];
                        float yr = p1[(size_t)m*(2*DINNER) + DINNER + n];
                        float z  = p2[(size_t)m*DPROJ + n];
                        float sz = z * sigf(z);
                        C[(size_t)m*ldc + n] = (g*ym + (1.f-g)*yr) * sz;
                    }
                }
            }
        }
    }
}

// 16-step k-major micro-GEMM (fp32, for scan kernels)
__device__ __forceinline__ void mm16(const float* __restrict__ P,
                                     const float* __restrict__ Q,
                                     float acc[4][4], int ty, int tx)
{
    #pragma unroll
    for (int kk = 0; kk < 16; kk++) {
        float a[4], b[4];
        #pragma unroll
        for (int i=0;i<4;i++) a[i] = P[kk*64 + ty + 16*i];
        #pragma unroll
        for (int j=0;j<4;j++) b[j] = Q[kk*64 + tx + 16*j];
        #pragma unroll
        for (int i=0;i<4;i++)
            #pragma unroll
            for (int j=0;j<4;j++) acc[i][j] = fmaf(a[i], b[j], acc[i][j]);
    }
}

// ---------------- elementwise kernels ----------------
__global__ void umix_kernel(const float* __restrict__ u, const float* __restrict__ tm)
{
    int idx = blockIdx.x*256 + threadIdx.x;
    if (idx >= NTOK*DMODEL) return;
    int m = idx / DMODEL, ch = idx - m*DMODEL;
    int t = m & (SEQLEN-1);
    float tmx = tm[ch];
    float cur = u[idx];
    float prev = (t > 0) ? u[idx - DMODEL] : 0.f;
    g_umix[idx] = cur*tmx + prev*(1.f - tmx);
}

__global__ void conv_kernel(const float* __restrict__ cw, const float* __restrict__ cb)
{
    int idx = blockIdx.x*256 + threadIdx.x;
    if (idx >= NTOK*CONVDIM) return;
    int m = idx / CONVDIM, ch = idx - m*CONVDIM;
    int t = m & (SEQLEN-1);
    float acc = cb[ch];
    #pragma unroll
    for (int k2 = 0; k2 < 4; k2++) {
        int tt = t - 3 + k2;
        if (tt >= 0)
            acc = fmaf(cw[ch*4+k2], g_proj[(size_t)(m-3+k2)*DPROJ + OFF_XBC + ch], acc);
    }
    g_xbc[(size_t)m*CONVDIM + ch] = acc * sigf(acc);   // SiLU
}

__global__ void dt_kernel(const float* __restrict__ dt_bias)
{
    int idx = blockIdx.x*256 + threadIdx.x;
    if (idx >= NTOK*NHEADS) return;
    int hh = idx % NHEADS;
    size_t m = idx / NHEADS;
    float x = g_proj[m*DPROJ + OFF_DT + hh] + dt_bias[hh];
    g_dt[idx] = (x > 20.f) ? x : log1pf(__expf(x));
}

// ---------------- SSD kernel 1: per (c,h,b): cum, Y_diag, chunk state ----------------
__global__ void __launch_bounds__(256) ssd_chunk_kernel(const float* __restrict__ A_log)
{
    int c = blockIdx.x, h = blockIdx.y, b = blockIdx.z;
    int tid = threadIdx.x, tx = tid & 15, ty = tid >> 4;
    int r = tid >> 2, q = tid & 3;
    int tok0 = b*SEQLEN + c*64;

    __shared__ float sP[16*64];
    __shared__ float sQ[16*64];
    __shared__ float sG[64*64];     // s-major: sG[s*64 + t]
    __shared__ float cum[64], sdt[64];

    if (tid < 64) sdt[tid] = g_dt[(size_t)(tok0+tid)*NHEADS + h];
    __syncthreads();
    if (tid == 0) {
        float Ah = -__expf(A_log[h]);
        float s = 0.f;
        for (int t = 0; t < 64; t++) { s += Ah*sdt[t]; cum[t] = s; }
    }
    __syncthreads();
    if (tid < 64) g_cumA[(size_t)(tok0+tid)*NHEADS + h] = cum[tid];
    if (tid == 0) g_alast[(size_t)(b*NCHUNK+c)*NHEADS + h] = cum[63];

    float acc[4][4];
    #pragma unroll
    for (int i=0;i<4;i++)
        #pragma unroll
        for (int j=0;j<4;j++) acc[i][j]=0.f;
    for (int n0 = 0; n0 < 64; n0 += 16) {
        float4 cv = *(const float4*)(g_xbc + (size_t)(tok0+r)*CONVDIM + OFF_C + n0 + q*4);
        float4 bv = *(const float4*)(g_xbc + (size_t)(tok0+r)*CONVDIM + OFF_B + n0 + q*4);
        sP[(q*4+0)*64+r]=cv.x; sP[(q*4+1)*64+r]=cv.y;
        sP[(q*4+2)*64+r]=cv.z; sP[(q*4+3)*64+r]=cv.w;
        sQ[(q*4+0)*64+r]=bv.x; sQ[(q*4+1)*64+r]=bv.y;
        sQ[(q*4+2)*64+r]=bv.z; sQ[(q*4+3)*64+r]=bv.w;
        __syncthreads();
        mm16(sP, sQ, acc, ty, tx);
        __syncthreads();
    }
    #pragma unroll
    for (int i=0;i<4;i++)
        #pragma unroll
        for (int j=0;j<4;j++){
            int t = ty+16*i, s = tx+16*j;
            sG[s*64 + t] = (s <= t) ? acc[i][j]*__expf(cum[t]-cum[s]) : 0.f;
        }
    __syncthreads();

    #pragma unroll
    for (int i=0;i<4;i++)
        #pragma unroll
        for (int j=0;j<4;j++) acc[i][j]=0.f;
    {
        int kk2 = tid >> 4, p4 = tid & 15;
        for (int s0 = 0; s0 < 64; s0 += 16) {
            float d = sdt[s0+kk2];
            float4 xv = *(const float4*)(g_xbc + (size_t)(tok0+s0+kk2)*CONVDIM + h*64 + p4*4);
            sQ[kk2*64 + p4*4+0]=xv.x*d; sQ[kk2*64 + p4*4+1]=xv.y*d;
            sQ[kk2*64 + p4*4+2]=xv.z*d; sQ[kk2*64 + p4*4+3]=xv.w*d;
            __syncthreads();
            mm16(&sG[s0*64], sQ, acc, ty, tx);
            __syncthreads();
        }
    }
    #pragma unroll
    for (int i=0;i<4;i++)
        #pragma unroll
        for (int j=0;j<4;j++)
            g_hcat[(size_t)(tok0+ty+16*i)*(2*DINNER) + h*64 + tx+16*j] = acc[i][j];

    #pragma unroll
    for (int i=0;i<4;i++)
        #pragma unroll
        for (int j=0;j<4;j++) acc[i][j]=0.f;
    {
        int kk2 = tid >> 4, p4 = tid & 15;
        float alastv = cum[63];
        for (int t0 = 0; t0 < 64; t0 += 16) {
            float f = sdt[t0+kk2] * __expf(alastv - cum[t0+kk2]);
            float4 xv = *(const float4*)(g_xbc + (size_t)(tok0+t0+kk2)*CONVDIM + h*64 + p4*4);
            float4 bv = *(const float4*)(g_xbc + (size_t)(tok0+t0+kk2)*CONVDIM + OFF_B + p4*4);
            sP[kk2*64 + p4*4+0]=xv.x*f; sP[kk2*64 + p4*4+1]=xv.y*f;
            sP[kk2*64 + p4*4+2]=xv.z*f; sP[kk2*64 + p4*4+3]=xv.w*f;
            sQ[kk2*64 + p4*4+0]=bv.x;   sQ[kk2*64 + p4*4+1]=bv.y;
            sQ[kk2*64 + p4*4+2]=bv.z;   sQ[kk2*64 + p4*4+3]=bv.w;
            __syncthreads();
            mm16(sP, sQ, acc, ty, tx);
            __syncthreads();
        }
    }
    {
        float* sb = g_states + ((size_t)(b*NCHUNK+c)*NHEADS + h)*4096;
        #pragma unroll
        for (int i=0;i<4;i++)
            #pragma unroll
            for (int j=0;j<4;j++)
                sb[(ty+16*i)*64 + tx+16*j] = acc[i][j];
    }
}

// ---------------- SSD kernel 2: cross-chunk state scan ----------------
__global__ void __launch_bounds__(256) ssd_scan_kernel()
{
    int h = blockIdx.x, b = blockIdx.y;
    int tid = threadIdx.x;
    float S[16];
    #pragma unroll
    for (int u=0;u<16;u++) S[u]=0.f;
    size_t eoff = (size_t)tid*16;
    for (int c = 0; c < NCHUNK; c++) {
        float e = __expf(g_alast[(size_t)(b*NCHUNK+c)*NHEADS + h]);
        float* ptr = g_states + ((size_t)(b*NCHUNK+c)*NHEADS + h)*4096 + eoff;
        #pragma unroll
        for (int u=0;u<16;u+=4){
            float4 o = *(float4*)(ptr+u);
            *(float4*)(ptr+u) = make_float4(S[u],S[u+1],S[u+2],S[u+3]);
            S[u+0]=S[u+0]*e+o.x; S[u+1]=S[u+1]*e+o.y;
            S[u+2]=S[u+2]*e+o.z; S[u+3]=S[u+3]*e+o.w;
        }
    }
}

// ---------------- SSD kernel 3: Y += exp(cum)*(C @ S_in^T) + x*D_skip ----------------
__global__ void __launch_bounds__(256) ssd_off_kernel(const float* __restrict__ D_skip)
{
    int c = blockIdx.x, h = blockIdx.y, b = blockIdx.z;
    int tid = threadIdx.x, tx = tid & 15, ty = tid >> 4;
    int r = tid >> 2, q = tid & 3;
    int tok0 = b*SEQLEN + c*64;

    __shared__ float sS[64*64];     // n-major: sS[n*64 + p]
    __shared__ float sC[16*64];
    __shared__ float cum[64];

    {
        const float* sb = g_states + ((size_t)(b*NCHUNK+c)*NHEADS + h)*4096;
        #pragma unroll
        for (int u=0;u<4;u++){
            float4 v = *(const float4*)(sb + r*64 + q*16 + u*4);
            sS[(q*16+u*4+0)*64 + r]=v.x; sS[(q*16+u*4+1)*64 + r]=v.y;
            sS[(q*16+u*4+2)*64 + r]=v.z; sS[(q*16+u*4+3)*64 + r]=v.w;
        }
    }
    if (tid < 64) cum[tid] = g_cumA[(size_t)(tok0+tid)*NHEADS + h];
    __syncthreads();

    float acc[4][4];
    #pragma unroll
    for (int i=0;i<4;i++)
        #pragma unroll
        for (int j=0;j<4;j++) acc[i][j]=0.f;
    for (int n0 = 0; n0 < 64; n0 += 16) {
        float4 cv = *(const float4*)(g_xbc + (size_t)(tok0+r)*CONVDIM + OFF_C + n0 + q*4);
        sC[(q*4+0)*64+r]=cv.x; sC[(q*4+1)*64+r]=cv.y;
        sC[(q*4+2)*64+r]=cv.z; sC[(q*4+3)*64+r]=cv.w;
        __syncthreads();
        mm16(sC, &sS[n0*64], acc, ty, tx);
        __syncthreads();
    }
    float dsk = D_skip[h];
    #pragma unroll
    for (int i=0;i<4;i++){
        int t = ty+16*i;
        float e = __expf(cum[t]);
        #pragma unroll
        for (int j=0;j<4;j++){
            int p = tx+16*j;
            float xv = g_xbc[(size_t)(tok0+t)*CONVDIM + h*64 + p];
            size_t o = (size_t)(tok0+t)*(2*DINNER) + h*64 + p;
            g_hcat[o] = g_hcat[o] + e*acc[i][j] + xv*dsk;
        }
    }
}

// ---------------- RWKV kernels ----------------
__global__ void rwkv_pre_kernel()
{
    int bc = blockIdx.x;
    int i = threadIdx.x;
    int tok0 = (bc/NCHUNK)*SEQLEN + (bc%NCHUNK)*64;
    float cumv = 0.f;
    for (int t = 0; t < 64; t++) {
        float rw = g_proj[(size_t)(tok0+t)*DPROJ + OFF_W + i];
        cumv += -__expf(rw);
        g_wcum[(size_t)(tok0+t)*64 + i] = cumv;
    }
}

__global__ void __launch_bounds__(256) rwkv_gram_kernel()
{
    int bc = blockIdx.x;
    int b = bc/NCHUNK, c = bc%NCHUNK;
    int tok0 = b*SEQLEN + c*64;
    int tid = threadIdx.x, tx = tid & 15, ty = tid >> 4;
    int r = tid >> 2, q = tid & 3;

    __shared__ float sA1[64*64];
    __shared__ float sA2[64*64];
    __shared__ float sM [64*64];

    #pragma unroll
    for (int u=0;u<4;u++){
        float4 kv = *(const float4*)(g_proj + (size_t)(tok0+r)*DPROJ + OFF_K + q*16 + u*4);
        float4 vv = *(const float4*)(g_proj + (size_t)(tok0+r)*DPROJ + OFF_V + q*16 + u*4);
        sA1[(q*16+u*4+0)*64 + r]=kv.x; sA1[(q*16+u*4+1)*64 + r]=kv.y;
        sA1[(q*16+u*4+2)*64 + r]=kv.z; sA1[(q*16+u*4+3)*64 + r]=kv.w;
        sA2[(q*16+u*4+0)*64 + r]=vv.x; sA2[(q*16+u*4+1)*64 + r]=vv.y;
        sA2[(q*16+u*4+2)*64 + r]=vv.z; sA2[(q*16+u*4+3)*64 + r]=vv.w;
    }
    __syncthreads();
    float acc[4][4];
    #pragma unroll
    for (int i=0;i<4;i++)
        #pragma unroll
        for (int j=0;j<4;j++) acc[i][j]=0.f;
    #pragma unroll
    for (int j0 = 0; j0 < 64; j0 += 16)
        mm16(&sA1[j0*64], &sA2[j0*64], acc, ty, tx);
    __syncthreads();
    #pragma unroll
    for (int i=0;i<4;i++)
        #pragma unroll
        for (int j=0;j<4;j++)
            sM[(ty+16*i)*64 + tx+16*j] = acc[i][j];
    __syncthreads();

    for (int idx = tid; idx < 4096; idx += 256) {
        int t = idx >> 6, i = idx & 63;
        sA1[idx] = g_wcum[(size_t)(tok0+t)*64 + i];
        sA2[idx] = g_proj[(size_t)(tok0+t)*DPROJ + OFF_K + i]
                 * g_proj[(size_t)(tok0+t)*DPROJ + OFF_BON + i];
    }
    __syncthreads();

    {
        int i = tid & 63, tg = tid >> 6;
        for (int tt = 0; tt < 16; tt++) {
            int t = tg*16 + tt;
            float ct = sA1[t*64 + i];
            float sum = 0.f;
            for (int s = 0; s <= t; s++)
                sum = fmaf(__expf(ct - sA1[s*64+i]) * sA2[s*64+i], sM[t*64+s], sum);
            float rr = sigf(g_proj[(size_t)(tok0+t)*DPROJ + OFF_R + i]);
            g_wkvy[(size_t)(tok0+t)*64 + i] = rr * sum;
        }
    }
}

__global__ void __launch_bounds__(256) rwkv_state_kernel()
{
    int bc = blockIdx.x;
    int b = bc/NCHUNK, c = bc%NCHUNK;
    int tok0 = b*SEQLEN + c*64;
    int tid = threadIdx.x, tx = tid & 15, ty = tid >> 4;

    __shared__ float sP[64*64];
    __shared__ float sV[64*64];

    for (int idx = tid; idx < 4096; idx += 256) {
        int s = idx >> 6, i = idx & 63;
        float cl = g_wcum[(size_t)(tok0+63)*64 + i];
        float cs = g_wcum[(size_t)(tok0+s)*64 + i];
        sP[idx] = __expf(cl - cs)
                * g_proj[(size_t)(tok0+s)*DPROJ + OFF_K + i]
                * g_proj[(size_t)(tok0+s)*DPROJ + OFF_BON + i];
        sV[idx] = g_proj[(size_t)(tok0+s)*DPROJ + OFF_V + i];
    }
    __syncthreads();
    if (tid < 64)
        g_wdecay[(size_t)bc*64 + tid] = __expf(g_wcum[(size_t)(tok0+63)*64 + tid]);

    float acc[4][4];
    #pragma unroll
    for (int i=0;i<4;i++)
        #pragma unroll
        for (int j=0;j<4;j++) acc[i][j]=0.f;
    #pragma unroll
    for (int s0 = 0; s0 < 64; s0 += 16)
        mm16(&sP[s0*64], &sV[s0*64], acc, ty, tx);

    float* T = g_wT + (size_t)bc*4096;
    #pragma unroll
    for (int i=0;i<4;i++)
        #pragma unroll
        for (int j=0;j<4;j++)
            T[(ty+16*i)*64 + tx+16*j] = acc[i][j];
}

__global__ void __launch_bounds__(256) rwkv_scan_kernel()
{
    int b = blockIdx.x;
    int tid = threadIdx.x;
    int i = tid >> 2, jb = (tid & 3)*16;
    float S[16];
    #pragma unroll
    for (int u=0;u<16;u++) S[u]=0.f;
    for (int c = 0; c < NCHUNK; c++) {
        int bc = b*NCHUNK + c;
        float e = g_wdecay[(size_t)bc*64 + i];
        float* ptr = g_wT + (size_t)bc*4096 + i*64 + jb;
        #pragma unroll
        for (int u=0;u<16;u+=4){
            float4 o = *(float4*)(ptr+u);
            *(float4*)(ptr+u) = make_float4(S[u],S[u+1],S[u+2],S[u+3]);
            S[u+0]=S[u+0]*e+o.x; S[u+1]=S[u+1]*e+o.y;
            S[u+2]=S[u+2]*e+o.z; S[u+3]=S[u+3]*e+o.w;
        }
    }
}

__global__ void __launch_bounds__(256) rwkv_inter_kernel()
{
    int bc = blockIdx.x;
    int b = bc/NCHUNK, c = bc%NCHUNK;
    int tok0 = b*SEQLEN + c*64;
    int tid = threadIdx.x, tx = tid & 15, ty = tid >> 4;
    int r = tid >> 2, q = tid & 3;

    __shared__ float sK[64*64];
    __shared__ float sS[64*64];

    #pragma unroll
    for (int u=0;u<4;u++){
        float4 kv = *(const float4*)(g_proj + (size_t)(tok0+r)*DPROJ + OFF_K + q*16 + u*4);
        sK[(q*16+u*4+0)*64 + r]=kv.x; sK[(q*16+u*4+1)*64 + r]=kv.y;
        sK[(q*16+u*4+2)*64 + r]=kv.z; sK[(q*16+u*4+3)*64 + r]=kv.w;
        float4 sv = *(const float4*)(g_wT + (size_t)bc*4096 + r*64 + q*16 + u*4);
        sS[(q*16+u*4+0)*64 + r]=sv.x; sS[(q*16+u*4+1)*64 + r]=sv.y;
        sS[(q*16+u*4+2)*64 + r]=sv.z; sS[(q*16+u*4+3)*64 + r]=sv.w;
    }
    __syncthreads();

    float acc[4][4];
    #pragma unroll
    for (int i=0;i<4;i++)
        #pragma unroll
        for (int j=0;j<4;j++) acc[i][j]=0.f;
    #pragma unroll
    for (int j0 = 0; j0 < 64; j0 += 16)
        mm16(&sK[j0*64], &sS[j0*64], acc, ty, tx);

    #pragma unroll
    for (int ii=0;ii<4;ii++){
        int t = ty+16*ii;
        #pragma unroll
        for (int jj=0;jj<4;jj++){
            int i = tx+16*jj;
            float rr = sigf(g_proj[(size_t)(tok0+t)*DPROJ + OFF_R + i]);
            float e  = __expf(g_wcum[(size_t)(tok0+t)*64 + i]);
            size_t o = (size_t)(tok0+t)*64 + i;
            g_wkvy[o] = g_wkvy[o] + rr * e * acc[ii][jj];
        }
    }
}

// ---------------- LayerNorm ----------------
__global__ void __launch_bounds__(256) ln_kernel(const float* __restrict__ g,
                                                 const float* __restrict__ bbias)
{
    int m = blockIdx.x;
    int tid = threadIdx.x;
    const float* row = g_ypre + (size_t)m*DINNER;
    float s = 0.f, s2 = 0.f;
    #pragma unroll
    for (int u = 0; u < 6; u++) {
        float v = row[tid + 256*u];
        s += v; s2 += v*v;
    }
    __shared__ float red[16];
    #pragma unroll
    for (int o = 16; o > 0; o >>= 1) {
        s  += __shfl_xor_sync(0xffffffff, s, o);
        s2 += __shfl_xor_sync(0xffffffff, s2, o);
    }
    if ((tid & 31) == 0) { red[tid>>5] = s; red[8 + (tid>>5)] = s2; }
    __syncthreads();
    if (tid < 8) { s = red[tid]; s2 = red[8+tid]; }
    else { s = 0.f; s2 = 0.f; }
    if (tid < 32) {
        #pragma unroll
        for (int o = 4; o > 0; o >>= 1) {
            s  += __shfl_xor_sync(0xffffffff, s, o);
            s2 += __shfl_xor_sync(0xffffffff, s2, o);
        }
    }
    if (tid == 0) { red[0] = s; red[1] = s2; }
    __syncthreads();
    float mu = red[0] * (1.f/DINNER);
    float var = red[1] * (1.f/DINNER) - mu*mu;
    float inv = rsqrtf(var + 1e-5f);
    #pragma unroll
    for (int u = 0; u < 6; u++) {
        int ch = tid + 256*u;
        float v = (row[ch] - mu) * inv;
        g_ynorm[(size_t)m*DINNER + ch] = v * g[ch] + bbias[ch];
    }
}

// ---------------- launch ----------------
extern "C" void kernel_launch(void* const* d_in, const int* in_sizes, int n_in,
                              void* d_out, int out_size)
{
    const float* u         = (const float*)d_in[0];
    const float* in_proj_w = (const float*)d_in[1];
    const float* conv_w    = (const float*)d_in[2];
    const float* conv_b    = (const float*)d_in[3];
    const float* dt_bias   = (const float*)d_in[4];
    const float* A_log     = (const float*)d_in[5];
    const float* D_skip    = (const float*)d_in[6];
    const float* time_mix  = (const float*)d_in[7];
    const float* wkv_up_w  = (const float*)d_in[8];
    const float* fg_w1     = (const float*)d_in[9];
    const float* fg_b1     = (const float*)d_in[10];
    const float* fg_w2     = (const float*)d_in[11];
    const float* fg_b2     = (const float*)d_in[12];
    const float* ln_g      = (const float*)d_in[13];
    const float* ln_b      = (const float*)d_in[14];
    const float* out_proj_w= (const float*)d_in[15];
    float* out = (float*)d_out;

    float* p_umix;  cudaGetSymbolAddress((void**)&p_umix,  g_umix);
    float* p_proj;  cudaGetSymbolAddress((void**)&p_proj,  g_proj);
    float* p_hcat;  cudaGetSymbolAddress((void**)&p_hcat,  g_hcat);
    float* p_h;     cudaGetSymbolAddress((void**)&p_h,     g_h);
    float* p_ypre;  cudaGetSymbolAddress((void**)&p_ypre,  g_ypre);
    float* p_ynorm; cudaGetSymbolAddress((void**)&p_ynorm, g_ynorm);
    float* p_wkvy;  cudaGetSymbolAddress((void**)&p_wkvy,  g_wkvy);

    cudaFuncSetAttribute(mgemm_kernel<0>, cudaFuncAttributeMaxDynamicSharedMemorySize, GEMM_SMEM);
    cudaFuncSetAttribute(mgemm_kernel<1>, cudaFuncAttributeMaxDynamicSharedMemorySize, GEMM_SMEM);
    cudaFuncSetAttribute(mgemm_kernel<2>, cudaFuncAttributeMaxDynamicSharedMemorySize, GEMM_SMEM);

    // 1. time-mix
    umix_kernel<<<(NTOK*DMODEL)/256, 256>>>(u, time_mix);
    // 2. in_proj GEMM
    mgemm_kernel<0><<<dim3((DPROJ+127)/128, NTOK/128), 256, GEMM_SMEM>>>(
        p_umix, in_proj_w, nullptr, p_proj, DPROJ, DPROJ, DMODEL, nullptr, nullptr);
    // 3. dt softplus
    dt_kernel<<<(NTOK*NHEADS)/256, 256>>>(dt_bias);
    // 4. causal conv + silu
    conv_kernel<<<(NTOK*CONVDIM)/256, 256>>>(conv_w, conv_b);
    // 5-7. SSD
    ssd_chunk_kernel<<<dim3(NCHUNK, NHEADS, BATCH), 256>>>(A_log);
    ssd_scan_kernel<<<dim3(NHEADS, BATCH), 256>>>();
    ssd_off_kernel<<<dim3(NCHUNK, NHEADS, BATCH), 256>>>(D_skip);
    // 8-12. RWKV
    rwkv_pre_kernel<<<BATCH*NCHUNK, 64>>>();
    rwkv_gram_kernel<<<BATCH*NCHUNK, 256>>>();
    rwkv_state_kernel<<<BATCH*NCHUNK, 256>>>();
    rwkv_scan_kernel<<<BATCH, 256>>>();
    rwkv_inter_kernel<<<BATCH*NCHUNK, 256>>>();
    // 13. wkv_up GEMM -> right half of hcat
    mgemm_kernel<0><<<dim3(DINNER/128, NTOK/128), 256, GEMM_SMEM>>>(
        p_wkvy, wkv_up_w, nullptr, p_hcat + DINNER, 2*DINNER, DINNER, 64, nullptr, nullptr);
    // 14. fg1: h = silu(hcat @ fg_w1^T + b1)
    mgemm_kernel<1><<<dim3(DINNER/128, NTOK/128), 256, GEMM_SMEM>>>(
        p_hcat, fg_w1, fg_b1, p_h, DINNER, DINNER, 2*DINNER, nullptr, nullptr);
    // 15. fg2 + gate combine + silu(z)
    mgemm_kernel<2><<<dim3(DINNER/128, NTOK/128), 256, GEMM_SMEM>>>(
        p_h, fg_w2, fg_b2, p_ypre, DINNER, DINNER, DINNER, p_hcat, p_proj);
    // 16. LayerNorm
    ln_kernel<<<NTOK, 256>>>(ln_g, ln_b);
    // 17. out_proj GEMM -> d_out
    mgemm_kernel<0><<<dim3(DMODEL/128, NTOK/128), 256, GEMM_SMEM>>>(
        p_ynorm, out_proj_w, nullptr, out, DMODEL, DMODEL, DINNER, nullptr, nullptr);
}

// round 13
// speedup vs baseline: 2.8461x; 1.1499x over previous
#include <cuda_runtime.h>
#include <math.h>
#include <stdint.h>

// ---------------- problem constants ----------------
#define BATCH   2
#define SEQLEN  4096
#define DMODEL  768
#define DINNER  1536
#define NHEADS  24
#define CONVDIM 1664
#define DPROJ   3544
#define NTOK    (BATCH*SEQLEN)      // 8192
#define NCHUNK  (SEQLEN/64)         // 64

// column offsets inside one proj row (width DPROJ)
#define OFF_XBC 1536
#define OFF_B   1536                // within g_xbc row (width CONVDIM)
#define OFF_C   1600                // within g_xbc row
#define OFF_DT  3200
#define OFF_R   3224
#define OFF_K   3288
#define OFF_V   3352
#define OFF_W   3416
#define OFF_BON 3480

// ---------------- scratch: static device globals (no allocs) ----------------
__device__ float g_umix [(size_t)NTOK*DMODEL];
__device__ float g_proj [(size_t)NTOK*DPROJ];
__device__ float g_xbc  [(size_t)NTOK*CONVDIM];
__device__ float g_dt   [(size_t)NTOK*NHEADS];
__device__ float g_cumA [(size_t)NTOK*NHEADS];
__device__ float g_alast[(size_t)BATCH*NCHUNK*NHEADS];
__device__ float g_states[(size_t)BATCH*NCHUNK*NHEADS*4096];
__device__ float g_hcat [(size_t)NTOK*2*DINNER];   // [y_mamba | y_rwkv]
__device__ float g_h    [(size_t)NTOK*DINNER];
__device__ float g_ypre [(size_t)NTOK*DINNER];
__device__ float g_ynorm[(size_t)NTOK*DINNER];
__device__ float g_wcum [(size_t)NTOK*64];
__device__ float g_wT   [(size_t)BATCH*NCHUNK*4096];
__device__ float g_wdecay[(size_t)BATCH*NCHUNK*64];
__device__ float g_wkvy [(size_t)NTOK*64];

// tf32-preconverted weights
__device__ float g_wi [(size_t)DPROJ*DMODEL];
__device__ float g_w1 [(size_t)DINNER*2*DINNER];
__device__ float g_w2 [(size_t)DINNER*DINNER];
__device__ float g_wo [(size_t)DMODEL*DINNER];
__device__ float g_wu [(size_t)DINNER*64];

__device__ __forceinline__ float sigf(float x){ return 1.f/(1.f+__expf(-x)); }

// round fp32 -> tf32 bit pattern (kept in a float register)
__device__ __forceinline__ float tf32r(float x){
    uint32_t u; asm("cvt.rna.tf32.f32 %0, %1;" : "=r"(u) : "f"(x));
    return __uint_as_float(u);
}

__device__ __forceinline__ uint32_t smem_u32(const void* p){
    uint32_t a;
    asm("{ .reg .u64 t; cvta.to.shared.u64 t, %1; cvt.u32.u64 %0, t; }" : "=r"(a) : "l"(p));
    return a;
}

// m16n8k8 tf32 MMA (baseline PTX, sm_80+)
__device__ __forceinline__ void mma8(float d[4], const uint32_t a[4], const uint32_t b[2]){
    asm volatile(
        "mma.sync.aligned.m16n8k8.row.col.f32.tf32.tf32.f32 "
        "{%0,%1,%2,%3}, {%4,%5,%6,%7}, {%8,%9}, {%0,%1,%2,%3};"
        : "+f"(d[0]), "+f"(d[1]), "+f"(d[2]), "+f"(d[3])
        : "r"(a[0]), "r"(a[1]), "r"(a[2]), "r"(a[3]), "r"(b[0]), "r"(b[1]));
}

__device__ __forceinline__ void cp16(uint32_t dst, const void* src, int szbytes){
    asm volatile("cp.async.cg.shared.global [%0], [%1], 16, %2;"
                 :: "r"(dst), "l"(src), "r"(szbytes) : "memory");
}
#define CP_COMMIT() asm volatile("cp.async.commit_group;" ::: "memory")
#define CP_WAIT1()  asm volatile("cp.async.wait_group 1;" ::: "memory")
#define CP_WAIT0()  asm volatile("cp.async.wait_group 0;" ::: "memory")

// ---------------- weight tf32 pre-convert ----------------
__global__ void cvt_kernel(const float* __restrict__ src, float* __restrict__ dst, int n)
{
    int i = blockIdx.x*256 + threadIdx.x;
    if (i < n) dst[i] = tf32r(src[i]);
}

// ---------------- tensor-core tf32 GEMM: C = A(MxK) @ W(NxK)^T ----------------
// A and W must already hold tf32-rounded values. 128x128 CTA tile, 8 warps 4x2,
// warp tile 32x64, K-chunks of 32, cp.async double buffer, smem stride 36.
// EPI 0: store. EPI 1: silu(acc+bias), tf32-round. EPI 2: gate combine.
// EPI 3: store tf32-rounded.
#define KT    32
#define AST   36
#define STGF  (128*AST)            // floats per (A or B) stage
#define GEMM_SMEM (4*STGF*4)       // 73728 bytes
template<int EPI>
__global__ void __launch_bounds__(256, 2) mgemm_kernel(
    const float* __restrict__ A,
    const float* __restrict__ W,
    const float* __restrict__ bias,
    float* __restrict__ C, int ldc,
    int N, int K,
    const float* __restrict__ p1, const float* __restrict__ p2)
{
    extern __shared__ float sm[];
    uint32_t smb = smem_u32(sm);
    int tid = threadIdx.x;
    int bm = blockIdx.y * 128, bn = blockIdx.x * 128;

    int lr = tid >> 1;              // load row 0..127
    int lc = (tid & 1) * 16;        // load col base 0/16
    const float* Arow = A + (size_t)(bm + lr)*K + lc;
    const float* Wrow = W + (size_t)(bn + lr)*K + lc;
    int wsz = ((bn + lr) < N) ? 16 : 0;

    int lane = tid & 31, w = tid >> 5;
    int wm = (w >> 1) * 32, wn = (w & 1) * 64;
    int gr = lane >> 2, tg = lane & 3;

    float acc[2][8][4];
    #pragma unroll
    for (int mi=0;mi<2;mi++)
        #pragma unroll
        for (int ni=0;ni<8;ni++)
            #pragma unroll
            for (int e=0;e<4;e++) acc[mi][ni][e]=0.f;

    int nch = K / KT;
    uint32_t adst = smb + (uint32_t)(lr*AST + lc)*4u;
    uint32_t bdst = adst + 2u*STGF*4u;

    // issue stage 0
    {
        #pragma unroll
        for (int u=0;u<4;u++){
            cp16(adst + u*16, Arow + 4*u, 16);
            cp16(bdst + u*16, Wrow + 4*u, wsz);
        }
        CP_COMMIT();
    }

    for (int c = 0; c < nch; c++) {
        int buf = c & 1;
        bool more = (c + 1) < nch;
        if (more) {
            int k0 = (c + 1) * KT;
            int nb = (c + 1) & 1;
            #pragma unroll
            for (int u=0;u<4;u++){
                cp16(adst + (uint32_t)nb*STGF*4u + u*16, Arow + k0 + 4*u, 16);
                cp16(bdst + (uint32_t)nb*STGF*4u + u*16, Wrow + k0 + 4*u, wsz);
            }
            CP_COMMIT();
            CP_WAIT1();
        } else {
            CP_WAIT0();
        }
        __syncthreads();

        const float* Ab = sm + buf*STGF;
        const float* Bb = sm + (2 + buf)*STGF;
        #pragma unroll
        for (int k8 = 0; k8 < 4; k8++) {
            int kb = k8 * 8;
            uint32_t afr[2][4];
            #pragma unroll
            for (int mi=0;mi<2;mi++){
                const float* ap = Ab + (wm + mi*16 + gr)*AST + kb + tg;
                afr[mi][0] = __float_as_uint(ap[0]);
                afr[mi][1] = __float_as_uint(ap[8*AST]);
                afr[mi][2] = __float_as_uint(ap[4]);
                afr[mi][3] = __float_as_uint(ap[8*AST+4]);
            }
            uint32_t bfr[8][2];
            #pragma unroll
            for (int ni=0;ni<8;ni++){
                const float* bp = Bb + (wn + ni*8 + gr)*AST + kb + tg;
                bfr[ni][0] = __float_as_uint(bp[0]);
                bfr[ni][1] = __float_as_uint(bp[4]);
            }
            #pragma unroll
            for (int mi=0;mi<2;mi++)
                #pragma unroll
                for (int ni=0;ni<8;ni++)
                    mma8(acc[mi][ni], afr[mi], bfr[ni]);
        }
        __syncthreads();
    }

    // ---- epilogue ----
    #pragma unroll
    for (int mi=0;mi<2;mi++){
        #pragma unroll
        for (int ni=0;ni<8;ni++){
            int col = bn + wn + ni*8 + 2*tg;
            #pragma unroll
            for (int half=0; half<2; half++){
                int m = bm + wm + mi*16 + gr + half*8;
                #pragma unroll
                for (int e=0; e<2; e++){
                    int n = col + e;
                    if (n >= N) continue;
                    float v = acc[mi][ni][half*2 + e];
                    if (EPI == 0) {
                        C[(size_t)m*ldc + n] = v;
                    } else if (EPI == 1) {
                        v += bias[n];
                        C[(size_t)m*ldc + n] = tf32r(v * sigf(v));
                    } else if (EPI == 2) {
                        float g  = sigf(v + bias[n]);
                        float ym = p1[(size_t)m*(2*DINNER) + n];
                        float yr = p1[(size_t)m*(2*DINNER) + DINNER + n];
                        float z  = p2[(size_t)m*DPROJ + n];
                        float sz = z * sigf(z);
                        C[(size_t)m*ldc + n] = (g*ym + (1.f-g)*yr) * sz;
                    } else {
                        C[(size_t)m*ldc + n] = tf32r(v);
                    }
                }
            }
        }
    }
}

// 16-step k-major micro-GEMM (fp32, for scan kernels)
__device__ __forceinline__ void mm16(const float* __restrict__ P,
                                     const float* __restrict__ Q,
                                     float acc[4][4], int ty, int tx)
{
    #pragma unroll
    for (int kk = 0; kk < 16; kk++) {
        float a[4], b[4];
        #pragma unroll
        for (int i=0;i<4;i++) a[i] = P[kk*64 + ty + 16*i];
        #pragma unroll
        for (int j=0;j<4;j++) b[j] = Q[kk*64 + tx + 16*j];
        #pragma unroll
        for (int i=0;i<4;i++)
            #pragma unroll
            for (int j=0;j<4;j++) acc[i][j] = fmaf(a[i], b[j], acc[i][j]);
    }
}

// ---------------- elementwise kernels ----------------
__global__ void umix_kernel(const float* __restrict__ u, const float* __restrict__ tm)
{
    int idx = blockIdx.x*256 + threadIdx.x;
    if (idx >= NTOK*DMODEL) return;
    int m = idx / DMODEL, ch = idx - m*DMODEL;
    int t = m & (SEQLEN-1);
    float tmx = tm[ch];
    float cur = u[idx];
    float prev = (t > 0) ? u[idx - DMODEL] : 0.f;
    g_umix[idx] = tf32r(cur*tmx + prev*(1.f - tmx));
}

__global__ void conv_kernel(const float* __restrict__ cw, const float* __restrict__ cb)
{
    int idx = blockIdx.x*256 + threadIdx.x;
    if (idx >= NTOK*CONVDIM) return;
    int m = idx / CONVDIM, ch = idx - m*CONVDIM;
    int t = m & (SEQLEN-1);
    float acc = cb[ch];
    #pragma unroll
    for (int k2 = 0; k2 < 4; k2++) {
        int tt = t - 3 + k2;
        if (tt >= 0)
            acc = fmaf(cw[ch*4+k2], g_proj[(size_t)(m-3+k2)*DPROJ + OFF_XBC + ch], acc);
    }
    g_xbc[(size_t)m*CONVDIM + ch] = acc * sigf(acc);   // SiLU
}

__global__ void dt_kernel(const float* __restrict__ dt_bias)
{
    int idx = blockIdx.x*256 + threadIdx.x;
    if (idx >= NTOK*NHEADS) return;
    int hh = idx % NHEADS;
    size_t m = idx / NHEADS;
    float x = g_proj[m*DPROJ + OFF_DT + hh] + dt_bias[hh];
    g_dt[idx] = (x > 20.f) ? x : log1pf(__expf(x));
}

// ---------------- SSD kernel 1: per (c,h,b): cum, Y_diag, chunk state ----------------
__global__ void __launch_bounds__(256) ssd_chunk_kernel(const float* __restrict__ A_log)
{
    int c = blockIdx.x, h = blockIdx.y, b = blockIdx.z;
    int tid = threadIdx.x, tx = tid & 15, ty = tid >> 4;
    int r = tid >> 2, q = tid & 3;
    int tok0 = b*SEQLEN + c*64;

    __shared__ float sP[16*64];
    __shared__ float sQ[16*64];
    __shared__ float sG[64*64];     // s-major: sG[s*64 + t]
    __shared__ float cum[64], sdt[64];

    if (tid < 64) sdt[tid] = g_dt[(size_t)(tok0+tid)*NHEADS + h];
    __syncthreads();
    if (tid == 0) {
        float Ah = -__expf(A_log[h]);
        float s = 0.f;
        for (int t = 0; t < 64; t++) { s += Ah*sdt[t]; cum[t] = s; }
    }
    __syncthreads();
    if (tid < 64) g_cumA[(size_t)(tok0+tid)*NHEADS + h] = cum[tid];
    if (tid == 0) g_alast[(size_t)(b*NCHUNK+c)*NHEADS + h] = cum[63];

    float acc[4][4];
    #pragma unroll
    for (int i=0;i<4;i++)
        #pragma unroll
        for (int j=0;j<4;j++) acc[i][j]=0.f;
    for (int n0 = 0; n0 < 64; n0 += 16) {
        float4 cv = *(const float4*)(g_xbc + (size_t)(tok0+r)*CONVDIM + OFF_C + n0 + q*4);
        float4 bv = *(const float4*)(g_xbc + (size_t)(tok0+r)*CONVDIM + OFF_B + n0 + q*4);
        sP[(q*4+0)*64+r]=cv.x; sP[(q*4+1)*64+r]=cv.y;
        sP[(q*4+2)*64+r]=cv.z; sP[(q*4+3)*64+r]=cv.w;
        sQ[(q*4+0)*64+r]=bv.x; sQ[(q*4+1)*64+r]=bv.y;
        sQ[(q*4+2)*64+r]=bv.z; sQ[(q*4+3)*64+r]=bv.w;
        __syncthreads();
        mm16(sP, sQ, acc, ty, tx);
        __syncthreads();
    }
    #pragma unroll
    for (int i=0;i<4;i++)
        #pragma unroll
        for (int j=0;j<4;j++){
            int t = ty+16*i, s = tx+16*j;
            sG[s*64 + t] = (s <= t) ? acc[i][j]*__expf(cum[t]-cum[s]) : 0.f;
        }
    __syncthreads();

    #pragma unroll
    for (int i=0;i<4;i++)
        #pragma unroll
        for (int j=0;j<4;j++) acc[i][j]=0.f;
    {
        int kk2 = tid >> 4, p4 = tid & 15;
        for (int s0 = 0; s0 < 64; s0 += 16) {
            float d = sdt[s0+kk2];
            float4 xv = *(const float4*)(g_xbc + (size_t)(tok0+s0+kk2)*CONVDIM + h*64 + p4*4);
            sQ[kk2*64 + p4*4+0]=xv.x*d; sQ[kk2*64 + p4*4+1]=xv.y*d;
            sQ[kk2*64 + p4*4+2]=xv.z*d; sQ[kk2*64 + p4*4+3]=xv.w*d;
            __syncthreads();
            mm16(&sG[s0*64], sQ, acc, ty, tx);
            __syncthreads();
        }
    }
    #pragma unroll
    for (int i=0;i<4;i++)
        #pragma unroll
        for (int j=0;j<4;j++)
            g_hcat[(size_t)(tok0+ty+16*i)*(2*DINNER) + h*64 + tx+16*j] = acc[i][j];

    #pragma unroll
    for (int i=0;i<4;i++)
        #pragma unroll
        for (int j=0;j<4;j++) acc[i][j]=0.f;
    {
        int kk2 = tid >> 4, p4 = tid & 15;
        float alastv = cum[63];
        for (int t0 = 0; t0 < 64; t0 += 16) {
            float f = sdt[t0+kk2] * __expf(alastv - cum[t0+kk2]);
            float4 xv = *(const float4*)(g_xbc + (size_t)(tok0+t0+kk2)*CONVDIM + h*64 + p4*4);
            float4 bv = *(const float4*)(g_xbc + (size_t)(tok0+t0+kk2)*CONVDIM + OFF_B + p4*4);
            sP[kk2*64 + p4*4+0]=xv.x*f; sP[kk2*64 + p4*4+1]=xv.y*f;
            sP[kk2*64 + p4*4+2]=xv.z*f; sP[kk2*64 + p4*4+3]=xv.w*f;
            sQ[kk2*64 + p4*4+0]=bv.x;   sQ[kk2*64 + p4*4+1]=bv.y;
            sQ[kk2*64 + p4*4+2]=bv.z;   sQ[kk2*64 + p4*4+3]=bv.w;
            __syncthreads();
            mm16(sP, sQ, acc, ty, tx);
            __syncthreads();
        }
    }
    {
        float* sb = g_states + ((size_t)(b*NCHUNK+c)*NHEADS + h)*4096;
        #pragma unroll
        for (int i=0;i<4;i++)
            #pragma unroll
            for (int j=0;j<4;j++)
                sb[(ty+16*i)*64 + tx+16*j] = acc[i][j];
    }
}

// ---------------- SSD kernel 2: cross-chunk state scan ----------------
__global__ void __launch_bounds__(256) ssd_scan_kernel()
{
    int h = blockIdx.x, b = blockIdx.y;
    int tid = threadIdx.x;
    float S[16];
    #pragma unroll
    for (int u=0;u<16;u++) S[u]=0.f;
    size_t eoff = (size_t)tid*16;
    for (int c = 0; c < NCHUNK; c++) {
        float e = __expf(g_alast[(size_t)(b*NCHUNK+c)*NHEADS + h]);
        float* ptr = g_states + ((size_t)(b*NCHUNK+c)*NHEADS + h)*4096 + eoff;
        #pragma unroll
        for (int u=0;u<16;u+=4){
            float4 o = *(float4*)(ptr+u);
            *(float4*)(ptr+u) = make_float4(S[u],S[u+1],S[u+2],S[u+3]);
            S[u+0]=S[u+0]*e+o.x; S[u+1]=S[u+1]*e+o.y;
            S[u+2]=S[u+2]*e+o.z; S[u+3]=S[u+3]*e+o.w;
        }
    }
}

// ---------------- SSD kernel 3: Y += exp(cum)*(C @ S_in^T) + x*D_skip ----------------
__global__ void __launch_bounds__(256) ssd_off_kernel(const float* __restrict__ D_skip)
{
    int c = blockIdx.x, h = blockIdx.y, b = blockIdx.z;
    int tid = threadIdx.x, tx = tid & 15, ty = tid >> 4;
    int r = tid >> 2, q = tid & 3;
    int tok0 = b*SEQLEN + c*64;

    __shared__ float sS[64*64];     // n-major: sS[n*64 + p]
    __shared__ float sC[16*64];
    __shared__ float cum[64];

    {
        const float* sb = g_states + ((size_t)(b*NCHUNK+c)*NHEADS + h)*4096;
        #pragma unroll
        for (int u=0;u<4;u++){
            float4 v = *(const float4*)(sb + r*64 + q*16 + u*4);
            sS[(q*16+u*4+0)*64 + r]=v.x; sS[(q*16+u*4+1)*64 + r]=v.y;
            sS[(q*16+u*4+2)*64 + r]=v.z; sS[(q*16+u*4+3)*64 + r]=v.w;
        }
    }
    if (tid < 64) cum[tid] = g_cumA[(size_t)(tok0+tid)*NHEADS + h];
    __syncthreads();

    float acc[4][4];
    #pragma unroll
    for (int i=0;i<4;i++)
        #pragma unroll
        for (int j=0;j<4;j++) acc[i][j]=0.f;
    for (int n0 = 0; n0 < 64; n0 += 16) {
        float4 cv = *(const float4*)(g_xbc + (size_t)(tok0+r)*CONVDIM + OFF_C + n0 + q*4);
        sC[(q*4+0)*64+r]=cv.x; sC[(q*4+1)*64+r]=cv.y;
        sC[(q*4+2)*64+r]=cv.z; sC[(q*4+3)*64+r]=cv.w;
        __syncthreads();
        mm16(sC, &sS[n0*64], acc, ty, tx);
        __syncthreads();
    }
    float dsk = D_skip[h];
    #pragma unroll
    for (int i=0;i<4;i++){
        int t = ty+16*i;
        float e = __expf(cum[t]);
        #pragma unroll
        for (int j=0;j<4;j++){
            int p = tx+16*j;
            float xv = g_xbc[(size_t)(tok0+t)*CONVDIM + h*64 + p];
            size_t o = (size_t)(tok0+t)*(2*DINNER) + h*64 + p;
            g_hcat[o] = tf32r(g_hcat[o] + e*acc[i][j] + xv*dsk);
        }
    }
}

// ---------------- RWKV kernels ----------------
__global__ void rwkv_pre_kernel()
{
    int bc = blockIdx.x;
    int i = threadIdx.x;
    int tok0 = (bc/NCHUNK)*SEQLEN + (bc%NCHUNK)*64;
    float cumv = 0.f;
    for (int t = 0; t < 64; t++) {
        float rw = g_proj[(size_t)(tok0+t)*DPROJ + OFF_W + i];
        cumv += -__expf(rw);
        g_wcum[(size_t)(tok0+t)*64 + i] = cumv;
    }
}

__global__ void __launch_bounds__(256) rwkv_gram_kernel()
{
    int bc = blockIdx.x;
    int b = bc/NCHUNK, c = bc%NCHUNK;
    int tok0 = b*SEQLEN + c*64;
    int tid = threadIdx.x, tx = tid & 15, ty = tid >> 4;
    int r = tid >> 2, q = tid & 3;

    __shared__ float sA1[64*64];
    __shared__ float sA2[64*64];
    __shared__ float sM [64*64];

    #pragma unroll
    for (int u=0;u<4;u++){
        float4 kv = *(const float4*)(g_proj + (size_t)(tok0+r)*DPROJ + OFF_K + q*16 + u*4);
        float4 vv = *(const float4*)(g_proj + (size_t)(tok0+r)*DPROJ + OFF_V + q*16 + u*4);
        sA1[(q*16+u*4+0)*64 + r]=kv.x; sA1[(q*16+u*4+1)*64 + r]=kv.y;
        sA1[(q*16+u*4+2)*64 + r]=kv.z; sA1[(q*16+u*4+3)*64 + r]=kv.w;
        sA2[(q*16+u*4+0)*64 + r]=vv.x; sA2[(q*16+u*4+1)*64 + r]=vv.y;
        sA2[(q*16+u*4+2)*64 + r]=vv.z; sA2[(q*16+u*4+3)*64 + r]=vv.w;
    }
    __syncthreads();
    float acc[4][4];
    #pragma unroll
    for (int i=0;i<4;i++)
        #pragma unroll
        for (int j=0;j<4;j++) acc[i][j]=0.f;
    #pragma unroll
    for (int j0 = 0; j0 < 64; j0 += 16)
        mm16(&sA1[j0*64], &sA2[j0*64], acc, ty, tx);
    __syncthreads();
    #pragma unroll
    for (int i=0;i<4;i++)
        #pragma unroll
        for (int j=0;j<4;j++)
            sM[(ty+16*i)*64 + tx+16*j] = acc[i][j];
    __syncthreads();

    for (int idx = tid; idx < 4096; idx += 256) {
        int t = idx >> 6, i = idx & 63;
        sA1[idx] = g_wcum[(size_t)(tok0+t)*64 + i];
        sA2[idx] = g_proj[(size_t)(tok0+t)*DPROJ + OFF_K + i]
                 * g_proj[(size_t)(tok0+t)*DPROJ + OFF_BON + i];
    }
    __syncthreads();

    {
        int i = tid & 63, tg = tid >> 6;
        for (int tt = 0; tt < 16; tt++) {
            int t = tg*16 + tt;
            float ct = sA1[t*64 + i];
            float sum = 0.f;
            for (int s = 0; s <= t; s++)
                sum = fmaf(__expf(ct - sA1[s*64+i]) * sA2[s*64+i], sM[t*64+s], sum);
            float rr = sigf(g_proj[(size_t)(tok0+t)*DPROJ + OFF_R + i]);
            g_wkvy[(size_t)(tok0+t)*64 + i] = rr * sum;
        }
    }
}

__global__ void __launch_bounds__(256) rwkv_state_kernel()
{
    int bc = blockIdx.x;
    int b = bc/NCHUNK, c = bc%NCHUNK;
    int tok0 = b*SEQLEN + c*64;
    int tid = threadIdx.x, tx = tid & 15, ty = tid >> 4;

    __shared__ float sP[64*64];
    __shared__ float sV[64*64];

    for (int idx = tid; idx < 4096; idx += 256) {
        int s = idx >> 6, i = idx & 63;
        float cl = g_wcum[(size_t)(tok0+63)*64 + i];
        float cs = g_wcum[(size_t)(tok0+s)*64 + i];
        sP[idx] = __expf(cl - cs)
                * g_proj[(size_t)(tok0+s)*DPROJ + OFF_K + i]
                * g_proj[(size_t)(tok0+s)*DPROJ + OFF_BON + i];
        sV[idx] = g_proj[(size_t)(tok0+s)*DPROJ + OFF_V + i];
    }
    __syncthreads();
    if (tid < 64)
        g_wdecay[(size_t)bc*64 + tid] = __expf(g_wcum[(size_t)(tok0+63)*64 + tid]);

    float acc[4][4];
    #pragma unroll
    for (int i=0;i<4;i++)
        #pragma unroll
        for (int j=0;j<4;j++) acc[i][j]=0.f;
    #pragma unroll
    for (int s0 = 0; s0 < 64; s0 += 16)
        mm16(&sP[s0*64], &sV[s0*64], acc, ty, tx);

    float* T = g_wT + (size_t)bc*4096;
    #pragma unroll
    for (int i=0;i<4;i++)
        #pragma unroll
        for (int j=0;j<4;j++)
            T[(ty+16*i)*64 + tx+16*j] = acc[i][j];
}

__global__ void __launch_bounds__(256) rwkv_scan_kernel()
{
    int b = blockIdx.x;
    int tid = threadIdx.x;
    int i = tid >> 2, jb = (tid & 3)*16;
    float S[16];
    #pragma unroll
    for (int u=0;u<16;u++) S[u]=0.f;
    for (int c = 0; c < NCHUNK; c++) {
        int bc = b*NCHUNK + c;
        float e = g_wdecay[(size_t)bc*64 + i];
        float* ptr = g_wT + (size_t)bc*4096 + i*64 + jb;
        #pragma unroll
        for (int u=0;u<16;u+=4){
            float4 o = *(float4*)(ptr+u);
            *(float4*)(ptr+u) = make_float4(S[u],S[u+1],S[u+2],S[u+3]);
            S[u+0]=S[u+0]*e+o.x; S[u+1]=S[u+1]*e+o.y;
            S[u+2]=S[u+2]*e+o.z; S[u+3]=S[u+3]*e+o.w;
        }
    }
}

__global__ void __launch_bounds__(256) rwkv_inter_kernel()
{
    int bc = blockIdx.x;
    int b = bc/NCHUNK, c = bc%NCHUNK;
    int tok0 = b*SEQLEN + c*64;
    int tid = threadIdx.x, tx = tid & 15, ty = tid >> 4;
    int r = tid >> 2, q = tid & 3;

    __shared__ float sK[64*64];
    __shared__ float sS[64*64];

    #pragma unroll
    for (int u=0;u<4;u++){
        float4 kv = *(const float4*)(g_proj + (size_t)(tok0+r)*DPROJ + OFF_K + q*16 + u*4);
        sK[(q*16+u*4+0)*64 + r]=kv.x; sK[(q*16+u*4+1)*64 + r]=kv.y;
        sK[(q*16+u*4+2)*64 + r]=kv.z; sK[(q*16+u*4+3)*64 + r]=kv.w;
        float4 sv = *(const float4*)(g_wT + (size_t)bc*4096 + r*64 + q*16 + u*4);
        sS[(q*16+u*4+0)*64 + r]=sv.x; sS[(q*16+u*4+1)*64 + r]=sv.y;
        sS[(q*16+u*4+2)*64 + r]=sv.z; sS[(q*16+u*4+3)*64 + r]=sv.w;
    }
    __syncthreads();

    float acc[4][4];
    #pragma unroll
    for (int i=0;i<4;i++)
        #pragma unroll
        for (int j=0;j<4;j++) acc[i][j]=0.f;
    #pragma unroll
    for (int j0 = 0; j0 < 64; j0 += 16)
        mm16(&sK[j0*64], &sS[j0*64], acc, ty, tx);

    #pragma unroll
    for (int ii=0;ii<4;ii++){
        int t = ty+16*ii;
        #pragma unroll
        for (int jj=0;jj<4;jj++){
            int i = tx+16*jj;
            float rr = sigf(g_proj[(size_t)(tok0+t)*DPROJ + OFF_R + i]);
            float e  = __expf(g_wcum[(size_t)(tok0+t)*64 + i]);
            size_t o = (size_t)(tok0+t)*64 + i;
            g_wkvy[o] = tf32r(g_wkvy[o] + rr * e * acc[ii][jj]);
        }
    }
}

// ---------------- LayerNorm ----------------
__global__ void __launch_bounds__(256) ln_kernel(const float* __restrict__ g,
                                                 const float* __restrict__ bbias)
{
    int m = blockIdx.x;
    int tid = threadIdx.x;
    const float* row = g_ypre + (size_t)m*DINNER;
    float s = 0.f, s2 = 0.f;
    #pragma unroll
    for (int u = 0; u < 6; u++) {
        float v = row[tid + 256*u];
        s += v; s2 += v*v;
    }
    __shared__ float red[16];
    #pragma unroll
    for (int o = 16; o > 0; o >>= 1) {
        s  += __shfl_xor_sync(0xffffffff, s, o);
        s2 += __shfl_xor_sync(0xffffffff, s2, o);
    }
    if ((tid & 31) == 0) { red[tid>>5] = s; red[8 + (tid>>5)] = s2; }
    __syncthreads();
    if (tid < 8) { s = red[tid]; s2 = red[8+tid]; }
    else { s = 0.f; s2 = 0.f; }
    if (tid < 32) {
        #pragma unroll
        for (int o = 4; o > 0; o >>= 1) {
            s  += __shfl_xor_sync(0xffffffff, s, o);
            s2 += __shfl_xor_sync(0xffffffff, s2, o);
        }
    }
    if (tid == 0) { red[0] = s; red[1] = s2; }
    __syncthreads();
    float mu = red[0] * (1.f/DINNER);
    float var = red[1] * (1.f/DINNER) - mu*mu;
    float inv = rsqrtf(var + 1e-5f);
    #pragma unroll
    for (int u = 0; u < 6; u++) {
        int ch = tid + 256*u;
        float v = (row[ch] - mu) * inv;
        g_ynorm[(size_t)m*DINNER + ch] = tf32r(v * g[ch] + bbias[ch]);
    }
}

// ---------------- launch ----------------
extern "C" void kernel_launch(void* const* d_in, const int* in_sizes, int n_in,
                              void* d_out, int out_size)
{
    const float* u         = (const float*)d_in[0];
    const float* in_proj_w = (const float*)d_in[1];
    const float* conv_w    = (const float*)d_in[2];
    const float* conv_b    = (const float*)d_in[3];
    const float* dt_bias   = (const float*)d_in[4];
    const float* A_log     = (const float*)d_in[5];
    const float* D_skip    = (const float*)d_in[6];
    const float* time_mix  = (const float*)d_in[7];
    const float* wkv_up_w  = (const float*)d_in[8];
    const float* fg_w1     = (const float*)d_in[9];
    const float* fg_b1     = (const float*)d_in[10];
    const float* fg_w2     = (const float*)d_in[11];
    const float* fg_b2     = (const float*)d_in[12];
    const float* ln_g      = (const float*)d_in[13];
    const float* ln_b      = (const float*)d_in[14];
    const float* out_proj_w= (const float*)d_in[15];
    float* out = (float*)d_out;

    float* p_umix;  cudaGetSymbolAddress((void**)&p_umix,  g_umix);
    float* p_proj;  cudaGetSymbolAddress((void**)&p_proj,  g_proj);
    float* p_hcat;  cudaGetSymbolAddress((void**)&p_hcat,  g_hcat);
    float* p_h;     cudaGetSymbolAddress((void**)&p_h,     g_h);
    float* p_ypre;  cudaGetSymbolAddress((void**)&p_ypre,  g_ypre);
    float* p_ynorm; cudaGetSymbolAddress((void**)&p_ynorm, g_ynorm);
    float* p_wkvy;  cudaGetSymbolAddress((void**)&p_wkvy,  g_wkvy);
    float* p_wi;    cudaGetSymbolAddress((void**)&p_wi,    g_wi);
    float* p_w1;    cudaGetSymbolAddress((void**)&p_w1,    g_w1);
    float* p_w2;    cudaGetSymbolAddress((void**)&p_w2,    g_w2);
    float* p_wo;    cudaGetSymbolAddress((void**)&p_wo,    g_wo);
    float* p_wu;    cudaGetSymbolAddress((void**)&p_wu,    g_wu);

    cudaFuncSetAttribute(mgemm_kernel<0>, cudaFuncAttributeMaxDynamicSharedMemorySize, GEMM_SMEM);
    cudaFuncSetAttribute(mgemm_kernel<1>, cudaFuncAttributeMaxDynamicSharedMemorySize, GEMM_SMEM);
    cudaFuncSetAttribute(mgemm_kernel<2>, cudaFuncAttributeMaxDynamicSharedMemorySize, GEMM_SMEM);
    cudaFuncSetAttribute(mgemm_kernel<3>, cudaFuncAttributeMaxDynamicSharedMemorySize, GEMM_SMEM);

    // 0. weight tf32 pre-convert (once per launch, not per CTA-tile)
    cvt_kernel<<<(DPROJ*DMODEL+255)/256, 256>>>(in_proj_w, p_wi, DPROJ*DMODEL);
    cvt_kernel<<<(DINNER*2*DINNER+255)/256, 256>>>(fg_w1, p_w1, DINNER*2*DINNER);
    cvt_kernel<<<(DINNER*DINNER+255)/256, 256>>>(fg_w2, p_w2, DINNER*DINNER);
    cvt_kernel<<<(DMODEL*DINNER+255)/256, 256>>>(out_proj_w, p_wo, DMODEL*DINNER);
    cvt_kernel<<<(DINNER*64+255)/256, 256>>>(wkv_up_w, p_wu, DINNER*64);

    // 1. time-mix (tf32-rounded output)
    umix_kernel<<<(NTOK*DMODEL)/256, 256>>>(u, time_mix);
    // 2. in_proj GEMM (exact output)
    mgemm_kernel<0><<<dim3((DPROJ+127)/128, NTOK/128), 256, GEMM_SMEM>>>(
        p_umix, p_wi, nullptr, p_proj, DPROJ, DPROJ, DMODEL, nullptr, nullptr);
    // 3. dt softplus
    dt_kernel<<<(NTOK*NHEADS)/256, 256>>>(dt_bias);
    // 4. causal conv + silu
    conv_kernel<<<(NTOK*CONVDIM)/256, 256>>>(conv_w, conv_b);
    // 5-7. SSD
    ssd_chunk_kernel<<<dim3(NCHUNK, NHEADS, BATCH), 256>>>(A_log);
    ssd_scan_kernel<<<dim3(NHEADS, BATCH), 256>>>();
    ssd_off_kernel<<<dim3(NCHUNK, NHEADS, BATCH), 256>>>(D_skip);
    // 8-12. RWKV
    rwkv_pre_kernel<<<BATCH*NCHUNK, 64>>>();
    rwkv_gram_kernel<<<BATCH*NCHUNK, 256>>>();
    rwkv_state_kernel<<<BATCH*NCHUNK, 256>>>();
    rwkv_scan_kernel<<<BATCH, 256>>>();
    rwkv_inter_kernel<<<BATCH*NCHUNK, 256>>>();
    // 13. wkv_up GEMM -> right half of hcat (tf32-rounded)
    mgemm_kernel<3><<<dim3(DINNER/128, NTOK/128), 256, GEMM_SMEM>>>(
        p_wkvy, p_wu, nullptr, p_hcat + DINNER, 2*DINNER, DINNER, 64, nullptr, nullptr);
    // 14. fg1: h = silu(hcat @ fg_w1^T + b1) (tf32-rounded)
    mgemm_kernel<1><<<dim3(DINNER/128, NTOK/128), 256, GEMM_SMEM>>>(
        p_hcat, p_w1, fg_b1, p_h, DINNER, DINNER, 2*DINNER, nullptr, nullptr);
    // 15. fg2 + gate combine + silu(z)
    mgemm_kernel<2><<<dim3(DINNER/128, NTOK/128), 256, GEMM_SMEM>>>(
        p_h, p_w2, fg_b2, p_ypre, DINNER, DINNER, DINNER, p_hcat, p_proj);
    // 16. LayerNorm (tf32-rounded output)
    ln_kernel<<<NTOK, 256>>>(ln_g, ln_b);
    // 17. out_proj GEMM -> d_out (exact output)
    mgemm_kernel<0><<<dim3(DMODEL/128, NTOK/128), 256, GEMM_SMEM>>>(
        p_ynorm, p_wo, nullptr, out, DMODEL, DMODEL, DINNER, nullptr, nullptr);
}

// round 14
// speedup vs baseline: 2.9749x; 1.0452x over previous
#include <cuda_runtime.h>
#include <math.h>
#include <stdint.h>

// ---------------- problem constants ----------------
#define BATCH   2
#define SEQLEN  4096
#define DMODEL  768
#define DINNER  1536
#define NHEADS  24
#define CONVDIM 1664
#define DPROJ   3544
#define NTOK    (BATCH*SEQLEN)      // 8192
#define NCHUNK  (SEQLEN/64)         // 64

// column offsets inside one proj row (width DPROJ)
#define OFF_XBC 1536
#define OFF_B   1536                // within g_xbc row (width CONVDIM)
#define OFF_C   1600                // within g_xbc row
#define OFF_DT  3200
#define OFF_R   3224
#define OFF_K   3288
#define OFF_V   3352
#define OFF_W   3416
#define OFF_BON 3480

// ---------------- scratch: static device globals (no allocs) ----------------
__device__ float g_umix [(size_t)NTOK*DMODEL];
__device__ float g_proj [(size_t)NTOK*DPROJ];
__device__ float g_xbc  [(size_t)NTOK*CONVDIM];
__device__ float g_dt   [(size_t)NTOK*NHEADS];
__device__ float g_cumA [(size_t)NTOK*NHEADS];
__device__ float g_alast[(size_t)BATCH*NCHUNK*NHEADS];
__device__ float g_states[(size_t)BATCH*NCHUNK*NHEADS*4096];
__device__ float g_hcat [(size_t)NTOK*2*DINNER];   // [y_mamba | y_rwkv]
__device__ float g_h    [(size_t)NTOK*DINNER];
__device__ float g_ypre [(size_t)NTOK*DINNER];
__device__ float g_ynorm[(size_t)NTOK*DINNER];
__device__ float g_wcum [(size_t)NTOK*64];
__device__ float g_wT   [(size_t)BATCH*NCHUNK*4096];
__device__ float g_wdecay[(size_t)BATCH*NCHUNK*64];
__device__ float g_wkvy [(size_t)NTOK*64];

// tf32-preconverted weights
__device__ float g_wi [(size_t)DPROJ*DMODEL];
__device__ float g_w1 [(size_t)DINNER*2*DINNER];
__device__ float g_w2 [(size_t)DINNER*DINNER];
__device__ float g_wo [(size_t)DMODEL*DINNER];
__device__ float g_wu [(size_t)DINNER*64];

__device__ __forceinline__ float sigf(float x){ return 1.f/(1.f+__expf(-x)); }

// round fp32 -> tf32 bit pattern (kept in a float register)
__device__ __forceinline__ float tf32r(float x){
    uint32_t u; asm("cvt.rna.tf32.f32 %0, %1;" : "=r"(u) : "f"(x));
    return __uint_as_float(u);
}

__device__ __forceinline__ uint32_t smem_u32(const void* p){
    uint32_t a;
    asm("{ .reg .u64 t; cvta.to.shared.u64 t, %1; cvt.u32.u64 %0, t; }" : "=r"(a) : "l"(p));
    return a;
}

// m16n8k8 tf32 MMA (baseline PTX, sm_80+)
__device__ __forceinline__ void mma8(float d[4], const uint32_t a[4], const uint32_t b[2]){
    asm volatile(
        "mma.sync.aligned.m16n8k8.row.col.f32.tf32.tf32.f32 "
        "{%0,%1,%2,%3}, {%4,%5,%6,%7}, {%8,%9}, {%0,%1,%2,%3};"
        : "+f"(d[0]), "+f"(d[1]), "+f"(d[2]), "+f"(d[3])
        : "r"(a[0]), "r"(a[1]), "r"(a[2]), "r"(a[3]), "r"(b[0]), "r"(b[1]));
}

__device__ __forceinline__ void ldsm4(uint32_t &r0, uint32_t &r1, uint32_t &r2, uint32_t &r3,
                                      uint32_t addr){
    asm volatile("ldmatrix.sync.aligned.m8n8.x4.shared.b16 {%0,%1,%2,%3}, [%4];"
        : "=r"(r0), "=r"(r1), "=r"(r2), "=r"(r3) : "r"(addr));
}

__device__ __forceinline__ void cp16(uint32_t dst, const void* src, int szbytes){
    asm volatile("cp.async.cg.shared.global [%0], [%1], 16, %2;"
                 :: "r"(dst), "l"(src), "r"(szbytes) : "memory");
}
#define CP_COMMIT() asm volatile("cp.async.commit_group;" ::: "memory")
#define CP_WAIT1()  asm volatile("cp.async.wait_group 1;" ::: "memory")
#define CP_WAIT0()  asm volatile("cp.async.wait_group 0;" ::: "memory")

// ---------------- weight tf32 pre-convert ----------------
__global__ void cvt_kernel(const float* __restrict__ src, float* __restrict__ dst, int n)
{
    int i = blockIdx.x*256 + threadIdx.x;
    if (i < n) dst[i] = tf32r(src[i]);
}

// ---------------- tensor-core tf32 GEMM: C = A(MxK) @ W(NxK)^T ----------------
// A and W must already hold tf32-rounded values. 128x128 CTA tile, 8 warps 4x2,
// warp tile 32x64, K-chunks of 32, 3-stage cp.async ring (one sync per chunk),
// ldmatrix fragment loads, smem stride 36.
// EPI 0: store. EPI 1: silu(acc+bias), tf32-round. EPI 2: gate combine.
// EPI 3: store tf32-rounded.
#define KT    32
#define AST   36
#define STGF  (128*AST)            // floats per (A or B) half-stage
#define STGB  (2*STGF*4)           // bytes per full stage (A+B) = 36864
#define GEMM_SMEM (3*STGB)         // 110592 bytes
template<int EPI>
__global__ void __launch_bounds__(256, 2) mgemm_kernel(
    const float* __restrict__ A,
    const float* __restrict__ W,
    const float* __restrict__ bias,
    float* __restrict__ C, int ldc,
    int N, int K,
    const float* __restrict__ p1, const float* __restrict__ p2)
{
    extern __shared__ float sm[];
    uint32_t smb = smem_u32(sm);
    int tid = threadIdx.x;
    int bm = blockIdx.y * 128, bn = blockIdx.x * 128;

    int lr = tid >> 1;              // load row 0..127
    int lc = (tid & 1) * 16;        // load col base 0/16
    const float* Arow = A + (size_t)(bm + lr)*K + lc;
    const float* Wrow = W + (size_t)(bn + lr)*K + lc;
    int wsz = ((bn + lr) < N) ? 16 : 0;
    uint32_t adst = smb + (uint32_t)(lr*AST + lc)*4u;
    uint32_t bdst = adst + (uint32_t)STGF*4u;

    int lane = tid & 31, w = tid >> 5;
    int wm = (w >> 1) * 32, wn = (w & 1) * 64;
    int gr = lane >> 2, tg = lane & 3;

    // ldmatrix per-lane base addresses
    int t4 = lane >> 3, rl = lane & 7;
    uint32_t aoff[2], boff[4];
    #pragma unroll
    for (int mi=0; mi<2; mi++){
        int row = wm + mi*16 + rl + (t4 & 1)*8;
        int ko  = (t4 >> 1) * 4;
        aoff[mi] = smb + (uint32_t)(row*AST + ko)*4u;
    }
    #pragma unroll
    for (int nb=0; nb<4; nb++){
        int row = wn + nb*16 + rl + (t4 >> 1)*8;
        int ko  = (t4 & 1) * 4;
        boff[nb] = smb + (uint32_t)STGF*4u + (uint32_t)(row*AST + ko)*4u;
    }

    float acc[2][8][4];
    #pragma unroll
    for (int mi=0;mi<2;mi++)
        #pragma unroll
        for (int ni=0;ni<8;ni++)
            #pragma unroll
            for (int e=0;e<4;e++) acc[mi][ni][e]=0.f;

    int nch = K / KT;

    // prologue: stages 0 and 1
    {
        #pragma unroll
        for (int u=0;u<4;u++){
            cp16(adst + u*16, Arow + 4*u, 16);
            cp16(bdst + u*16, Wrow + 4*u, wsz);
        }
        CP_COMMIT();
        if (nch > 1) {
            #pragma unroll
            for (int u=0;u<4;u++){
                cp16(adst + STGB + u*16, Arow + KT + 4*u, 16);
                cp16(bdst + STGB + u*16, Wrow + KT + 4*u, wsz);
            }
            CP_COMMIT();
        }
    }

    int stage = 0;
    for (int c = 0; c < nch; c++) {
        if (c + 1 < nch) CP_WAIT1(); else CP_WAIT0();
        __syncthreads();

        if (c + 2 < nch) {
            int ns = stage + 2; if (ns >= 3) ns -= 3;
            uint32_t so = (uint32_t)ns * STGB;
            int k0 = (c + 2) * KT;
            #pragma unroll
            for (int u=0;u<4;u++){
                cp16(adst + so + u*16, Arow + k0 + 4*u, 16);
                cp16(bdst + so + u*16, Wrow + k0 + 4*u, wsz);
            }
            CP_COMMIT();
        }

        uint32_t so = (uint32_t)stage * STGB;
        #pragma unroll
        for (int k8 = 0; k8 < 4; k8++) {
            uint32_t kb = (uint32_t)(k8 * 8) * 4u;
            uint32_t afr[2][4];
            #pragma unroll
            for (int mi=0;mi<2;mi++)
                ldsm4(afr[mi][0], afr[mi][1], afr[mi][2], afr[mi][3], aoff[mi] + so + kb);
            uint32_t bfr[8][2];
            #pragma unroll
            for (int nb=0;nb<4;nb++)
                ldsm4(bfr[2*nb][0], bfr[2*nb][1], bfr[2*nb+1][0], bfr[2*nb+1][1],
                      boff[nb] + so + kb);
            #pragma unroll
            for (int mi=0;mi<2;mi++)
                #pragma unroll
                for (int ni=0;ni<8;ni++)
                    mma8(acc[mi][ni], afr[mi], bfr[ni]);
        }
        stage++; if (stage >= 3) stage -= 3;
    }

    // ---- epilogue ----
    #pragma unroll
    for (int mi=0;mi<2;mi++){
        #pragma unroll
        for (int ni=0;ni<8;ni++){
            int col = bn + wn + ni*8 + 2*tg;
            #pragma unroll
            for (int half=0; half<2; half++){
                int m = bm + wm + mi*16 + gr + half*8;
                #pragma unroll
                for (int e=0; e<2; e++){
                    int n = col + e;
                    if (n >= N) continue;
                    float v = acc[mi][ni][half*2 + e];
                    if (EPI == 0) {
                        C[(size_t)m*ldc + n] = v;
                    } else if (EPI == 1) {
                        v += bias[n];
                        C[(size_t)m*ldc + n] = tf32r(v * sigf(v));
                    } else if (EPI == 2) {
                        float g  = sigf(v + bias[n]);
                        float ym = p1[(size_t)m*(2*DINNER) + n];
                        float yr = p1[(size_t)m*(2*DINNER) + DINNER + n];
                        float z  = p2[(size_t)m*DPROJ + n];
                        float sz = z * sigf(z);
                        C[(size_t)m*ldc + n] = (g*ym + (1.f-g)*yr) * sz;
                    } else {
                        C[(size_t)m*ldc + n] = tf32r(v);
                    }
                }
            }
        }
    }
}

// 16-step k-major micro-GEMM (fp32, for scan kernels)
__device__ __forceinline__ void mm16(const float* __restrict__ P,
                                     const float* __restrict__ Q,
                                     float acc[4][4], int ty, int tx)
{
    #pragma unroll
    for (int kk = 0; kk < 16; kk++) {
        float a[4], b[4];
        #pragma unroll
        for (int i=0;i<4;i++) a[i] = P[kk*64 + ty + 16*i];
        #pragma unroll
        for (int j=0;j<4;j++) b[j] = Q[kk*64 + tx + 16*j];
        #pragma unroll
        for (int i=0;i<4;i++)
            #pragma unroll
            for (int j=0;j<4;j++) acc[i][j] = fmaf(a[i], b[j], acc[i][j]);
    }
}

// ---------------- elementwise kernels ----------------
__global__ void umix_kernel(const float* __restrict__ u, const float* __restrict__ tm)
{
    int idx = blockIdx.x*256 + threadIdx.x;
    if (idx >= NTOK*DMODEL) return;
    int m = idx / DMODEL, ch = idx - m*DMODEL;
    int t = m & (SEQLEN-1);
    float tmx = tm[ch];
    float cur = u[idx];
    float prev = (t > 0) ? u[idx - DMODEL] : 0.f;
    g_umix[idx] = tf32r(cur*tmx + prev*(1.f - tmx));
}

__global__ void conv_kernel(const float* __restrict__ cw, const float* __restrict__ cb)
{
    int idx = blockIdx.x*256 + threadIdx.x;
    if (idx >= NTOK*CONVDIM) return;
    int m = idx / CONVDIM, ch = idx - m*CONVDIM;
    int t = m & (SEQLEN-1);
    float acc = cb[ch];
    #pragma unroll
    for (int k2 = 0; k2 < 4; k2++) {
        int tt = t - 3 + k2;
        if (tt >= 0)
            acc = fmaf(cw[ch*4+k2], g_proj[(size_t)(m-3+k2)*DPROJ + OFF_XBC + ch], acc);
    }
    g_xbc[(size_t)m*CONVDIM + ch] = acc * sigf(acc);   // SiLU
}

__global__ void dt_kernel(const float* __restrict__ dt_bias)
{
    int idx = blockIdx.x*256 + threadIdx.x;
    if (idx >= NTOK*NHEADS) return;
    int hh = idx % NHEADS;
    size_t m = idx / NHEADS;
    float x = g_proj[m*DPROJ + OFF_DT + hh] + dt_bias[hh];
    g_dt[idx] = (x > 20.f) ? x : log1pf(__expf(x));
}

// ---------------- SSD kernel 1: per (c,h,b): cum, Y_diag, chunk state ----------------
__global__ void __launch_bounds__(256) ssd_chunk_kernel(const float* __restrict__ A_log)
{
    int c = blockIdx.x, h = blockIdx.y, b = blockIdx.z;
    int tid = threadIdx.x, tx = tid & 15, ty = tid >> 4;
    int r = tid >> 2, q = tid & 3;
    int tok0 = b*SEQLEN + c*64;

    __shared__ float sP[16*64];
    __shared__ float sQ[16*64];
    __shared__ float sG[64*64];     // s-major: sG[s*64 + t]
    __shared__ float cum[64], sdt[64];

    if (tid < 64) sdt[tid] = g_dt[(size_t)(tok0+tid)*NHEADS + h];
    __syncthreads();
    if (tid == 0) {
        float Ah = -__expf(A_log[h]);
        float s = 0.f;
        for (int t = 0; t < 64; t++) { s += Ah*sdt[t]; cum[t] = s; }
    }
    __syncthreads();
    if (tid < 64) g_cumA[(size_t)(tok0+tid)*NHEADS + h] = cum[tid];
    if (tid == 0) g_alast[(size_t)(b*NCHUNK+c)*NHEADS + h] = cum[63];

    float acc[4][4];
    #pragma unroll
    for (int i=0;i<4;i++)
        #pragma unroll
        for (int j=0;j<4;j++) acc[i][j]=0.f;
    for (int n0 = 0; n0 < 64; n0 += 16) {
        float4 cv = *(const float4*)(g_xbc + (size_t)(tok0+r)*CONVDIM + OFF_C + n0 + q*4);
        float4 bv = *(const float4*)(g_xbc + (size_t)(tok0+r)*CONVDIM + OFF_B + n0 + q*4);
        sP[(q*4+0)*64+r]=cv.x; sP[(q*4+1)*64+r]=cv.y;
        sP[(q*4+2)*64+r]=cv.z; sP[(q*4+3)*64+r]=cv.w;
        sQ[(q*4+0)*64+r]=bv.x; sQ[(q*4+1)*64+r]=bv.y;
        sQ[(q*4+2)*64+r]=bv.z; sQ[(q*4+3)*64+r]=bv.w;
        __syncthreads();
        mm16(sP, sQ, acc, ty, tx);
        __syncthreads();
    }
    #pragma unroll
    for (int i=0;i<4;i++)
        #pragma unroll
        for (int j=0;j<4;j++){
            int t = ty+16*i, s = tx+16*j;
            sG[s*64 + t] = (s <= t) ? acc[i][j]*__expf(cum[t]-cum[s]) : 0.f;
        }
    __syncthreads();

    #pragma unroll
    for (int i=0;i<4;i++)
        #pragma unroll
        for (int j=0;j<4;j++) acc[i][j]=0.f;
    {
        int kk2 = tid >> 4, p4 = tid & 15;
        for (int s0 = 0; s0 < 64; s0 += 16) {
            float d = sdt[s0+kk2];
            float4 xv = *(const float4*)(g_xbc + (size_t)(tok0+s0+kk2)*CONVDIM + h*64 + p4*4);
            sQ[kk2*64 + p4*4+0]=xv.x*d; sQ[kk2*64 + p4*4+1]=xv.y*d;
            sQ[kk2*64 + p4*4+2]=xv.z*d; sQ[kk2*64 + p4*4+3]=xv.w*d;
            __syncthreads();
            mm16(&sG[s0*64], sQ, acc, ty, tx);
            __syncthreads();
        }
    }
    #pragma unroll
    for (int i=0;i<4;i++)
        #pragma unroll
        for (int j=0;j<4;j++)
            g_hcat[(size_t)(tok0+ty+16*i)*(2*DINNER) + h*64 + tx+16*j] = acc[i][j];

    #pragma unroll
    for (int i=0;i<4;i++)
        #pragma unroll
        for (int j=0;j<4;j++) acc[i][j]=0.f;
    {
        int kk2 = tid >> 4, p4 = tid & 15;
        float alastv = cum[63];
        for (int t0 = 0; t0 < 64; t0 += 16) {
            float f = sdt[t0+kk2] * __expf(alastv - cum[t0+kk2]);
            float4 xv = *(const float4*)(g_xbc + (size_t)(tok0+t0+kk2)*CONVDIM + h*64 + p4*4);
            float4 bv = *(const float4*)(g_xbc + (size_t)(tok0+t0+kk2)*CONVDIM + OFF_B + p4*4);
            sP[kk2*64 + p4*4+0]=xv.x*f; sP[kk2*64 + p4*4+1]=xv.y*f;
            sP[kk2*64 + p4*4+2]=xv.z*f; sP[kk2*64 + p4*4+3]=xv.w*f;
            sQ[kk2*64 + p4*4+0]=bv.x;   sQ[kk2*64 + p4*4+1]=bv.y;
            sQ[kk2*64 + p4*4+2]=bv.z;   sQ[kk2*64 + p4*4+3]=bv.w;
            __syncthreads();
            mm16(sP, sQ, acc, ty, tx);
            __syncthreads();
        }
    }
    {
        float* sb = g_states + ((size_t)(b*NCHUNK+c)*NHEADS + h)*4096;
        #pragma unroll
        for (int i=0;i<4;i++)
            #pragma unroll
            for (int j=0;j<4;j++)
                sb[(ty+16*i)*64 + tx+16*j] = acc[i][j];
    }
}

// ---------------- SSD kernel 2: cross-chunk state scan ----------------
__global__ void __launch_bounds__(256) ssd_scan_kernel()
{
    int h = blockIdx.x, b = blockIdx.y;
    int tid = threadIdx.x;
    float S[16];
    #pragma unroll
    for (int u=0;u<16;u++) S[u]=0.f;
    size_t eoff = (size_t)tid*16;
    for (int c = 0; c < NCHUNK; c++) {
        float e = __expf(g_alast[(size_t)(b*NCHUNK+c)*NHEADS + h]);
        float* ptr = g_states + ((size_t)(b*NCHUNK+c)*NHEADS + h)*4096 + eoff;
        #pragma unroll
        for (int u=0;u<16;u+=4){
            float4 o = *(float4*)(ptr+u);
            *(float4*)(ptr+u) = make_float4(S[u],S[u+1],S[u+2],S[u+3]);
            S[u+0]=S[u+0]*e+o.x; S[u+1]=S[u+1]*e+o.y;
            S[u+2]=S[u+2]*e+o.z; S[u+3]=S[u+3]*e+o.w;
        }
    }
}

// ---------------- SSD kernel 3: Y += exp(cum)*(C @ S_in^T) + x*D_skip ----------------
__global__ void __launch_bounds__(256) ssd_off_kernel(const float* __restrict__ D_skip)
{
    int c = blockIdx.x, h = blockIdx.y, b = blockIdx.z;
    int tid = threadIdx.x, tx = tid & 15, ty = tid >> 4;
    int r = tid >> 2, q = tid & 3;
    int tok0 = b*SEQLEN + c*64;

    __shared__ float sS[64*64];     // n-major: sS[n*64 + p]
    __shared__ float sC[16*64];
    __shared__ float cum[64];

    {
        const float* sb = g_states + ((size_t)(b*NCHUNK+c)*NHEADS + h)*4096;
        #pragma unroll
        for (int u=0;u<4;u++){
            float4 v = *(const float4*)(sb + r*64 + q*16 + u*4);
            sS[(q*16+u*4+0)*64 + r]=v.x; sS[(q*16+u*4+1)*64 + r]=v.y;
            sS[(q*16+u*4+2)*64 + r]=v.z; sS[(q*16+u*4+3)*64 + r]=v.w;
        }
    }
    if (tid < 64) cum[tid] = g_cumA[(size_t)(tok0+tid)*NHEADS + h];
    __syncthreads();

    float acc[4][4];
    #pragma unroll
    for (int i=0;i<4;i++)
        #pragma unroll
        for (int j=0;j<4;j++) acc[i][j]=0.f;
    for (int n0 = 0; n0 < 64; n0 += 16) {
        float4 cv = *(const float4*)(g_xbc + (size_t)(tok0+r)*CONVDIM + OFF_C + n0 + q*4);
        sC[(q*4+0)*64+r]=cv.x; sC[(q*4+1)*64+r]=cv.y;
        sC[(q*4+2)*64+r]=cv.z; sC[(q*4+3)*64+r]=cv.w;
        __syncthreads();
        mm16(sC, &sS[n0*64], acc, ty, tx);
        __syncthreads();
    }
    float dsk = D_skip[h];
    #pragma unroll
    for (int i=0;i<4;i++){
        int t = ty+16*i;
        float e = __expf(cum[t]);
        #pragma unroll
        for (int j=0;j<4;j++){
            int p = tx+16*j;
            float xv = g_xbc[(size_t)(tok0+t)*CONVDIM + h*64 + p];
            size_t o = (size_t)(tok0+t)*(2*DINNER) + h*64 + p;
            g_hcat[o] = tf32r(g_hcat[o] + e*acc[i][j] + xv*dsk);
        }
    }
}

// ---------------- RWKV kernels ----------------
__global__ void rwkv_pre_kernel()
{
    int bc = blockIdx.x;
    int i = threadIdx.x;
    int tok0 = (bc/NCHUNK)*SEQLEN + (bc%NCHUNK)*64;
    float cumv = 0.f;
    for (int t = 0; t < 64; t++) {
        float rw = g_proj[(size_t)(tok0+t)*DPROJ + OFF_W + i];
        cumv += -__expf(rw);
        g_wcum[(size_t)(tok0+t)*64 + i] = cumv;
    }
}

__global__ void __launch_bounds__(256) rwkv_gram_kernel()
{
    int bc = blockIdx.x;
    int b = bc/NCHUNK, c = bc%NCHUNK;
    int tok0 = b*SEQLEN + c*64;
    int tid = threadIdx.x, tx = tid & 15, ty = tid >> 4;
    int r = tid >> 2, q = tid & 3;

    __shared__ float sA1[64*64];
    __shared__ float sA2[64*64];
    __shared__ float sM [64*64];

    #pragma unroll
    for (int u=0;u<4;u++){
        float4 kv = *(const float4*)(g_proj + (size_t)(tok0+r)*DPROJ + OFF_K + q*16 + u*4);
        float4 vv = *(const float4*)(g_proj + (size_t)(tok0+r)*DPROJ + OFF_V + q*16 + u*4);
        sA1[(q*16+u*4+0)*64 + r]=kv.x; sA1[(q*16+u*4+1)*64 + r]=kv.y;
        sA1[(q*16+u*4+2)*64 + r]=kv.z; sA1[(q*16+u*4+3)*64 + r]=kv.w;
        sA2[(q*16+u*4+0)*64 + r]=vv.x; sA2[(q*16+u*4+1)*64 + r]=vv.y;
        sA2[(q*16+u*4+2)*64 + r]=vv.z; sA2[(q*16+u*4+3)*64 + r]=vv.w;
    }
    __syncthreads();
    float acc[4][4];
    #pragma unroll
    for (int i=0;i<4;i++)
        #pragma unroll
        for (int j=0;j<4;j++) acc[i][j]=0.f;
    #pragma unroll
    for (int j0 = 0; j0 < 64; j0 += 16)
        mm16(&sA1[j0*64], &sA2[j0*64], acc, ty, tx);
    __syncthreads();
    #pragma unroll
    for (int i=0;i<4;i++)
        #pragma unroll
        for (int j=0;j<4;j++)
            sM[(ty+16*i)*64 + tx+16*j] = acc[i][j];
    __syncthreads();

    for (int idx = tid; idx < 4096; idx += 256) {
        int t = idx >> 6, i = idx & 63;
        sA1[idx] = g_wcum[(size_t)(tok0+t)*64 + i];
        sA2[idx] = g_proj[(size_t)(tok0+t)*DPROJ + OFF_K + i]
                 * g_proj[(size_t)(tok0+t)*DPROJ + OFF_BON + i];
    }
    __syncthreads();

    {
        int i = tid & 63, tg = tid >> 6;
        for (int tt = 0; tt < 16; tt++) {
            int t = tg*16 + tt;
            float ct = sA1[t*64 + i];
            float sum = 0.f;
            for (int s = 0; s <= t; s++)
                sum = fmaf(__expf(ct - sA1[s*64+i]) * sA2[s*64+i], sM[t*64+s], sum);
            float rr = sigf(g_proj[(size_t)(tok0+t)*DPROJ + OFF_R + i]);
            g_wkvy[(size_t)(tok0+t)*64 + i] = rr * sum;
        }
    }
}

__global__ void __launch_bounds__(256) rwkv_state_kernel()
{
    int bc = blockIdx.x;
    int b = bc/NCHUNK, c = bc%NCHUNK;
    int tok0 = b*SEQLEN + c*64;
    int tid = threadIdx.x, tx = tid & 15, ty = tid >> 4;

    __shared__ float sP[64*64];
    __shared__ float sV[64*64];

    for (int idx = tid; idx < 4096; idx += 256) {
        int s = idx >> 6, i = idx & 63;
        float cl = g_wcum[(size_t)(tok0+63)*64 + i];
        float cs = g_wcum[(size_t)(tok0+s)*64 + i];
        sP[idx] = __expf(cl - cs)
                * g_proj[(size_t)(tok0+s)*DPROJ + OFF_K + i]
                * g_proj[(size_t)(tok0+s)*DPROJ + OFF_BON + i];
        sV[idx] = g_proj[(size_t)(tok0+s)*DPROJ + OFF_V + i];
    }
    __syncthreads();
    if (tid < 64)
        g_wdecay[(size_t)bc*64 + tid] = __expf(g_wcum[(size_t)(tok0+63)*64 + tid]);

    float acc[4][4];
    #pragma unroll
    for (int i=0;i<4;i++)
        #pragma unroll
        for (int j=0;j<4;j++) acc[i][j]=0.f;
    #pragma unroll
    for (int s0 = 0; s0 < 64; s0 += 16)
        mm16(&sP[s0*64], &sV[s0*64], acc, ty, tx);

    float* T = g_wT + (size_t)bc*4096;
    #pragma unroll
    for (int i=0;i<4;i++)
        #pragma unroll
        for (int j=0;j<4;j++)
            T[(ty+16*i)*64 + tx+16*j] = acc[i][j];
}

__global__ void __launch_bounds__(256) rwkv_scan_kernel()
{
    int b = blockIdx.x;
    int tid = threadIdx.x;
    int i = tid >> 2, jb = (tid & 3)*16;
    float S[16];
    #pragma unroll
    for (int u=0;u<16;u++) S[u]=0.f;
    for (int c = 0; c < NCHUNK; c++) {
        int bc = b*NCHUNK + c;
        float e = g_wdecay[(size_t)bc*64 + i];
        float* ptr = g_wT + (size_t)bc*4096 + i*64 + jb;
        #pragma unroll
        for (int u=0;u<16;u+=4){
            float4 o = *(float4*)(ptr+u);
            *(float4*)(ptr+u) = make_float4(S[u],S[u+1],S[u+2],S[u+3]);
            S[u+0]=S[u+0]*e+o.x; S[u+1]=S[u+1]*e+o.y;
            S[u+2]=S[u+2]*e+o.z; S[u+3]=S[u+3]*e+o.w;
        }
    }
}

__global__ void __launch_bounds__(256) rwkv_inter_kernel()
{
    int bc = blockIdx.x;
    int b = bc/NCHUNK, c = bc%NCHUNK;
    int tok0 = b*SEQLEN + c*64;
    int tid = threadIdx.x, tx = tid & 15, ty = tid >> 4;
    int r = tid >> 2, q = tid & 3;

    __shared__ float sK[64*64];
    __shared__ float sS[64*64];

    #pragma unroll
    for (int u=0;u<4;u++){
        float4 kv = *(const float4*)(g_proj + (size_t)(tok0+r)*DPROJ + OFF_K + q*16 + u*4);
        sK[(q*16+u*4+0)*64 + r]=kv.x; sK[(q*16+u*4+1)*64 + r]=kv.y;
        sK[(q*16+u*4+2)*64 + r]=kv.z; sK[(q*16+u*4+3)*64 + r]=kv.w;
        float4 sv = *(const float4*)(g_wT + (size_t)bc*4096 + r*64 + q*16 + u*4);
        sS[(q*16+u*4+0)*64 + r]=sv.x; sS[(q*16+u*4+1)*64 + r]=sv.y;
        sS[(q*16+u*4+2)*64 + r]=sv.z; sS[(q*16+u*4+3)*64 + r]=sv.w;
    }
    __syncthreads();

    float acc[4][4];
    #pragma unroll
    for (int i=0;i<4;i++)
        #pragma unroll
        for (int j=0;j<4;j++) acc[i][j]=0.f;
    #pragma unroll
    for (int j0 = 0; j0 < 64; j0 += 16)
        mm16(&sK[j0*64], &sS[j0*64], acc, ty, tx);

    #pragma unroll
    for (int ii=0;ii<4;ii++){
        int t = ty+16*ii;
        #pragma unroll
        for (int jj=0;jj<4;jj++){
            int i = tx+16*jj;
            float rr = sigf(g_proj[(size_t)(tok0+t)*DPROJ + OFF_R + i]);
            float e  = __expf(g_wcum[(size_t)(tok0+t)*64 + i]);
            size_t o = (size_t)(tok0+t)*64 + i;
            g_wkvy[o] = tf32r(g_wkvy[o] + rr * e * acc[ii][jj]);
        }
    }
}

// ---------------- LayerNorm ----------------
__global__ void __launch_bounds__(256) ln_kernel(const float* __restrict__ g,
                                                 const float* __restrict__ bbias)
{
    int m = blockIdx.x;
    int tid = threadIdx.x;
    const float* row = g_ypre + (size_t)m*DINNER;
    float s = 0.f, s2 = 0.f;
    #pragma unroll
    for (int u = 0; u < 6; u++) {
        float v = row[tid + 256*u];
        s += v; s2 += v*v;
    }
    __shared__ float red[16];
    #pragma unroll
    for (int o = 16; o > 0; o >>= 1) {
        s  += __shfl_xor_sync(0xffffffff, s, o);
        s2 += __shfl_xor_sync(0xffffffff, s2, o);
    }
    if ((tid & 31) == 0) { red[tid>>5] = s; red[8 + (tid>>5)] = s2; }
    __syncthreads();
    if (tid < 8) { s = red[tid]; s2 = red[8+tid]; }
    else { s = 0.f; s2 = 0.f; }
    if (tid < 32) {
        #pragma unroll
        for (int o = 4; o > 0; o >>= 1) {
            s  += __shfl_xor_sync(0xffffffff, s, o);
            s2 += __shfl_xor_sync(0xffffffff, s2, o);
        }
    }
    if (tid == 0) { red[0] = s; red[1] = s2; }
    __syncthreads();
    float mu = red[0] * (1.f/DINNER);
    float var = red[1] * (1.f/DINNER) - mu*mu;
    float inv = rsqrtf(var + 1e-5f);
    #pragma unroll
    for (int u = 0; u < 6; u++) {
        int ch = tid + 256*u;
        float v = (row[ch] - mu) * inv;
        g_ynorm[(size_t)m*DINNER + ch] = tf32r(v * g[ch] + bbias[ch]);
    }
}

// ---------------- launch ----------------
extern "C" void kernel_launch(void* const* d_in, const int* in_sizes, int n_in,
                              void* d_out, int out_size)
{
    const float* u         = (const float*)d_in[0];
    const float* in_proj_w = (const float*)d_in[1];
    const float* conv_w    = (const float*)d_in[2];
    const float* conv_b    = (const float*)d_in[3];
    const float* dt_bias   = (const float*)d_in[4];
    const float* A_log     = (const float*)d_in[5];
    const float* D_skip    = (const float*)d_in[6];
    const float* time_mix  = (const float*)d_in[7];
    const float* wkv_up_w  = (const float*)d_in[8];
    const float* fg_w1     = (const float*)d_in[9];
    const float* fg_b1     = (const float*)d_in[10];
    const float* fg_w2     = (const float*)d_in[11];
    const float* fg_b2     = (const float*)d_in[12];
    const float* ln_g      = (const float*)d_in[13];
    const float* ln_b      = (const float*)d_in[14];
    const float* out_proj_w= (const float*)d_in[15];
    float* out = (float*)d_out;

    float* p_umix;  cudaGetSymbolAddress((void**)&p_umix,  g_umix);
    float* p_proj;  cudaGetSymbolAddress((void**)&p_proj,  g_proj);
    float* p_hcat;  cudaGetSymbolAddress((void**)&p_hcat,  g_hcat);
    float* p_h;     cudaGetSymbolAddress((void**)&p_h,     g_h);
    float* p_ypre;  cudaGetSymbolAddress((void**)&p_ypre,  g_ypre);
    float* p_ynorm; cudaGetSymbolAddress((void**)&p_ynorm, g_ynorm);
    float* p_wkvy;  cudaGetSymbolAddress((void**)&p_wkvy,  g_wkvy);
    float* p_wi;    cudaGetSymbolAddress((void**)&p_wi,    g_wi);
    float* p_w1;    cudaGetSymbolAddress((void**)&p_w1,    g_w1);
    float* p_w2;    cudaGetSymbolAddress((void**)&p_w2,    g_w2);
    float* p_wo;    cudaGetSymbolAddress((void**)&p_wo,    g_wo);
    float* p_wu;    cudaGetSymbolAddress((void**)&p_wu,    g_wu);

    cudaFuncSetAttribute(mgemm_kernel<0>, cudaFuncAttributeMaxDynamicSharedMemorySize, GEMM_SMEM);
    cudaFuncSetAttribute(mgemm_kernel<1>, cudaFuncAttributeMaxDynamicSharedMemorySize, GEMM_SMEM);
    cudaFuncSetAttribute(mgemm_kernel<2>, cudaFuncAttributeMaxDynamicSharedMemorySize, GEMM_SMEM);
    cudaFuncSetAttribute(mgemm_kernel<3>, cudaFuncAttributeMaxDynamicSharedMemorySize, GEMM_SMEM);

    // 0. weight tf32 pre-convert (once per launch, not per CTA-tile)
    cvt_kernel<<<(DPROJ*DMODEL+255)/256, 256>>>(in_proj_w, p_wi, DPROJ*DMODEL);
    cvt_kernel<<<(DINNER*2*DINNER+255)/256, 256>>>(fg_w1, p_w1, DINNER*2*DINNER);
    cvt_kernel<<<(DINNER*DINNER+255)/256, 256>>>(fg_w2, p_w2, DINNER*DINNER);
    cvt_kernel<<<(DMODEL*DINNER+255)/256, 256>>>(out_proj_w, p_wo, DMODEL*DINNER);
    cvt_kernel<<<(DINNER*64+255)/256, 256>>>(wkv_up_w, p_wu, DINNER*64);

    // 1. time-mix (tf32-rounded output)
    umix_kernel<<<(NTOK*DMODEL)/256, 256>>>(u, time_mix);
    // 2. in_proj GEMM (exact output)
    mgemm_kernel<0><<<dim3((DPROJ+127)/128, NTOK/128), 256, GEMM_SMEM>>>(
        p_umix, p_wi, nullptr, p_proj, DPROJ, DPROJ, DMODEL, nullptr, nullptr);
    // 3. dt softplus
    dt_kernel<<<(NTOK*NHEADS)/256, 256>>>(dt_bias);
    // 4. causal conv + silu
    conv_kernel<<<(NTOK*CONVDIM)/256, 256>>>(conv_w, conv_b);
    // 5-7. SSD
    ssd_chunk_kernel<<<dim3(NCHUNK, NHEADS, BATCH), 256>>>(A_log);
    ssd_scan_kernel<<<dim3(NHEADS, BATCH), 256>>>();
    ssd_off_kernel<<<dim3(NCHUNK, NHEADS, BATCH), 256>>>(D_skip);
    // 8-12. RWKV
    rwkv_pre_kernel<<<BATCH*NCHUNK, 64>>>();
    rwkv_gram_kernel<<<BATCH*NCHUNK, 256>>>();
    rwkv_state_kernel<<<BATCH*NCHUNK, 256>>>();
    rwkv_scan_kernel<<<BATCH, 256>>>();
    rwkv_inter_kernel<<<BATCH*NCHUNK, 256>>>();
    // 13. wkv_up GEMM -> right half of hcat (tf32-rounded)
    mgemm_kernel<3><<<dim3(DINNER/128, NTOK/128), 256, GEMM_SMEM>>>(
        p_wkvy, p_wu, nullptr, p_hcat + DINNER, 2*DINNER, DINNER, 64, nullptr, nullptr);
    // 14. fg1: h = silu(hcat @ fg_w1^T + b1) (tf32-rounded)
    mgemm_kernel<1><<<dim3(DINNER/128, NTOK/128), 256, GEMM_SMEM>>>(
        p_hcat, p_w1, fg_b1, p_h, DINNER, DINNER, 2*DINNER, nullptr, nullptr);
    // 15. fg2 + gate combine + silu(z)
    mgemm_kernel<2><<<dim3(DINNER/128, NTOK/128), 256, GEMM_SMEM>>>(
        p_h, p_w2, fg_b2, p_ypre, DINNER, DINNER, DINNER, p_hcat, p_proj);
    // 16. LayerNorm (tf32-rounded output)
    ln_kernel<<<NTOK, 256>>>(ln_g, ln_b);
    // 17. out_proj GEMM -> d_out (exact output)
    mgemm_kernel<0><<<dim3(DMODEL/128, NTOK/128), 256, GEMM_SMEM>>>(
        p_ynorm, p_wo, nullptr, out, DMODEL, DMODEL, DINNER, nullptr, nullptr);
}

// round 16
// speedup vs baseline: 3.0741x; 1.0333x over previous
#include <cuda_runtime.h>
#include <math.h>
#include <stdint.h>

// ---------------- problem constants ----------------
#define BATCH   2
#define SEQLEN  4096
#define DMODEL  768
#define DINNER  1536
#define NHEADS  24
#define CONVDIM 1664
#define DPROJ   3544
#define NTOK    (BATCH*SEQLEN)      // 8192
#define NCHUNK  (SEQLEN/64)         // 64

// column offsets inside one proj row (width DPROJ)
#define OFF_XBC 1536
#define OFF_B   1536                // within g_xbc row (width CONVDIM)
#define OFF_C   1600                // within g_xbc row
#define OFF_DT  3200
#define OFF_R   3224
#define OFF_K   3288
#define OFF_V   3352
#define OFF_W   3416
#define OFF_BON 3480

// ---------------- scratch: static device globals (no allocs) ----------------
__device__ float g_umix [(size_t)NTOK*DMODEL];
__device__ float g_proj [(size_t)NTOK*DPROJ];
__device__ float g_xbc  [(size_t)NTOK*CONVDIM];
__device__ float g_dt   [(size_t)NTOK*NHEADS];
__device__ float g_cumA [(size_t)NTOK*NHEADS];
__device__ float g_alast[(size_t)BATCH*NCHUNK*NHEADS];
__device__ float g_states[(size_t)BATCH*NCHUNK*NHEADS*4096];
__device__ float g_hcat [(size_t)NTOK*2*DINNER];   // [y_mamba | y_rwkv]
__device__ float g_h    [(size_t)NTOK*DINNER];
__device__ float g_ypre [(size_t)NTOK*DINNER];
__device__ float g_ynorm[(size_t)NTOK*DINNER];
__device__ float g_wcum [(size_t)NTOK*64];
__device__ float g_wT   [(size_t)BATCH*NCHUNK*4096];
__device__ float g_wdecay[(size_t)BATCH*NCHUNK*64];
__device__ float g_wkvy [(size_t)NTOK*64];

// tf32-preconverted weights
__device__ float g_wi [(size_t)DPROJ*DMODEL];
__device__ float g_w1 [(size_t)DINNER*2*DINNER];
__device__ float g_w2 [(size_t)DINNER*DINNER];
__device__ float g_wo [(size_t)DMODEL*DINNER];
__device__ float g_wu [(size_t)DINNER*64];

__device__ __forceinline__ float sigf(float x){ return 1.f/(1.f+__expf(-x)); }

// round fp32 -> tf32 bit pattern (kept in a float register)
__device__ __forceinline__ float tf32r(float x){
    uint32_t u; asm("cvt.rna.tf32.f32 %0, %1;" : "=r"(u) : "f"(x));
    return __uint_as_float(u);
}

__device__ __forceinline__ uint32_t smem_u32(const void* p){
    uint32_t a;
    asm("{ .reg .u64 t; cvta.to.shared.u64 t, %1; cvt.u32.u64 %0, t; }" : "=r"(a) : "l"(p));
    return a;
}

// m16n8k8 tf32 MMA (baseline PTX, sm_80+)
__device__ __forceinline__ void mma8(float d[4], const uint32_t a[4], const uint32_t b[2]){
    asm volatile(
        "mma.sync.aligned.m16n8k8.row.col.f32.tf32.tf32.f32 "
        "{%0,%1,%2,%3}, {%4,%5,%6,%7}, {%8,%9}, {%0,%1,%2,%3};"
        : "+f"(d[0]), "+f"(d[1]), "+f"(d[2]), "+f"(d[3])
        : "r"(a[0]), "r"(a[1]), "r"(a[2]), "r"(a[3]), "r"(b[0]), "r"(b[1]));
}

__device__ __forceinline__ void ldsm4(uint32_t &r0, uint32_t &r1, uint32_t &r2, uint32_t &r3,
                                      uint32_t addr){
    asm volatile("ldmatrix.sync.aligned.m8n8.x4.shared.b16 {%0,%1,%2,%3}, [%4];"
        : "=r"(r0), "=r"(r1), "=r"(r2), "=r"(r3) : "r"(addr));
}

__device__ __forceinline__ void cp16(uint32_t dst, const void* src, int szbytes){
    asm volatile("cp.async.cg.shared.global [%0], [%1], 16, %2;"
                 :: "r"(dst), "l"(src), "r"(szbytes) : "memory");
}
#define CP_COMMIT() asm volatile("cp.async.commit_group;" ::: "memory")
#define CP_WAIT1()  asm volatile("cp.async.wait_group 1;" ::: "memory")
#define CP_WAIT0()  asm volatile("cp.async.wait_group 0;" ::: "memory")

// ---------------- weight tf32 pre-convert ----------------
__global__ void cvt_kernel(const float* __restrict__ src, float* __restrict__ dst, int n)
{
    int i = blockIdx.x*256 + threadIdx.x;
    if (i < n) dst[i] = tf32r(src[i]);
}

// ---------------- tensor-core tf32 GEMM: C = A(MxK) @ W(NxK)^T ----------------
// A and W must already hold tf32-rounded values. 128x128 CTA tile, 8 warps 4x2,
// warp tile 32x64, K-chunks of 32, 3-stage cp.async ring (one sync per chunk),
// ldmatrix fragment loads, smem stride 36.
// EPI 0: store. EPI 1: silu(acc+bias), tf32-round. EPI 2: gate combine.
// EPI 3: store tf32-rounded.
#define KT    32
#define AST   36
#define STGF  (128*AST)            // floats per (A or B) half-stage
#define STGB  (2*STGF*4)           // bytes per full stage (A+B) = 36864
#define GEMM_SMEM (3*STGB)         // 110592 bytes
template<int EPI>
__global__ void __launch_bounds__(256, 2) mgemm_kernel(
    const float* __restrict__ A,
    const float* __restrict__ W,
    const float* __restrict__ bias,
    float* __restrict__ C, int ldc,
    int N, int K,
    const float* __restrict__ p1, const float* __restrict__ p2)
{
    extern __shared__ float sm[];
    uint32_t smb = smem_u32(sm);
    int tid = threadIdx.x;
    int bm = blockIdx.y * 128, bn = blockIdx.x * 128;

    int lr = tid >> 1;              // load row 0..127
    int lc = (tid & 1) * 16;        // load col base 0/16
    const float* Arow = A + (size_t)(bm + lr)*K + lc;
    const float* Wrow = W + (size_t)(bn + lr)*K + lc;
    int wsz = ((bn + lr) < N) ? 16 : 0;
    uint32_t adst = smb + (uint32_t)(lr*AST + lc)*4u;
    uint32_t bdst = adst + (uint32_t)STGF*4u;

    int lane = tid & 31, w = tid >> 5;
    int wm = (w >> 1) * 32, wn = (w & 1) * 64;
    int gr = lane >> 2, tg = lane & 3;

    // ldmatrix per-lane base addresses
    int t4 = lane >> 3, rl = lane & 7;
    uint32_t aoff[2], boff[4];
    #pragma unroll
    for (int mi=0; mi<2; mi++){
        int row = wm + mi*16 + rl + (t4 & 1)*8;
        int ko  = (t4 >> 1) * 4;
        aoff[mi] = smb + (uint32_t)(row*AST + ko)*4u;
    }
    #pragma unroll
    for (int nb=0; nb<4; nb++){
        int row = wn + nb*16 + rl + (t4 >> 1)*8;
        int ko  = (t4 & 1) * 4;
        boff[nb] = smb + (uint32_t)STGF*4u + (uint32_t)(row*AST + ko)*4u;
    }

    float acc[2][8][4];
    #pragma unroll
    for (int mi=0;mi<2;mi++)
        #pragma unroll
        for (int ni=0;ni<8;ni++)
            #pragma unroll
            for (int e=0;e<4;e++) acc[mi][ni][e]=0.f;

    int nch = K / KT;

    // prologue: stages 0 and 1
    {
        #pragma unroll
        for (int u=0;u<4;u++){
            cp16(adst + u*16, Arow + 4*u, 16);
            cp16(bdst + u*16, Wrow + 4*u, wsz);
        }
        CP_COMMIT();
        if (nch > 1) {
            #pragma unroll
            for (int u=0;u<4;u++){
                cp16(adst + STGB + u*16, Arow + KT + 4*u, 16);
                cp16(bdst + STGB + u*16, Wrow + KT + 4*u, wsz);
            }
            CP_COMMIT();
        }
    }

    int stage = 0;
    for (int c = 0; c < nch; c++) {
        if (c + 1 < nch) CP_WAIT1(); else CP_WAIT0();
        __syncthreads();

        if (c + 2 < nch) {
            int ns = stage + 2; if (ns >= 3) ns -= 3;
            uint32_t so = (uint32_t)ns * STGB;
            int k0 = (c + 2) * KT;
            #pragma unroll
            for (int u=0;u<4;u++){
                cp16(adst + so + u*16, Arow + k0 + 4*u, 16);
                cp16(bdst + so + u*16, Wrow + k0 + 4*u, wsz);
            }
            CP_COMMIT();
        }

        uint32_t so = (uint32_t)stage * STGB;
        #pragma unroll
        for (int k8 = 0; k8 < 4; k8++) {
            uint32_t kb = (uint32_t)(k8 * 8) * 4u;
            uint32_t afr[2][4];
            #pragma unroll
            for (int mi=0;mi<2;mi++)
                ldsm4(afr[mi][0], afr[mi][1], afr[mi][2], afr[mi][3], aoff[mi] + so + kb);
            uint32_t bfr[8][2];
            #pragma unroll
            for (int nb=0;nb<4;nb++)
                ldsm4(bfr[2*nb][0], bfr[2*nb][1], bfr[2*nb+1][0], bfr[2*nb+1][1],
                      boff[nb] + so + kb);
            #pragma unroll
            for (int mi=0;mi<2;mi++)
                #pragma unroll
                for (int ni=0;ni<8;ni++)
                    mma8(acc[mi][ni], afr[mi], bfr[ni]);
        }
        stage++; if (stage >= 3) stage -= 3;
    }

    // ---- epilogue ----
    #pragma unroll
    for (int mi=0;mi<2;mi++){
        #pragma unroll
        for (int ni=0;ni<8;ni++){
            int col = bn + wn + ni*8 + 2*tg;
            #pragma unroll
            for (int half=0; half<2; half++){
                int m = bm + wm + mi*16 + gr + half*8;
                #pragma unroll
                for (int e=0; e<2; e++){
                    int n = col + e;
                    if (n >= N) continue;
                    float v = acc[mi][ni][half*2 + e];
                    if (EPI == 0) {
                        C[(size_t)m*ldc + n] = v;
                    } else if (EPI == 1) {
                        v += bias[n];
                        C[(size_t)m*ldc + n] = tf32r(v * sigf(v));
                    } else if (EPI == 2) {
                        float g  = sigf(v + bias[n]);
                        float ym = p1[(size_t)m*(2*DINNER) + n];
                        float yr = p1[(size_t)m*(2*DINNER) + DINNER + n];
                        float z  = p2[(size_t)m*DPROJ + n];
                        float sz = z * sigf(z);
                        C[(size_t)m*ldc + n] = (g*ym + (1.f-g)*yr) * sz;
                    } else {
                        C[(size_t)m*ldc + n] = tf32r(v);
                    }
                }
            }
        }
    }
}

// 16-step k-major micro-GEMM (fp32, for scan kernels)
__device__ __forceinline__ void mm16(const float* __restrict__ P,
                                     const float* __restrict__ Q,
                                     float acc[4][4], int ty, int tx)
{
    #pragma unroll
    for (int kk = 0; kk < 16; kk++) {
        float a[4], b[4];
        #pragma unroll
        for (int i=0;i<4;i++) a[i] = P[kk*64 + ty + 16*i];
        #pragma unroll
        for (int j=0;j<4;j++) b[j] = Q[kk*64 + tx + 16*j];
        #pragma unroll
        for (int i=0;i<4;i++)
            #pragma unroll
            for (int j=0;j<4;j++) acc[i][j] = fmaf(a[i], b[j], acc[i][j]);
    }
}

// ---------------- elementwise kernels ----------------
__global__ void umix_kernel(const float* __restrict__ u, const float* __restrict__ tm)
{
    int idx = blockIdx.x*256 + threadIdx.x;
    if (idx >= NTOK*DMODEL) return;
    int m = idx / DMODEL, ch = idx - m*DMODEL;
    int t = m & (SEQLEN-1);
    float tmx = tm[ch];
    float cur = u[idx];
    float prev = (t > 0) ? u[idx - DMODEL] : 0.f;
    g_umix[idx] = tf32r(cur*tmx + prev*(1.f - tmx));
}

__global__ void conv_kernel(const float* __restrict__ cw, const float* __restrict__ cb)
{
    int idx = blockIdx.x*256 + threadIdx.x;
    if (idx >= NTOK*CONVDIM) return;
    int m = idx / CONVDIM, ch = idx - m*CONVDIM;
    int t = m & (SEQLEN-1);
    float acc = cb[ch];
    #pragma unroll
    for (int k2 = 0; k2 < 4; k2++) {
        int tt = t - 3 + k2;
        if (tt >= 0)
            acc = fmaf(cw[ch*4+k2], g_proj[(size_t)(m-3+k2)*DPROJ + OFF_XBC + ch], acc);
    }
    g_xbc[(size_t)m*CONVDIM + ch] = acc * sigf(acc);   // SiLU
}

__global__ void dt_kernel(const float* __restrict__ dt_bias)
{
    int idx = blockIdx.x*256 + threadIdx.x;
    if (idx >= NTOK*NHEADS) return;
    int hh = idx % NHEADS;
    size_t m = idx / NHEADS;
    float x = g_proj[m*DPROJ + OFF_DT + hh] + dt_bias[hh];
    g_dt[idx] = (x > 20.f) ? x : log1pf(__expf(x));
}

// ---------------- SSD kernel 1: per (c,h,b): cum, Y_diag, chunk state ----------------
__global__ void __launch_bounds__(256) ssd_chunk_kernel(const float* __restrict__ A_log)
{
    int c = blockIdx.x, h = blockIdx.y, b = blockIdx.z;
    int tid = threadIdx.x, tx = tid & 15, ty = tid >> 4;
    int r = tid >> 2, q = tid & 3;
    int tok0 = b*SEQLEN + c*64;

    __shared__ float sP[16*64];
    __shared__ float sQ[16*64];
    __shared__ float sG[64*64];     // s-major: sG[s*64 + t]
    __shared__ float cum[64], sdt[64];

    if (tid < 64) sdt[tid] = g_dt[(size_t)(tok0+tid)*NHEADS + h];
    __syncthreads();
    if (tid == 0) {
        float Ah = -__expf(A_log[h]);
        float s = 0.f;
        for (int t = 0; t < 64; t++) { s += Ah*sdt[t]; cum[t] = s; }
    }
    __syncthreads();
    if (tid < 64) g_cumA[(size_t)(tok0+tid)*NHEADS + h] = cum[tid];
    if (tid == 0) g_alast[(size_t)(b*NCHUNK+c)*NHEADS + h] = cum[63];

    float acc[4][4];
    #pragma unroll
    for (int i=0;i<4;i++)
        #pragma unroll
        for (int j=0;j<4;j++) acc[i][j]=0.f;
    for (int n0 = 0; n0 < 64; n0 += 16) {
        float4 cv = *(const float4*)(g_xbc + (size_t)(tok0+r)*CONVDIM + OFF_C + n0 + q*4);
        float4 bv = *(const float4*)(g_xbc + (size_t)(tok0+r)*CONVDIM + OFF_B + n0 + q*4);
        sP[(q*4+0)*64+r]=cv.x; sP[(q*4+1)*64+r]=cv.y;
        sP[(q*4+2)*64+r]=cv.z; sP[(q*4+3)*64+r]=cv.w;
        sQ[(q*4+0)*64+r]=bv.x; sQ[(q*4+1)*64+r]=bv.y;
        sQ[(q*4+2)*64+r]=bv.z; sQ[(q*4+3)*64+r]=bv.w;
        __syncthreads();
        mm16(sP, sQ, acc, ty, tx);
        __syncthreads();
    }
    #pragma unroll
    for (int i=0;i<4;i++)
        #pragma unroll
        for (int j=0;j<4;j++){
            int t = ty+16*i, s = tx+16*j;
            sG[s*64 + t] = (s <= t) ? acc[i][j]*__expf(cum[t]-cum[s]) : 0.f;
        }
    __syncthreads();

    #pragma unroll
    for (int i=0;i<4;i++)
        #pragma unroll
        for (int j=0;j<4;j++) acc[i][j]=0.f;
    {
        int kk2 = tid >> 4, p4 = tid & 15;
        for (int s0 = 0; s0 < 64; s0 += 16) {
            float d = sdt[s0+kk2];
            float4 xv = *(const float4*)(g_xbc + (size_t)(tok0+s0+kk2)*CONVDIM + h*64 + p4*4);
            sQ[kk2*64 + p4*4+0]=xv.x*d; sQ[kk2*64 + p4*4+1]=xv.y*d;
            sQ[kk2*64 + p4*4+2]=xv.z*d; sQ[kk2*64 + p4*4+3]=xv.w*d;
            __syncthreads();
            mm16(&sG[s0*64], sQ, acc, ty, tx);
            __syncthreads();
        }
    }
    #pragma unroll
    for (int i=0;i<4;i++)
        #pragma unroll
        for (int j=0;j<4;j++)
            g_hcat[(size_t)(tok0+ty+16*i)*(2*DINNER) + h*64 + tx+16*j] = acc[i][j];

    #pragma unroll
    for (int i=0;i<4;i++)
        #pragma unroll
        for (int j=0;j<4;j++) acc[i][j]=0.f;
    {
        int kk2 = tid >> 4, p4 = tid & 15;
        float alastv = cum[63];
        for (int t0 = 0; t0 < 64; t0 += 16) {
            float f = sdt[t0+kk2] * __expf(alastv - cum[t0+kk2]);
            float4 xv = *(const float4*)(g_xbc + (size_t)(tok0+t0+kk2)*CONVDIM + h*64 + p4*4);
            float4 bv = *(const float4*)(g_xbc + (size_t)(tok0+t0+kk2)*CONVDIM + OFF_B + p4*4);
            sP[kk2*64 + p4*4+0]=xv.x*f; sP[kk2*64 + p4*4+1]=xv.y*f;
            sP[kk2*64 + p4*4+2]=xv.z*f; sP[kk2*64 + p4*4+3]=xv.w*f;
            sQ[kk2*64 + p4*4+0]=bv.x;   sQ[kk2*64 + p4*4+1]=bv.y;
            sQ[kk2*64 + p4*4+2]=bv.z;   sQ[kk2*64 + p4*4+3]=bv.w;
            __syncthreads();
            mm16(sP, sQ, acc, ty, tx);
            __syncthreads();
        }
    }
    {
        float* sb = g_states + ((size_t)(b*NCHUNK+c)*NHEADS + h)*4096;
        #pragma unroll
        for (int i=0;i<4;i++)
            #pragma unroll
            for (int j=0;j<4;j++)
                sb[(ty+16*i)*64 + tx+16*j] = acc[i][j];
    }
}

// ---------------- SSD kernel 2: cross-chunk state scan ----------------
__global__ void __launch_bounds__(256) ssd_scan_kernel()
{
    int h = blockIdx.x, b = blockIdx.y;
    int tid = threadIdx.x;
    float S[16];
    #pragma unroll
    for (int u=0;u<16;u++) S[u]=0.f;
    size_t eoff = (size_t)tid*16;
    for (int c = 0; c < NCHUNK; c++) {
        float e = __expf(g_alast[(size_t)(b*NCHUNK+c)*NHEADS + h]);
        float* ptr = g_states + ((size_t)(b*NCHUNK+c)*NHEADS + h)*4096 + eoff;
        #pragma unroll
        for (int u=0;u<16;u+=4){
            float4 o = *(float4*)(ptr+u);
            *(float4*)(ptr+u) = make_float4(S[u],S[u+1],S[u+2],S[u+3]);
            S[u+0]=S[u+0]*e+o.x; S[u+1]=S[u+1]*e+o.y;
            S[u+2]=S[u+2]*e+o.z; S[u+3]=S[u+3]*e+o.w;
        }
    }
}

// ---------------- SSD kernel 3: Y += exp(cum)*(C @ S_in^T) + x*D_skip ----------------
__global__ void __launch_bounds__(256) ssd_off_kernel(const float* __restrict__ D_skip)
{
    int c = blockIdx.x, h = blockIdx.y, b = blockIdx.z;
    int tid = threadIdx.x, tx = tid & 15, ty = tid >> 4;
    int r = tid >> 2, q = tid & 3;
    int tok0 = b*SEQLEN + c*64;

    __shared__ float sS[64*64];     // n-major: sS[n*64 + p]
    __shared__ float sC[16*64];
    __shared__ float cum[64];

    {
        const float* sb = g_states + ((size_t)(b*NCHUNK+c)*NHEADS + h)*4096;
        #pragma unroll
        for (int u=0;u<4;u++){
            float4 v = *(const float4*)(sb + r*64 + q*16 + u*4);
            sS[(q*16+u*4+0)*64 + r]=v.x; sS[(q*16+u*4+1)*64 + r]=v.y;
            sS[(q*16+u*4+2)*64 + r]=v.z; sS[(q*16+u*4+3)*64 + r]=v.w;
        }
    }
    if (tid < 64) cum[tid] = g_cumA[(size_t)(tok0+tid)*NHEADS + h];
    __syncthreads();

    float acc[4][4];
    #pragma unroll
    for (int i=0;i<4;i++)
        #pragma unroll
        for (int j=0;j<4;j++) acc[i][j]=0.f;
    for (int n0 = 0; n0 < 64; n0 += 16) {
        float4 cv = *(const float4*)(g_xbc + (size_t)(tok0+r)*CONVDIM + OFF_C + n0 + q*4);
        sC[(q*4+0)*64+r]=cv.x; sC[(q*4+1)*64+r]=cv.y;
        sC[(q*4+2)*64+r]=cv.z; sC[(q*4+3)*64+r]=cv.w;
        __syncthreads();
        mm16(sC, &sS[n0*64], acc, ty, tx);
        __syncthreads();
    }
    float dsk = D_skip[h];
    #pragma unroll
    for (int i=0;i<4;i++){
        int t = ty+16*i;
        float e = __expf(cum[t]);
        #pragma unroll
        for (int j=0;j<4;j++){
            int p = tx+16*j;
            float xv = g_xbc[(size_t)(tok0+t)*CONVDIM + h*64 + p];
            size_t o = (size_t)(tok0+t)*(2*DINNER) + h*64 + p;
            g_hcat[o] = tf32r(g_hcat[o] + e*acc[i][j] + xv*dsk);
        }
    }
}

// ---------------- RWKV kernels ----------------
__global__ void rwkv_pre_kernel()
{
    int bc = blockIdx.x;
    int i = threadIdx.x;
    int tok0 = (bc/NCHUNK)*SEQLEN + (bc%NCHUNK)*64;
    float cumv = 0.f;
    for (int t = 0; t < 64; t++) {
        float rw = g_proj[(size_t)(tok0+t)*DPROJ + OFF_W + i];
        cumv += -__expf(rw);
        g_wcum[(size_t)(tok0+t)*64 + i] = cumv;
    }
}

__global__ void __launch_bounds__(256) rwkv_gram_kernel()
{
    int bc = blockIdx.x;
    int b = bc/NCHUNK, c = bc%NCHUNK;
    int tok0 = b*SEQLEN + c*64;
    int tid = threadIdx.x, tx = tid & 15, ty = tid >> 4;
    int r = tid >> 2, q = tid & 3;

    __shared__ float sA1[64*64];
    __shared__ float sA2[64*64];
    __shared__ float sM [64*64];

    #pragma unroll
    for (int u=0;u<4;u++){
        float4 kv = *(const float4*)(g_proj + (size_t)(tok0+r)*DPROJ + OFF_K + q*16 + u*4);
        float4 vv = *(const float4*)(g_proj + (size_t)(tok0+r)*DPROJ + OFF_V + q*16 + u*4);
        sA1[(q*16+u*4+0)*64 + r]=kv.x; sA1[(q*16+u*4+1)*64 + r]=kv.y;
        sA1[(q*16+u*4+2)*64 + r]=kv.z; sA1[(q*16+u*4+3)*64 + r]=kv.w;
        sA2[(q*16+u*4+0)*64 + r]=vv.x; sA2[(q*16+u*4+1)*64 + r]=vv.y;
        sA2[(q*16+u*4+2)*64 + r]=vv.z; sA2[(q*16+u*4+3)*64 + r]=vv.w;
    }
    __syncthreads();
    float acc[4][4];
    #pragma unroll
    for (int i=0;i<4;i++)
        #pragma unroll
        for (int j=0;j<4;j++) acc[i][j]=0.f;
    #pragma unroll
    for (int j0 = 0; j0 < 64; j0 += 16)
        mm16(&sA1[j0*64], &sA2[j0*64], acc, ty, tx);
    __syncthreads();
    #pragma unroll
    for (int i=0;i<4;i++)
        #pragma unroll
        for (int j=0;j<4;j++)
            sM[(ty+16*i)*64 + tx+16*j] = acc[i][j];
    __syncthreads();

    for (int idx = tid; idx < 4096; idx += 256) {
        int t = idx >> 6, i = idx & 63;
        sA1[idx] = g_wcum[(size_t)(tok0+t)*64 + i];
        sA2[idx] = g_proj[(size_t)(tok0+t)*DPROJ + OFF_K + i]
                 * g_proj[(size_t)(tok0+t)*DPROJ + OFF_BON + i];
    }
    __syncthreads();

    {
        int i = tid & 63, tg = tid >> 6;
        for (int tt = 0; tt < 16; tt++) {
            int t = tg*16 + tt;
            float ct = sA1[t*64 + i];
            float sum = 0.f;
            for (int s = 0; s <= t; s++)
                sum = fmaf(__expf(ct - sA1[s*64+i]) * sA2[s*64+i], sM[t*64+s], sum);
            float rr = sigf(g_proj[(size_t)(tok0+t)*DPROJ + OFF_R + i]);
            g_wkvy[(size_t)(tok0+t)*64 + i] = rr * sum;
        }
    }
}

__global__ void __launch_bounds__(256) rwkv_state_kernel()
{
    int bc = blockIdx.x;
    int b = bc/NCHUNK, c = bc%NCHUNK;
    int tok0 = b*SEQLEN + c*64;
    int tid = threadIdx.x, tx = tid & 15, ty = tid >> 4;

    __shared__ float sP[64*64];
    __shared__ float sV[64*64];

    for (int idx = tid; idx < 4096; idx += 256) {
        int s = idx >> 6, i = idx & 63;
        float cl = g_wcum[(size_t)(tok0+63)*64 + i];
        float cs = g_wcum[(size_t)(tok0+s)*64 + i];
        sP[idx] = __expf(cl - cs)
                * g_proj[(size_t)(tok0+s)*DPROJ + OFF_K + i]
                * g_proj[(size_t)(tok0+s)*DPROJ + OFF_BON + i];
        sV[idx] = g_proj[(size_t)(tok0+s)*DPROJ + OFF_V + i];
    }
    __syncthreads();
    if (tid < 64)
        g_wdecay[(size_t)bc*64 + tid] = __expf(g_wcum[(size_t)(tok0+63)*64 + tid]);

    float acc[4][4];
    #pragma unroll
    for (int i=0;i<4;i++)
        #pragma unroll
        for (int j=0;j<4;j++) acc[i][j]=0.f;
    #pragma unroll
    for (int s0 = 0; s0 < 64; s0 += 16)
        mm16(&sP[s0*64], &sV[s0*64], acc, ty, tx);

    float* T = g_wT + (size_t)bc*4096;
    #pragma unroll
    for (int i=0;i<4;i++)
        #pragma unroll
        for (int j=0;j<4;j++)
            T[(ty+16*i)*64 + tx+16*j] = acc[i][j];
}

__global__ void __launch_bounds__(256) rwkv_scan_kernel()
{
    int b = blockIdx.x;
    int tid = threadIdx.x;
    int i = tid >> 2, jb = (tid & 3)*16;
    float S[16];
    #pragma unroll
    for (int u=0;u<16;u++) S[u]=0.f;
    for (int c = 0; c < NCHUNK; c++) {
        int bc = b*NCHUNK + c;
        float e = g_wdecay[(size_t)bc*64 + i];
        float* ptr = g_wT + (size_t)bc*4096 + i*64 + jb;
        #pragma unroll
        for (int u=0;u<16;u+=4){
            float4 o = *(float4*)(ptr+u);
            *(float4*)(ptr+u) = make_float4(S[u],S[u+1],S[u+2],S[u+3]);
            S[u+0]=S[u+0]*e+o.x; S[u+1]=S[u+1]*e+o.y;
            S[u+2]=S[u+2]*e+o.z; S[u+3]=S[u+3]*e+o.w;
        }
    }
}

__global__ void __launch_bounds__(256) rwkv_inter_kernel()
{
    int bc = blockIdx.x;
    int b = bc/NCHUNK, c = bc%NCHUNK;
    int tok0 = b*SEQLEN + c*64;
    int tid = threadIdx.x, tx = tid & 15, ty = tid >> 4;
    int r = tid >> 2, q = tid & 3;

    __shared__ float sK[64*64];
    __shared__ float sS[64*64];

    #pragma unroll
    for (int u=0;u<4;u++){
        float4 kv = *(const float4*)(g_proj + (size_t)(tok0+r)*DPROJ + OFF_K + q*16 + u*4);
        sK[(q*16+u*4+0)*64 + r]=kv.x; sK[(q*16+u*4+1)*64 + r]=kv.y;
        sK[(q*16+u*4+2)*64 + r]=kv.z; sK[(q*16+u*4+3)*64 + r]=kv.w;
        float4 sv = *(const float4*)(g_wT + (size_t)bc*4096 + r*64 + q*16 + u*4);
        sS[(q*16+u*4+0)*64 + r]=sv.x; sS[(q*16+u*4+1)*64 + r]=sv.y;
        sS[(q*16+u*4+2)*64 + r]=sv.z; sS[(q*16+u*4+3)*64 + r]=sv.w;
    }
    __syncthreads();

    float acc[4][4];
    #pragma unroll
    for (int i=0;i<4;i++)
        #pragma unroll
        for (int j=0;j<4;j++) acc[i][j]=0.f;
    #pragma unroll
    for (int j0 = 0; j0 < 64; j0 += 16)
        mm16(&sK[j0*64], &sS[j0*64], acc, ty, tx);

    #pragma unroll
    for (int ii=0;ii<4;ii++){
        int t = ty+16*ii;
        #pragma unroll
        for (int jj=0;jj<4;jj++){
            int i = tx+16*jj;
            float rr = sigf(g_proj[(size_t)(tok0+t)*DPROJ + OFF_R + i]);
            float e  = __expf(g_wcum[(size_t)(tok0+t)*64 + i]);
            size_t o = (size_t)(tok0+t)*64 + i;
            g_wkvy[o] = tf32r(g_wkvy[o] + rr * e * acc[ii][jj]);
        }
    }
}

// ---------------- LayerNorm ----------------
__global__ void __launch_bounds__(256) ln_kernel(const float* __restrict__ g,
                                                 const float* __restrict__ bbias)
{
    int m = blockIdx.x;
    int tid = threadIdx.x;
    const float* row = g_ypre + (size_t)m*DINNER;
    float s = 0.f, s2 = 0.f;
    #pragma unroll
    for (int u = 0; u < 6; u++) {
        float v = row[tid + 256*u];
        s += v; s2 += v*v;
    }
    __shared__ float red[16];
    #pragma unroll
    for (int o = 16; o > 0; o >>= 1) {
        s  += __shfl_xor_sync(0xffffffff, s, o);
        s2 += __shfl_xor_sync(0xffffffff, s2, o);
    }
    if ((tid & 31) == 0) { red[tid>>5] = s; red[8 + (tid>>5)] = s2; }
    __syncthreads();
    if (tid < 8) { s = red[tid]; s2 = red[8+tid]; }
    else { s = 0.f; s2 = 0.f; }
    if (tid < 32) {
        #pragma unroll
        for (int o = 4; o > 0; o >>= 1) {
            s  += __shfl_xor_sync(0xffffffff, s, o);
            s2 += __shfl_xor_sync(0xffffffff, s2, o);
        }
    }
    if (tid == 0) { red[0] = s; red[1] = s2; }
    __syncthreads();
    float mu = red[0] * (1.f/DINNER);
    float var = red[1] * (1.f/DINNER) - mu*mu;
    float inv = rsqrtf(var + 1e-5f);
    #pragma unroll
    for (int u = 0; u < 6; u++) {
        int ch = tid + 256*u;
        float v = (row[ch] - mu) * inv;
        g_ynorm[(size_t)m*DINNER + ch] = tf32r(v * g[ch] + bbias[ch]);
    }
}

// ---------------- launch ----------------
extern "C" void kernel_launch(void* const* d_in, const int* in_sizes, int n_in,
                              void* d_out, int out_size)
{
    const float* u         = (const float*)d_in[0];
    const float* in_proj_w = (const float*)d_in[1];
    const float* conv_w    = (const float*)d_in[2];
    const float* conv_b    = (const float*)d_in[3];
    const float* dt_bias   = (const float*)d_in[4];
    const float* A_log     = (const float*)d_in[5];
    const float* D_skip    = (const float*)d_in[6];
    const float* time_mix  = (const float*)d_in[7];
    const float* wkv_up_w  = (const float*)d_in[8];
    const float* fg_w1     = (const float*)d_in[9];
    const float* fg_b1     = (const float*)d_in[10];
    const float* fg_w2     = (const float*)d_in[11];
    const float* fg_b2     = (const float*)d_in[12];
    const float* ln_g      = (const float*)d_in[13];
    const float* ln_b      = (const float*)d_in[14];
    const float* out_proj_w= (const float*)d_in[15];
    float* out = (float*)d_out;

    float* p_umix;  cudaGetSymbolAddress((void**)&p_umix,  g_umix);
    float* p_proj;  cudaGetSymbolAddress((void**)&p_proj,  g_proj);
    float* p_hcat;  cudaGetSymbolAddress((void**)&p_hcat,  g_hcat);
    float* p_h;     cudaGetSymbolAddress((void**)&p_h,     g_h);
    float* p_ypre;  cudaGetSymbolAddress((void**)&p_ypre,  g_ypre);
    float* p_ynorm; cudaGetSymbolAddress((void**)&p_ynorm, g_ynorm);
    float* p_wkvy;  cudaGetSymbolAddress((void**)&p_wkvy,  g_wkvy);
    float* p_wi;    cudaGetSymbolAddress((void**)&p_wi,    g_wi);
    float* p_w1;    cudaGetSymbolAddress((void**)&p_w1,    g_w1);
    float* p_w2;    cudaGetSymbolAddress((void**)&p_w2,    g_w2);
    float* p_wo;    cudaGetSymbolAddress((void**)&p_wo,    g_wo);
    float* p_wu;    cudaGetSymbolAddress((void**)&p_wu,    g_wu);

    // one-time side-stream + events (created on the uncaptured correctness
    // call; reused as graph fork/join edges during capture)
    static cudaStream_t s2 = nullptr;
    static cudaEvent_t evStart = nullptr, evWi = nullptr, evProj = nullptr, evRwkv = nullptr;
    if (s2 == nullptr) {
        cudaStreamCreateWithFlags(&s2, cudaStreamNonBlocking);
        cudaEventCreateWithFlags(&evStart, cudaEventDisableTiming);
        cudaEventCreateWithFlags(&evWi,    cudaEventDisableTiming);
        cudaEventCreateWithFlags(&evProj,  cudaEventDisableTiming);
        cudaEventCreateWithFlags(&evRwkv,  cudaEventDisableTiming);
        cudaFuncSetAttribute(mgemm_kernel<0>, cudaFuncAttributeMaxDynamicSharedMemorySize, GEMM_SMEM);
        cudaFuncSetAttribute(mgemm_kernel<1>, cudaFuncAttributeMaxDynamicSharedMemorySize, GEMM_SMEM);
        cudaFuncSetAttribute(mgemm_kernel<2>, cudaFuncAttributeMaxDynamicSharedMemorySize, GEMM_SMEM);
        cudaFuncSetAttribute(mgemm_kernel<3>, cudaFuncAttributeMaxDynamicSharedMemorySize, GEMM_SMEM);
    }

    // ---- legal capture fork: s2 enters the capture via an event recorded
    // on the origin (captured) stream BEFORE any s2 launch ----
    cudaEventRecord(evStart, 0);
    cudaStreamWaitEvent(s2, evStart, 0);

    // s2: weight cvts (overlap with umix on main)
    cvt_kernel<<<(DPROJ*DMODEL+255)/256, 256, 0, s2>>>(in_proj_w, p_wi, DPROJ*DMODEL);
    cudaEventRecord(evWi, s2);
    cvt_kernel<<<(DINNER*2*DINNER+255)/256, 256, 0, s2>>>(fg_w1, p_w1, DINNER*2*DINNER);
    cvt_kernel<<<(DINNER*DINNER+255)/256, 256, 0, s2>>>(fg_w2, p_w2, DINNER*DINNER);
    cvt_kernel<<<(DMODEL*DINNER+255)/256, 256, 0, s2>>>(out_proj_w, p_wo, DMODEL*DINNER);
    cvt_kernel<<<(DINNER*64+255)/256, 256, 0, s2>>>(wkv_up_w, p_wu, DINNER*64);

    // main: time-mix, then in_proj (needs evWi)
    umix_kernel<<<(NTOK*DMODEL)/256, 256>>>(u, time_mix);
    cudaStreamWaitEvent(0, evWi, 0);
    mgemm_kernel<0><<<dim3((DPROJ+127)/128, NTOK/128), 256, GEMM_SMEM>>>(
        p_umix, p_wi, nullptr, p_proj, DPROJ, DPROJ, DMODEL, nullptr, nullptr);
    cudaEventRecord(evProj, 0);

    // ---- fork: RWKV chain + wkv_up on s2 (depends on proj only) ----
    cudaStreamWaitEvent(s2, evProj, 0);
    rwkv_pre_kernel<<<BATCH*NCHUNK, 64, 0, s2>>>();
    rwkv_gram_kernel<<<BATCH*NCHUNK, 256, 0, s2>>>();
    rwkv_state_kernel<<<BATCH*NCHUNK, 256, 0, s2>>>();
    rwkv_scan_kernel<<<BATCH, 256, 0, s2>>>();
    rwkv_inter_kernel<<<BATCH*NCHUNK, 256, 0, s2>>>();
    mgemm_kernel<3><<<dim3(DINNER/128, NTOK/128), 256, GEMM_SMEM, s2>>>(
        p_wkvy, p_wu, nullptr, p_hcat + DINNER, 2*DINNER, DINNER, 64, nullptr, nullptr);
    cudaEventRecord(evRwkv, s2);

    // main: SSD chain (writes left half of hcat)
    dt_kernel<<<(NTOK*NHEADS)/256, 256>>>(dt_bias);
    conv_kernel<<<(NTOK*CONVDIM)/256, 256>>>(conv_w, conv_b);
    ssd_chunk_kernel<<<dim3(NCHUNK, NHEADS, BATCH), 256>>>(A_log);
    ssd_scan_kernel<<<dim3(NHEADS, BATCH), 256>>>();
    ssd_off_kernel<<<dim3(NCHUNK, NHEADS, BATCH), 256>>>(D_skip);

    // ---- join: fg1 needs both halves of hcat (joins all s2 work) ----
    cudaStreamWaitEvent(0, evRwkv, 0);
    mgemm_kernel<1><<<dim3(DINNER/128, NTOK/128), 256, GEMM_SMEM>>>(
        p_hcat, p_w1, fg_b1, p_h, DINNER, DINNER, 2*DINNER, nullptr, nullptr);
    mgemm_kernel<2><<<dim3(DINNER/128, NTOK/128), 256, GEMM_SMEM>>>(
        p_h, p_w2, fg_b2, p_ypre, DINNER, DINNER, DINNER, p_hcat, p_proj);
    ln_kernel<<<NTOK, 256>>>(ln_g, ln_b);
    mgemm_kernel<0><<<dim3(DMODEL/128, NTOK/128), 256, GEMM_SMEM>>>(
        p_ynorm, p_wo, nullptr, out, DMODEL, DMODEL, DINNER, nullptr, nullptr);
}